// round 5
// baseline (speedup 1.0000x reference)
#include <cuda_runtime.h>
#include <cstdint>

#define Bc   2
#define Lc   2048
#define Dc   2048
#define Hc   16
#define KVHc 8
#define Dhc  128
#define QKVN 4096
#define D3c  6144
#define EPSc 1e-5f

// ---------------- scratch (device globals: allocation-guard safe) -------------
__device__ float g_mod[Bc * D3c];
__device__ float g_xm [(size_t)Bc * Lc * Dc];
__device__ float g_qkv[(size_t)Bc * Lc * QKVN];   // 0..2047 Q | 2048..3071 K | 3072..4095 V
__device__ float g_o  [(size_t)Bc * Lc * Dc];
__device__ float g_wT [(size_t)QKVN * Dc];
__device__ float g_woT[(size_t)Dc * Dc];

__device__ __forceinline__ float to_tf32(float v) {
    uint32_t u; asm("cvt.rna.tf32.f32 %0, %1;" : "=r"(u) : "f"(v));
    return __uint_as_float(u);
}
__device__ __forceinline__ void mma8(float* d, const uint4& a, uint32_t b0, uint32_t b1) {
    asm volatile("mma.sync.aligned.m16n8k8.row.col.f32.tf32.tf32.f32 "
                 "{%0,%1,%2,%3}, {%4,%5,%6,%7}, {%8,%9}, {%0,%1,%2,%3};"
                 : "+f"(d[0]), "+f"(d[1]), "+f"(d[2]), "+f"(d[3])
                 : "r"(a.x), "r"(a.y), "r"(a.z), "r"(a.w), "r"(b0), "r"(b1));
}

// ================= kernel 1: mod = silu(temb) @ w_mod + b_mod =================
__global__ void k_mod(const float* __restrict__ temb, const float* __restrict__ w_mod,
                      const float* __restrict__ b_mod) {
    __shared__ float st[Dc];
    int b = blockIdx.y;
    int j = blockIdx.x * 256 + threadIdx.x;
    for (int i = threadIdx.x; i < Dc; i += 256) {
        float x = temb[b * Dc + i];
        st[i] = x / (1.f + __expf(-x));
    }
    __syncthreads();
    float acc = b_mod[j];
#pragma unroll 4
    for (int i = 0; i < Dc; i++) acc = fmaf(st[i], w_mod[(size_t)i * D3c + j], acc);
    g_mod[b * D3c + j] = acc;
}

// ====== kernel 2: xm = tf32(rmsnorm(x)*w_ln*(1+scale)+shift) ==================
__global__ void k_rmsmod(const float* __restrict__ x, const float* __restrict__ w_ln) {
    int row = blockIdx.x;
    int b   = row >> 11;
    const float* xr = x + (size_t)row * Dc;
    int tid = threadIdx.x;
    float ss = 0.f;
    for (int i = tid; i < Dc; i += 256) { float v = xr[i]; ss = fmaf(v, v, ss); }
#pragma unroll
    for (int o = 16; o; o >>= 1) ss += __shfl_xor_sync(0xffffffffu, ss, o);
    __shared__ float red[8];
    __shared__ float sinv;
    if ((tid & 31) == 0) red[tid >> 5] = ss;
    __syncthreads();
    if (tid == 0) {
        float t = 0.f;
#pragma unroll
        for (int w = 0; w < 8; w++) t += red[w];
        sinv = rsqrtf(t * (1.f / Dc) + EPSc);
    }
    __syncthreads();
    float inv = sinv;
    const float* sh = g_mod + b * D3c;
    const float* sc = sh + Dc;
    float* xm = g_xm + (size_t)row * Dc;
    for (int i = tid; i < Dc; i += 256)
        xm[i] = to_tf32(fmaf(xr[i] * inv * w_ln[i], 1.f + sc[i], sh[i]));
}

// ====== transpose src[K][N] -> dst[N][K], round tf32 ==========================
__global__ void k_transpose(const float* __restrict__ src, float* __restrict__ dst,
                            int K, int N) {
    __shared__ float t[32][33];
    int kb = blockIdx.y * 32, nb = blockIdx.x * 32;
    int x = threadIdx.x, y = threadIdx.y;
#pragma unroll
    for (int i = 0; i < 32; i += 8)
        t[y + i][x] = src[(size_t)(kb + y + i) * N + nb + x];
    __syncthreads();
#pragma unroll
    for (int i = 0; i < 32; i += 8)
        dst[(size_t)(nb + y + i) * K + kb + x] = to_tf32(t[x][y + i]);
}

// ====== tf32 mma.sync GEMM: C[M,N] = A[M,K] @ Bt[N,K]^T (round-3, verified) ===
#define MMASMEM (24576 * 4)

template<int EPI>
__global__ void __launch_bounds__(256, 1)
k_mma(const float* __restrict__ Ag, const float* __restrict__ Bg,
      float* __restrict__ C, int N, int K, const float* __restrict__ hid) {
    extern __shared__ float smf[];
    float* Asm = smf;
    float* Bsm = smf + 8192;

    int t = threadIdx.x, lane = t & 31, wid = t >> 5;
    int wm = wid >> 2, wn = wid & 3;
    int m0 = blockIdx.y * 128, n0 = blockIdx.x * 256;

    int r0 = t >> 3;
    int kb = (t & 7) * 4;
    int ch = (kb >> 2) & 1;
    int ks = kb >> 3;
    int half = ks & 1, kp = ks >> 1;
    int Abase = (ks * 8 + (r0 >> 4)) * 128 + (r0 & 7) * 16 + ((r0 & 15) >> 3) + 2 * ch;
    int Bbase = (kp * 32 + (r0 >> 3)) * 128 + (r0 & 7) * 16 + half * 2 + ch;

    const float* Aptr = Ag + (size_t)(m0 + r0) * K + kb;
    const float* Bptr = Bg + (size_t)(n0 + r0) * K + kb;

    float acc[4][8][4];
#pragma unroll
    for (int i = 0; i < 4; i++)
#pragma unroll
        for (int j = 0; j < 8; j++)
#pragma unroll
            for (int c = 0; c < 4; c++) acc[i][j][c] = 0.f;

    float4 pa[4], pb[8];
#pragma unroll
    for (int p = 0; p < 4; p++) pa[p] = *(const float4*)(Aptr + (size_t)(p * 32) * K);
#pragma unroll
    for (int p = 0; p < 8; p++) pb[p] = *(const float4*)(Bptr + (size_t)(p * 32) * K);
#pragma unroll
    for (int p = 0; p < 4; p++) {
        Asm[Abase + p * 256 + 0] = pa[p].x; Asm[Abase + p * 256 + 4] = pa[p].y;
        Asm[Abase + p * 256 + 8] = pa[p].z; Asm[Abase + p * 256 + 12] = pa[p].w;
    }
#pragma unroll
    for (int p = 0; p < 8; p++) {
        Bsm[Bbase + p * 512 + 0] = pb[p].x; Bsm[Bbase + p * 512 + 4] = pb[p].y;
        Bsm[Bbase + p * 512 + 8] = pb[p].z; Bsm[Bbase + p * 512 + 12] = pb[p].w;
    }
    __syncthreads();

    int nk = K >> 5;
    int buf = 0;
    for (int kt = 0; kt < nk; kt++) {
        bool more = (kt + 1 < nk);
        if (more) {
            const float* Ap = Aptr + (kt + 1) * 32;
            const float* Bp = Bptr + (kt + 1) * 32;
#pragma unroll
            for (int p = 0; p < 4; p++) pa[p] = *(const float4*)(Ap + (size_t)(p * 32) * K);
#pragma unroll
            for (int p = 0; p < 8; p++) pb[p] = *(const float4*)(Bp + (size_t)(p * 32) * K);
        }

        const float* Ab = Asm + buf * 4096;
        const float* Bb = Bsm + buf * 8192;
#pragma unroll
        for (int kpp = 0; kpp < 2; kpp++) {
            uint4 bb[8];
#pragma unroll
            for (int j = 0; j < 8; j++)
                bb[j] = *(const uint4*)(Bb + (kpp * 32 + wn * 8 + j) * 128 + lane * 4);
#pragma unroll
            for (int hh = 0; hh < 2; hh++) {
                uint4 aa[4];
#pragma unroll
                for (int i = 0; i < 4; i++)
                    aa[i] = *(const uint4*)(Ab + ((kpp * 2 + hh) * 8 + wm * 4 + i) * 128 + lane * 4);
#pragma unroll
                for (int i = 0; i < 4; i++)
#pragma unroll
                    for (int j = 0; j < 8; j++)
                        mma8(acc[i][j], aa[i],
                             hh ? bb[j].z : bb[j].x,
                             hh ? bb[j].w : bb[j].y);
            }
        }

        if (more) {
            float* Ab2 = Asm + (buf ^ 1) * 4096;
            float* Bb2 = Bsm + (buf ^ 1) * 8192;
#pragma unroll
            for (int p = 0; p < 4; p++) {
                Ab2[Abase + p * 256 + 0] = pa[p].x; Ab2[Abase + p * 256 + 4] = pa[p].y;
                Ab2[Abase + p * 256 + 8] = pa[p].z; Ab2[Abase + p * 256 + 12] = pa[p].w;
            }
#pragma unroll
            for (int p = 0; p < 8; p++) {
                Bb2[Bbase + p * 512 + 0] = pb[p].x; Bb2[Bbase + p * 512 + 4] = pb[p].y;
                Bb2[Bbase + p * 512 + 8] = pb[p].z; Bb2[Bbase + p * 512 + 12] = pb[p].w;
            }
        }
        __syncthreads();
        buf ^= 1;
    }

#pragma unroll
    for (int i = 0; i < 4; i++) {
        int gm = m0 + (wm * 4 + i) * 16 + (lane >> 2);
#pragma unroll
        for (int j = 0; j < 8; j++) {
            int gn = n0 + (wn * 8 + j) * 8 + 2 * (lane & 3);
            size_t o0 = (size_t)gm * N + gn;
            size_t o1 = (size_t)(gm + 8) * N + gn;
            if (EPI == 0) {
                *(float2*)(C + o0) = make_float2(acc[i][j][0], acc[i][j][1]);
                *(float2*)(C + o1) = make_float2(acc[i][j][2], acc[i][j][3]);
            } else {
                int b0 = gm >> 11, b1 = (gm + 8) >> 11;
                float2 h0 = *(const float2*)(hid + o0);
                float2 h1 = *(const float2*)(hid + o1);
                float2 g0 = *(const float2*)(g_mod + b0 * D3c + 2 * Dc + gn);
                float2 g1 = *(const float2*)(g_mod + b1 * D3c + 2 * Dc + gn);
                *(float2*)(C + o0) = make_float2(fmaf(g0.x, acc[i][j][0], h0.x),
                                                 fmaf(g0.y, acc[i][j][1], h0.y));
                *(float2*)(C + o1) = make_float2(fmaf(g1.x, acc[i][j][2], h1.x),
                                                 fmaf(g1.y, acc[i][j][3], h1.y));
            }
        }
    }
}

// ====== per-head RMSNorm + mixed RoPE =========================================
__global__ void __launch_bounds__(256)
k_qknorm_rope(const float* __restrict__ cos1d, const float* __restrict__ sin1d,
              const float* __restrict__ rope3d,
              const float* __restrict__ qn, const float* __restrict__ kn,
              const int* __restrict__ mp) {
    int warp = threadIdx.x >> 5, lane = threadIdx.x & 31;
    int v  = blockIdx.x * 8 + warp;
    int bl = v / 24, r = v % 24;
    int b = bl >> 11, l = bl & 2047;

    float* ptr; const float* w;
    if (r < Hc) { ptr = g_qkv + (size_t)bl * QKVN + r * Dhc;               w = qn; }
    else        { ptr = g_qkv + (size_t)bl * QKVN + 2048 + (r - Hc) * Dhc; w = kn; }

    float val[4];
    float ss = 0.f;
#pragma unroll
    for (int i = 0; i < 4; i++) { val[i] = ptr[lane + 32 * i]; ss = fmaf(val[i], val[i], ss); }
#pragma unroll
    for (int o = 16; o; o >>= 1) ss += __shfl_xor_sync(0xffffffffu, ss, o);
    float inv = rsqrtf(ss * (1.f / Dhc) + EPSc);
#pragma unroll
    for (int i = 0; i < 4; i++) val[i] *= inv * w[lane + 32 * i];

    bool is64 = (mp[1] == 0);
    bool in_full = false, in_img = false; int rel = 0;
#pragma unroll
    for (int m = 0; m < 2; m++) {
        int off, ln;
        if (is64) { off = mp[(b * 4 + m * 2) * 2]; ln = mp[(b * 4 + m * 2 + 1) * 2]; }
        else      { off = mp[b * 4 + m * 2];       ln = mp[b * 4 + m * 2 + 1]; }
        int seg_end = off + max(ln, 1);
        if (l >= off && l < seg_end) in_full = true;
        if (l >= off + 1 && l < off + ln) { in_img = true; rel += l - (off + 1); }
    }
    bool text = !in_full;
    bool img  = in_img && (rel < 1024);
    rel = min(max(rel, 0), 1023);

    float out[4];
    if (text) {
#pragma unroll
        for (int i = 0; i < 4; i++) {
            int d = lane + 32 * i;
            float c = cos1d[l * Dhc + d], s = sin1d[l * Dhc + d];
            float rot = (i < 2) ? -val[i ^ 2] : val[i ^ 2];
            out[i] = fmaf(val[i], c, rot * s);
        }
    } else {
#pragma unroll
        for (int i = 0; i < 4; i++) {
            int d = lane + 32 * i; int p = d >> 1; int jj = d & 1;
            float partner = __shfl_xor_sync(0xffffffffu, val[i], 1);
            float q0 = jj ? partner : val[i];
            float q1 = jj ? val[i] : partner;
            const float* R = rope3d + ((size_t)rel * 64 + p) * 4;
            float oimg = fmaf(q0, R[jj], q1 * R[2 + jj]);
            out[i] = img ? oimg : val[i];
        }
    }
#pragma unroll
    for (int i = 0; i < 4; i++) ptr[lane + 32 * i] = out[i];
}

// ====== flash attention, tf32 mma.sync ========================================
// CTA: 128 q-rows x 1 head. 8 warps (4 m x 2 n). kv-tile = 64.
// smem floats: Qf[16384] Kf[8192] Vf[8192] Pf[8192] red[512]
#define FSMEM ((16384 + 8192 + 8192 + 8192 + 512) * 4)

__global__ void __launch_bounds__(256, 1)
k_flash(float* __restrict__ go) {
    extern __shared__ float sm[];
    float*  Qf  = sm;
    float*  Kf  = sm + 16384;
    float*  Vf  = sm + 24576;
    float*  Pf  = sm + 32768;
    float2* red = (float2*)(sm + 40960);   // [wn][128] (rowmax, rowsum)

    int t = threadIdx.x, l = t & 31, wid = t >> 5;
    int lo = l & 3, lr = l >> 2;
    int wm = wid >> 1, wn = wid & 1;
    int q0 = blockIdx.x << 7;
    int h  = blockIdx.y, b = blockIdx.z;
    int kh = h >> 1;
    const float SC = 0.08838834764831845f;   // 1/sqrt(128)

    // ---- load Q (once) into A-fragment layout, tf32 ----
    {
        const float* qb = g_qkv + (size_t)(b * Lc + q0) * QKVN + h * Dhc;
#pragma unroll
        for (int i = 0; i < 16; i++) {
            int idx = t + (i << 8);
            int row = idx >> 5, c4 = (idx & 31) << 2;
            float4 v = *(const float4*)(qb + (size_t)row * QKVN + c4);
            int base = ((c4 >> 3) * 8 + (row >> 4)) * 128 + (row & 7) * 16
                     + ((row >> 3) & 1) + ((c4 >> 2) & 1) * 2;
            Qf[base + 0]  = to_tf32(v.x); Qf[base + 4]  = to_tf32(v.y);
            Qf[base + 8]  = to_tf32(v.z); Qf[base + 12] = to_tf32(v.w);
        }
    }
    // ---- load K(0), V(0) ----
    {
#pragma unroll
        for (int i = 0; i < 8; i++) {
            int idx = t + (i << 8);
            int n = idx >> 5, c4 = (idx & 31) << 2;
            float4 v = *(const float4*)(g_qkv + (size_t)(b * Lc + n) * QKVN + 2048 + kh * Dhc + c4);
            int base = ((c4 >> 4) * 8 + (n >> 3)) * 128 + (n & 7) * 16
                     + ((c4 >> 2) & 1) + ((c4 >> 3) & 1) * 2;
            Kf[base + 0] = to_tf32(v.x); Kf[base + 4] = to_tf32(v.y);
            Kf[base + 8] = to_tf32(v.z); Kf[base + 12] = to_tf32(v.w);
        }
#pragma unroll
        for (int i = 0; i < 8; i++) {
            int idx = t + (i << 8);
            int kv = idx >> 5, c4 = (idx & 31) << 2;
            float4 v = *(const float4*)(g_qkv + (size_t)(b * Lc + kv) * QKVN + 3072 + kh * Dhc + c4);
            int base = ((kv >> 4) * 16 + (c4 >> 3)) * 128 + (c4 & 7) * 16
                     + (kv & 3) * 4 + ((kv >> 2) & 1) + ((kv >> 3) & 1) * 2;
            Vf[base + 0]  = to_tf32(v.x); Vf[base + 16] = to_tf32(v.y);
            Vf[base + 32] = to_tf32(v.z); Vf[base + 48] = to_tf32(v.w);
        }
    }
    __syncthreads();

    float accO[2][8][4];
    float m_run[4], l_run[4];
#pragma unroll
    for (int i = 0; i < 2; i++)
#pragma unroll
        for (int j = 0; j < 8; j++)
#pragma unroll
            for (int c = 0; c < 4; c++) accO[i][j][c] = 0.f;
#pragma unroll
    for (int r = 0; r < 4; r++) { m_run[r] = -1e30f; l_run[r] = 0.f; }

    for (int kt = 0; kt < 32; kt++) {
        bool more = (kt + 1 < 32);
        // prefetch K(t+1)
        float4 pre[8];
        if (more) {
#pragma unroll
            for (int i = 0; i < 8; i++) {
                int idx = t + (i << 8);
                int n = idx >> 5, c4 = (idx & 31) << 2;
                pre[i] = *(const float4*)(g_qkv + (size_t)(b * Lc + (kt + 1) * 64 + n) * QKVN
                                          + 2048 + kh * Dhc + c4);
            }
        }

        // ---- S = Q @ K^T (warp tile 32x32) ----
        float accS[2][4][4];
#pragma unroll
        for (int i = 0; i < 2; i++)
#pragma unroll
            for (int j = 0; j < 4; j++)
#pragma unroll
                for (int c = 0; c < 4; c++) accS[i][j][c] = 0.f;
#pragma unroll
        for (int kp = 0; kp < 8; kp++) {
            uint4 bb[4];
#pragma unroll
            for (int nj = 0; nj < 4; nj++)
                bb[nj] = *(const uint4*)&Kf[(kp * 8 + wn * 4 + nj) * 128 + l * 4];
#pragma unroll
            for (int hh = 0; hh < 2; hh++) {
                uint4 aa[2];
#pragma unroll
                for (int mi = 0; mi < 2; mi++)
                    aa[mi] = *(const uint4*)&Qf[((kp * 2 + hh) * 8 + wm * 2 + mi) * 128 + l * 4];
#pragma unroll
                for (int mi = 0; mi < 2; mi++)
#pragma unroll
                    for (int nj = 0; nj < 4; nj++)
                        mma8(accS[mi][nj], aa[mi],
                             hh ? bb[nj].z : bb[nj].x,
                             hh ? bb[nj].w : bb[nj].y);
            }
        }

        // ---- softmax part 1: scale, warp-partial max, exp, partial sum ----
        float pm[4], ps[4];
#pragma unroll
        for (int r = 0; r < 4; r++) { pm[r] = -1e30f; ps[r] = 0.f; }
#pragma unroll
        for (int mi = 0; mi < 2; mi++)
#pragma unroll
            for (int nj = 0; nj < 4; nj++)
#pragma unroll
                for (int c = 0; c < 4; c++) {
                    float v = accS[mi][nj][c] * SC;
                    accS[mi][nj][c] = v;
                    int ri = mi * 2 + (c >> 1);
                    pm[ri] = fmaxf(pm[ri], v);
                }
#pragma unroll
        for (int r = 0; r < 4; r++) {
            pm[r] = fmaxf(pm[r], __shfl_xor_sync(0xffffffffu, pm[r], 1));
            pm[r] = fmaxf(pm[r], __shfl_xor_sync(0xffffffffu, pm[r], 2));
        }
#pragma unroll
        for (int mi = 0; mi < 2; mi++)
#pragma unroll
            for (int nj = 0; nj < 4; nj++)
#pragma unroll
                for (int c = 0; c < 4; c++) {
                    int ri = mi * 2 + (c >> 1);
                    float p = __expf(accS[mi][nj][c] - pm[ri]);
                    accS[mi][nj][c] = p;
                    ps[ri] += p;
                }
#pragma unroll
        for (int r = 0; r < 4; r++) {
            ps[r] += __shfl_xor_sync(0xffffffffu, ps[r], 1);
            ps[r] += __shfl_xor_sync(0xffffffffu, ps[r], 2);
        }
        if (lo == 0) {
#pragma unroll
            for (int mi = 0; mi < 2; mi++)
#pragma unroll
                for (int rb = 0; rb < 2; rb++) {
                    int grow = wm * 32 + mi * 16 + lr + 8 * rb;
                    red[wn * 128 + grow] = make_float2(pm[mi * 2 + rb], ps[mi * 2 + rb]);
                }
        }
        __syncthreads();   // red ready; all warps done reading Kf

        // ---- merge stats across wn-halves, correct O, store Pf ----
        float cf[4], corr[4];
#pragma unroll
        for (int mi = 0; mi < 2; mi++)
#pragma unroll
            for (int rb = 0; rb < 2; rb++) {
                int ri = mi * 2 + rb;
                int grow = wm * 32 + mi * 16 + lr + 8 * rb;
                float2 f0 = red[grow], f1 = red[128 + grow];
                float mnew = fmaxf(m_run[ri], fmaxf(f0.x, f1.x));
                float gsum = f0.y * __expf(f0.x - mnew) + f1.y * __expf(f1.x - mnew);
                corr[ri] = __expf(m_run[ri] - mnew);
                l_run[ri] = l_run[ri] * corr[ri] + gsum;
                m_run[ri] = mnew;
                cf[ri] = __expf(pm[ri] - mnew);
            }
#pragma unroll
        for (int mi = 0; mi < 2; mi++)
#pragma unroll
            for (int nj = 0; nj < 8; nj++)
#pragma unroll
                for (int c = 0; c < 4; c++)
                    accO[mi][nj][c] *= corr[mi * 2 + (c >> 1)];
        // Pf store (A-frag layout, m=q row local, k=kv local)
#pragma unroll
        for (int mi = 0; mi < 2; mi++)
#pragma unroll
            for (int nj = 0; nj < 4; nj++)
#pragma unroll
                for (int c = 0; c < 4; c++) {
                    int rb = c >> 1, cb = c & 1;
                    int addr = ((wn * 4 + nj) * 8 + wm * 2 + mi) * 128
                             + lr * 16 + rb + (2 * (lo & 1) + cb) * 4 + (lo >> 1) * 2;
                    Pf[addr] = to_tf32(accS[mi][nj][c] * cf[mi * 2 + rb]);
                }
        // store prefetched K(t+1)
        if (more) {
#pragma unroll
            for (int i = 0; i < 8; i++) {
                int idx = t + (i << 8);
                int n = idx >> 5, c4 = (idx & 31) << 2;
                int base = ((c4 >> 4) * 8 + (n >> 3)) * 128 + (n & 7) * 16
                         + ((c4 >> 2) & 1) + ((c4 >> 3) & 1) * 2;
                Kf[base + 0] = to_tf32(pre[i].x); Kf[base + 4]  = to_tf32(pre[i].y);
                Kf[base + 8] = to_tf32(pre[i].z); Kf[base + 12] = to_tf32(pre[i].w);
            }
            // prefetch V(t+1)
#pragma unroll
            for (int i = 0; i < 8; i++) {
                int idx = t + (i << 8);
                int kv = idx >> 5, c4 = (idx & 31) << 2;
                pre[i] = *(const float4*)(g_qkv + (size_t)(b * Lc + (kt + 1) * 64 + kv) * QKVN
                                          + 3072 + kh * Dhc + c4);
            }
        }
        __syncthreads();   // Pf ready (Kf(t+1) ready for next iter)

        // ---- O += P @ V (warp tile 32x64) ----
#pragma unroll
        for (int kp = 0; kp < 4; kp++) {
            uint4 bb[8];
#pragma unroll
            for (int nj = 0; nj < 8; nj++)
                bb[nj] = *(const uint4*)&Vf[(kp * 16 + wn * 8 + nj) * 128 + l * 4];
#pragma unroll
            for (int hh = 0; hh < 2; hh++) {
                uint4 aa[2];
#pragma unroll
                for (int mi = 0; mi < 2; mi++)
                    aa[mi] = *(const uint4*)&Pf[((kp * 2 + hh) * 8 + wm * 2 + mi) * 128 + l * 4];
#pragma unroll
                for (int mi = 0; mi < 2; mi++)
#pragma unroll
                    for (int nj = 0; nj < 8; nj++)
                        mma8(accO[mi][nj], aa[mi],
                             hh ? bb[nj].z : bb[nj].x,
                             hh ? bb[nj].w : bb[nj].y);
            }
        }
        __syncthreads();   // all reads of Vf / Pf done

        // store prefetched V(t+1)
        if (more) {
#pragma unroll
            for (int i = 0; i < 8; i++) {
                int idx = t + (i << 8);
                int kv = idx >> 5, c4 = (idx & 31) << 2;
                int base = ((kv >> 4) * 16 + (c4 >> 3)) * 128 + (c4 & 7) * 16
                         + (kv & 3) * 4 + ((kv >> 2) & 1) + ((kv >> 3) & 1) * 2;
                Vf[base + 0]  = to_tf32(pre[i].x); Vf[base + 16] = to_tf32(pre[i].y);
                Vf[base + 32] = to_tf32(pre[i].z); Vf[base + 48] = to_tf32(pre[i].w);
            }
        }
    }

    // ---- epilogue: O /= l, write (tf32 for O-projection GEMM) ----
    float inv[4];
#pragma unroll
    for (int r = 0; r < 4; r++) inv[r] = 1.f / l_run[r];
#pragma unroll
    for (int mi = 0; mi < 2; mi++)
#pragma unroll
        for (int nj = 0; nj < 8; nj++) {
            int col = h * Dhc + wn * 64 + nj * 8 + 2 * lo;
#pragma unroll
            for (int rb = 0; rb < 2; rb++) {
                int row = q0 + wm * 32 + mi * 16 + lr + 8 * rb;
                float iv = inv[mi * 2 + rb];
                *(float2*)(go + (size_t)(b * Lc + row) * Dc + col) =
                    make_float2(to_tf32(accO[mi][nj][rb * 2 + 0] * iv),
                                to_tf32(accO[mi][nj][rb * 2 + 1] * iv));
            }
        }
}

// ================================ host ========================================
extern "C" void kernel_launch(void* const* d_in, const int* in_sizes, int n_in,
                              void* d_out, int out_size) {
    const float* hidden = (const float*)d_in[0];
    const float* temb   = (const float*)d_in[1];
    const float* w_ln   = (const float*)d_in[2];
    const float* w_mod  = (const float*)d_in[3];
    const float* b_mod  = (const float*)d_in[4];
    const float* wq     = (const float*)d_in[5];
    const float* wk     = (const float*)d_in[6];
    const float* wv     = (const float*)d_in[7];
    const float* wo     = (const float*)d_in[8];
    const float* qn     = (const float*)d_in[9];
    const float* kn     = (const float*)d_in[10];
    const float* cos1   = (const float*)d_in[11];
    const float* sin1   = (const float*)d_in[12];
    const float* rope3  = (const float*)d_in[13];
    const int*   mpos   = (const int*)d_in[14];
    float* out = (float*)d_out;

    void *pxm, *pqkv, *po, *pwT, *pwoT;
    cudaGetSymbolAddress(&pxm,  g_xm);
    cudaGetSymbolAddress(&pqkv, g_qkv);
    cudaGetSymbolAddress(&po,   g_o);
    cudaGetSymbolAddress(&pwT,  g_wT);
    cudaGetSymbolAddress(&pwoT, g_woT);

    cudaFuncSetAttribute(k_mma<0>, cudaFuncAttributeMaxDynamicSharedMemorySize, MMASMEM);
    cudaFuncSetAttribute(k_mma<1>, cudaFuncAttributeMaxDynamicSharedMemorySize, MMASMEM);
    cudaFuncSetAttribute(k_flash, cudaFuncAttributeMaxDynamicSharedMemorySize, FSMEM);

    k_mod<<<dim3(D3c / 256, Bc), 256>>>(temb, w_mod, b_mod);
    k_rmsmod<<<Bc * Lc, 256>>>(hidden, w_ln);

    k_transpose<<<dim3(Dc / 32, Dc / 32), dim3(32, 8)>>>(wq, (float*)pwT, Dc, Dc);
    k_transpose<<<dim3(1024 / 32, Dc / 32), dim3(32, 8)>>>(wk, (float*)pwT + (size_t)2048 * Dc, Dc, 1024);
    k_transpose<<<dim3(1024 / 32, Dc / 32), dim3(32, 8)>>>(wv, (float*)pwT + (size_t)3072 * Dc, Dc, 1024);
    k_transpose<<<dim3(Dc / 32, Dc / 32), dim3(32, 8)>>>(wo, (float*)pwoT, Dc, Dc);

    k_mma<0><<<dim3(QKVN / 256, (Bc * Lc) / 128), 256, MMASMEM>>>(
        (const float*)pxm, (const float*)pwT, (float*)pqkv, QKVN, Dc, nullptr);

    k_qknorm_rope<<<(Bc * Lc * (Hc + KVHc)) / 8, 256>>>(cos1, sin1, rope3, qn, kn, mpos);

    k_flash<<<dim3(Lc / 128, Hc, Bc), 256, FSMEM>>>((float*)po);

    k_mma<1><<<dim3(Dc / 256, (Bc * Lc) / 128), 256, MMASMEM>>>(
        (const float*)po, (const float*)pwoT, out, Dc, Dc, hidden);
}

// round 6
// speedup vs baseline: 1.0033x; 1.0033x over previous
#include <cuda_runtime.h>
#include <cstdint>

#define Bc   2
#define Lc   2048
#define Dc   2048
#define Hc   16
#define KVHc 8
#define Dhc  128
#define QKVN 4096
#define D3c  6144
#define EPSc 1e-5f

// ---------------- scratch (device globals: allocation-guard safe) -------------
__device__ float g_mod[Bc * D3c];
__device__ float g_xm [(size_t)Bc * Lc * Dc];
__device__ float g_qkv[(size_t)Bc * Lc * QKVN];   // 0..2047 Q | 2048..3071 K | 3072..4095 V
__device__ float g_o  [(size_t)Bc * Lc * Dc];
__device__ float g_wT [(size_t)QKVN * Dc];
__device__ float g_woT[(size_t)Dc * Dc];

__device__ __forceinline__ float to_tf32(float v) {
    uint32_t u; asm("cvt.rna.tf32.f32 %0, %1;" : "=r"(u) : "f"(v));
    return __uint_as_float(u);
}
__device__ __forceinline__ void mma8(float* d, const uint4& a, uint32_t b0, uint32_t b1) {
    asm volatile("mma.sync.aligned.m16n8k8.row.col.f32.tf32.tf32.f32 "
                 "{%0,%1,%2,%3}, {%4,%5,%6,%7}, {%8,%9}, {%0,%1,%2,%3};"
                 : "+f"(d[0]), "+f"(d[1]), "+f"(d[2]), "+f"(d[3])
                 : "r"(a.x), "r"(a.y), "r"(a.z), "r"(a.w), "r"(b0), "r"(b1));
}

// ================= kernel 1: mod = silu(temb) @ w_mod + b_mod =================
__global__ void k_mod(const float* __restrict__ temb, const float* __restrict__ w_mod,
                      const float* __restrict__ b_mod) {
    __shared__ float st[Dc];
    int b = blockIdx.y;
    int j = blockIdx.x * 256 + threadIdx.x;
    for (int i = threadIdx.x; i < Dc; i += 256) {
        float x = temb[b * Dc + i];
        st[i] = x / (1.f + __expf(-x));
    }
    __syncthreads();
    float acc = b_mod[j];
#pragma unroll 4
    for (int i = 0; i < Dc; i++) acc = fmaf(st[i], w_mod[(size_t)i * D3c + j], acc);
    g_mod[b * D3c + j] = acc;
}

// ====== kernel 2: xm = tf32(rmsnorm(x)*w_ln*(1+scale)+shift) ==================
__global__ void k_rmsmod(const float* __restrict__ x, const float* __restrict__ w_ln) {
    int row = blockIdx.x;
    int b   = row >> 11;
    const float* xr = x + (size_t)row * Dc;
    int tid = threadIdx.x;
    float ss = 0.f;
    for (int i = tid; i < Dc; i += 256) { float v = xr[i]; ss = fmaf(v, v, ss); }
#pragma unroll
    for (int o = 16; o; o >>= 1) ss += __shfl_xor_sync(0xffffffffu, ss, o);
    __shared__ float red[8];
    __shared__ float sinv;
    if ((tid & 31) == 0) red[tid >> 5] = ss;
    __syncthreads();
    if (tid == 0) {
        float t = 0.f;
#pragma unroll
        for (int w = 0; w < 8; w++) t += red[w];
        sinv = rsqrtf(t * (1.f / Dc) + EPSc);
    }
    __syncthreads();
    float inv = sinv;
    const float* sh = g_mod + b * D3c;
    const float* sc = sh + Dc;
    float* xm = g_xm + (size_t)row * Dc;
    for (int i = tid; i < Dc; i += 256)
        xm[i] = to_tf32(fmaf(xr[i] * inv * w_ln[i], 1.f + sc[i], sh[i]));
}

// ====== transpose src[K][N] -> dst[N][K], round tf32 ==========================
__global__ void k_transpose(const float* __restrict__ src, float* __restrict__ dst,
                            int K, int N) {
    __shared__ float t[32][33];
    int kb = blockIdx.y * 32, nb = blockIdx.x * 32;
    int x = threadIdx.x, y = threadIdx.y;
#pragma unroll
    for (int i = 0; i < 32; i += 8)
        t[y + i][x] = src[(size_t)(kb + y + i) * N + nb + x];
    __syncthreads();
#pragma unroll
    for (int i = 0; i < 32; i += 8)
        dst[(size_t)(nb + y + i) * K + kb + x] = to_tf32(t[x][y + i]);
}

// ====== tf32 mma.sync GEMM: C[M,N] = A[M,K] @ Bt[N,K]^T (round-3, verified) ===
#define MMASMEM (24576 * 4)

template<int EPI>
__global__ void __launch_bounds__(256, 1)
k_mma(const float* __restrict__ Ag, const float* __restrict__ Bg,
      float* __restrict__ C, int N, int K, const float* __restrict__ hid) {
    extern __shared__ float smf[];
    float* Asm = smf;
    float* Bsm = smf + 8192;

    int t = threadIdx.x, lane = t & 31, wid = t >> 5;
    int wm = wid >> 2, wn = wid & 3;
    int m0 = blockIdx.y * 128, n0 = blockIdx.x * 256;

    int r0 = t >> 3;
    int kb = (t & 7) * 4;
    int ch = (kb >> 2) & 1;
    int ks = kb >> 3;
    int half = ks & 1, kp = ks >> 1;
    int Abase = (ks * 8 + (r0 >> 4)) * 128 + (r0 & 7) * 16 + ((r0 & 15) >> 3) + 2 * ch;
    int Bbase = (kp * 32 + (r0 >> 3)) * 128 + (r0 & 7) * 16 + half * 2 + ch;

    const float* Aptr = Ag + (size_t)(m0 + r0) * K + kb;
    const float* Bptr = Bg + (size_t)(n0 + r0) * K + kb;

    float acc[4][8][4];
#pragma unroll
    for (int i = 0; i < 4; i++)
#pragma unroll
        for (int j = 0; j < 8; j++)
#pragma unroll
            for (int c = 0; c < 4; c++) acc[i][j][c] = 0.f;

    float4 pa[4], pb[8];
#pragma unroll
    for (int p = 0; p < 4; p++) pa[p] = *(const float4*)(Aptr + (size_t)(p * 32) * K);
#pragma unroll
    for (int p = 0; p < 8; p++) pb[p] = *(const float4*)(Bptr + (size_t)(p * 32) * K);
#pragma unroll
    for (int p = 0; p < 4; p++) {
        Asm[Abase + p * 256 + 0] = pa[p].x; Asm[Abase + p * 256 + 4] = pa[p].y;
        Asm[Abase + p * 256 + 8] = pa[p].z; Asm[Abase + p * 256 + 12] = pa[p].w;
    }
#pragma unroll
    for (int p = 0; p < 8; p++) {
        Bsm[Bbase + p * 512 + 0] = pb[p].x; Bsm[Bbase + p * 512 + 4] = pb[p].y;
        Bsm[Bbase + p * 512 + 8] = pb[p].z; Bsm[Bbase + p * 512 + 12] = pb[p].w;
    }
    __syncthreads();

    int nk = K >> 5;
    int buf = 0;
    for (int kt = 0; kt < nk; kt++) {
        bool more = (kt + 1 < nk);
        if (more) {
            const float* Ap = Aptr + (kt + 1) * 32;
            const float* Bp = Bptr + (kt + 1) * 32;
#pragma unroll
            for (int p = 0; p < 4; p++) pa[p] = *(const float4*)(Ap + (size_t)(p * 32) * K);
#pragma unroll
            for (int p = 0; p < 8; p++) pb[p] = *(const float4*)(Bp + (size_t)(p * 32) * K);
        }

        const float* Ab = Asm + buf * 4096;
        const float* Bb = Bsm + buf * 8192;
#pragma unroll
        for (int kpp = 0; kpp < 2; kpp++) {
            uint4 bb[8];
#pragma unroll
            for (int j = 0; j < 8; j++)
                bb[j] = *(const uint4*)(Bb + (kpp * 32 + wn * 8 + j) * 128 + lane * 4);
#pragma unroll
            for (int hh = 0; hh < 2; hh++) {
                uint4 aa[4];
#pragma unroll
                for (int i = 0; i < 4; i++)
                    aa[i] = *(const uint4*)(Ab + ((kpp * 2 + hh) * 8 + wm * 4 + i) * 128 + lane * 4);
#pragma unroll
                for (int i = 0; i < 4; i++)
#pragma unroll
                    for (int j = 0; j < 8; j++)
                        mma8(acc[i][j], aa[i],
                             hh ? bb[j].z : bb[j].x,
                             hh ? bb[j].w : bb[j].y);
            }
        }

        if (more) {
            float* Ab2 = Asm + (buf ^ 1) * 4096;
            float* Bb2 = Bsm + (buf ^ 1) * 8192;
#pragma unroll
            for (int p = 0; p < 4; p++) {
                Ab2[Abase + p * 256 + 0] = pa[p].x; Ab2[Abase + p * 256 + 4] = pa[p].y;
                Ab2[Abase + p * 256 + 8] = pa[p].z; Ab2[Abase + p * 256 + 12] = pa[p].w;
            }
#pragma unroll
            for (int p = 0; p < 8; p++) {
                Bb2[Bbase + p * 512 + 0] = pb[p].x; Bb2[Bbase + p * 512 + 4] = pb[p].y;
                Bb2[Bbase + p * 512 + 8] = pb[p].z; Bb2[Bbase + p * 512 + 12] = pb[p].w;
            }
        }
        __syncthreads();
        buf ^= 1;
    }

#pragma unroll
    for (int i = 0; i < 4; i++) {
        int gm = m0 + (wm * 4 + i) * 16 + (lane >> 2);
#pragma unroll
        for (int j = 0; j < 8; j++) {
            int gn = n0 + (wn * 8 + j) * 8 + 2 * (lane & 3);
            size_t o0 = (size_t)gm * N + gn;
            size_t o1 = (size_t)(gm + 8) * N + gn;
            if (EPI == 0) {
                *(float2*)(C + o0) = make_float2(acc[i][j][0], acc[i][j][1]);
                *(float2*)(C + o1) = make_float2(acc[i][j][2], acc[i][j][3]);
            } else {
                int b0 = gm >> 11, b1 = (gm + 8) >> 11;
                float2 h0 = *(const float2*)(hid + o0);
                float2 h1 = *(const float2*)(hid + o1);
                float2 g0 = *(const float2*)(g_mod + b0 * D3c + 2 * Dc + gn);
                float2 g1 = *(const float2*)(g_mod + b1 * D3c + 2 * Dc + gn);
                *(float2*)(C + o0) = make_float2(fmaf(g0.x, acc[i][j][0], h0.x),
                                                 fmaf(g0.y, acc[i][j][1], h0.y));
                *(float2*)(C + o1) = make_float2(fmaf(g1.x, acc[i][j][2], h1.x),
                                                 fmaf(g1.y, acc[i][j][3], h1.y));
            }
        }
    }
}

// ====== per-head RMSNorm + mixed RoPE =========================================
__global__ void __launch_bounds__(256)
k_qknorm_rope(const float* __restrict__ cos1d, const float* __restrict__ sin1d,
              const float* __restrict__ rope3d,
              const float* __restrict__ qn, const float* __restrict__ kn,
              const int* __restrict__ mp) {
    int warp = threadIdx.x >> 5, lane = threadIdx.x & 31;
    int v  = blockIdx.x * 8 + warp;
    int bl = v / 24, r = v % 24;
    int b = bl >> 11, l = bl & 2047;

    float* ptr; const float* w;
    if (r < Hc) { ptr = g_qkv + (size_t)bl * QKVN + r * Dhc;               w = qn; }
    else        { ptr = g_qkv + (size_t)bl * QKVN + 2048 + (r - Hc) * Dhc; w = kn; }

    float val[4];
    float ss = 0.f;
#pragma unroll
    for (int i = 0; i < 4; i++) { val[i] = ptr[lane + 32 * i]; ss = fmaf(val[i], val[i], ss); }
#pragma unroll
    for (int o = 16; o; o >>= 1) ss += __shfl_xor_sync(0xffffffffu, ss, o);
    float inv = rsqrtf(ss * (1.f / Dhc) + EPSc);
#pragma unroll
    for (int i = 0; i < 4; i++) val[i] *= inv * w[lane + 32 * i];

    bool is64 = (mp[1] == 0);
    bool in_full = false, in_img = false; int rel = 0;
#pragma unroll
    for (int m = 0; m < 2; m++) {
        int off, ln;
        if (is64) { off = mp[(b * 4 + m * 2) * 2]; ln = mp[(b * 4 + m * 2 + 1) * 2]; }
        else      { off = mp[b * 4 + m * 2];       ln = mp[b * 4 + m * 2 + 1]; }
        int seg_end = off + max(ln, 1);
        if (l >= off && l < seg_end) in_full = true;
        if (l >= off + 1 && l < off + ln) { in_img = true; rel += l - (off + 1); }
    }
    bool text = !in_full;
    bool img  = in_img && (rel < 1024);
    rel = min(max(rel, 0), 1023);

    float out[4];
    if (text) {
#pragma unroll
        for (int i = 0; i < 4; i++) {
            int d = lane + 32 * i;
            float c = cos1d[l * Dhc + d], s = sin1d[l * Dhc + d];
            float rot = (i < 2) ? -val[i ^ 2] : val[i ^ 2];
            out[i] = fmaf(val[i], c, rot * s);
        }
    } else {
#pragma unroll
        for (int i = 0; i < 4; i++) {
            int d = lane + 32 * i; int p = d >> 1; int jj = d & 1;
            float partner = __shfl_xor_sync(0xffffffffu, val[i], 1);
            float q0 = jj ? partner : val[i];
            float q1 = jj ? val[i] : partner;
            const float* R = rope3d + ((size_t)rel * 64 + p) * 4;
            float oimg = fmaf(q0, R[jj], q1 * R[2 + jj]);
            out[i] = img ? oimg : val[i];
        }
    }
#pragma unroll
    for (int i = 0; i < 4; i++) ptr[lane + 32 * i] = out[i];
}

// ====== flash attention, tf32 mma.sync ========================================
// CTA: 128 q-rows x 1 head. 8 warps (4 m x 2 n). kv-tile = 64.
// smem floats: Qf[16384] Kf[8192] Vf[8192] Pf[8192] red[512]
#define FSMEM ((16384 + 8192 + 8192 + 8192 + 512) * 4)

__global__ void __launch_bounds__(256, 1)
k_flash(float* __restrict__ go) {
    extern __shared__ float sm[];
    float*  Qf  = sm;
    float*  Kf  = sm + 16384;
    float*  Vf  = sm + 24576;
    float*  Pf  = sm + 32768;
    float2* red = (float2*)(sm + 40960);   // [wn][128] (rowmax, rowsum)

    int t = threadIdx.x, l = t & 31, wid = t >> 5;
    int lo = l & 3, lr = l >> 2;
    int wm = wid >> 1, wn = wid & 1;
    int q0 = blockIdx.x << 7;
    int h  = blockIdx.y, b = blockIdx.z;
    int kh = h >> 1;
    const float SC = 0.08838834764831845f;   // 1/sqrt(128)

    // ---- load Q (once) into A-fragment layout, tf32 ----
    {
        const float* qb = g_qkv + (size_t)(b * Lc + q0) * QKVN + h * Dhc;
#pragma unroll
        for (int i = 0; i < 16; i++) {
            int idx = t + (i << 8);
            int row = idx >> 5, c4 = (idx & 31) << 2;
            float4 v = *(const float4*)(qb + (size_t)row * QKVN + c4);
            int base = ((c4 >> 3) * 8 + (row >> 4)) * 128 + (row & 7) * 16
                     + ((row >> 3) & 1) + ((c4 >> 2) & 1) * 2;
            Qf[base + 0]  = to_tf32(v.x); Qf[base + 4]  = to_tf32(v.y);
            Qf[base + 8]  = to_tf32(v.z); Qf[base + 12] = to_tf32(v.w);
        }
    }
    // ---- load K(0), V(0) ----
    {
#pragma unroll
        for (int i = 0; i < 8; i++) {
            int idx = t + (i << 8);
            int n = idx >> 5, c4 = (idx & 31) << 2;
            float4 v = *(const float4*)(g_qkv + (size_t)(b * Lc + n) * QKVN + 2048 + kh * Dhc + c4);
            int base = ((c4 >> 4) * 8 + (n >> 3)) * 128 + (n & 7) * 16
                     + ((c4 >> 2) & 1) + ((c4 >> 3) & 1) * 2;
            Kf[base + 0] = to_tf32(v.x); Kf[base + 4] = to_tf32(v.y);
            Kf[base + 8] = to_tf32(v.z); Kf[base + 12] = to_tf32(v.w);
        }
#pragma unroll
        for (int i = 0; i < 8; i++) {
            int idx = t + (i << 8);
            int kv = idx >> 5, c4 = (idx & 31) << 2;
            float4 v = *(const float4*)(g_qkv + (size_t)(b * Lc + kv) * QKVN + 3072 + kh * Dhc + c4);
            int base = ((kv >> 4) * 16 + (c4 >> 3)) * 128 + (c4 & 7) * 16
                     + (kv & 3) * 4 + ((kv >> 2) & 1) + ((kv >> 3) & 1) * 2;
            Vf[base + 0]  = to_tf32(v.x); Vf[base + 16] = to_tf32(v.y);
            Vf[base + 32] = to_tf32(v.z); Vf[base + 48] = to_tf32(v.w);
        }
    }
    __syncthreads();

    float accO[2][8][4];
    float m_run[4], l_run[4];
#pragma unroll
    for (int i = 0; i < 2; i++)
#pragma unroll
        for (int j = 0; j < 8; j++)
#pragma unroll
            for (int c = 0; c < 4; c++) accO[i][j][c] = 0.f;
#pragma unroll
    for (int r = 0; r < 4; r++) { m_run[r] = -1e30f; l_run[r] = 0.f; }

    for (int kt = 0; kt < 32; kt++) {
        bool more = (kt + 1 < 32);
        // prefetch K(t+1)
        float4 pre[8];
        if (more) {
#pragma unroll
            for (int i = 0; i < 8; i++) {
                int idx = t + (i << 8);
                int n = idx >> 5, c4 = (idx & 31) << 2;
                pre[i] = *(const float4*)(g_qkv + (size_t)(b * Lc + (kt + 1) * 64 + n) * QKVN
                                          + 2048 + kh * Dhc + c4);
            }
        }

        // ---- S = Q @ K^T (warp tile 32x32) ----
        float accS[2][4][4];
#pragma unroll
        for (int i = 0; i < 2; i++)
#pragma unroll
            for (int j = 0; j < 4; j++)
#pragma unroll
                for (int c = 0; c < 4; c++) accS[i][j][c] = 0.f;
#pragma unroll
        for (int kp = 0; kp < 8; kp++) {
            uint4 bb[4];
#pragma unroll
            for (int nj = 0; nj < 4; nj++)
                bb[nj] = *(const uint4*)&Kf[(kp * 8 + wn * 4 + nj) * 128 + l * 4];
#pragma unroll
            for (int hh = 0; hh < 2; hh++) {
                uint4 aa[2];
#pragma unroll
                for (int mi = 0; mi < 2; mi++)
                    aa[mi] = *(const uint4*)&Qf[((kp * 2 + hh) * 8 + wm * 2 + mi) * 128 + l * 4];
#pragma unroll
                for (int mi = 0; mi < 2; mi++)
#pragma unroll
                    for (int nj = 0; nj < 4; nj++)
                        mma8(accS[mi][nj], aa[mi],
                             hh ? bb[nj].z : bb[nj].x,
                             hh ? bb[nj].w : bb[nj].y);
            }
        }

        // ---- softmax part 1: scale, warp-partial max, exp, partial sum ----
        float pm[4], ps[4];
#pragma unroll
        for (int r = 0; r < 4; r++) { pm[r] = -1e30f; ps[r] = 0.f; }
#pragma unroll
        for (int mi = 0; mi < 2; mi++)
#pragma unroll
            for (int nj = 0; nj < 4; nj++)
#pragma unroll
                for (int c = 0; c < 4; c++) {
                    float v = accS[mi][nj][c] * SC;
                    accS[mi][nj][c] = v;
                    int ri = mi * 2 + (c >> 1);
                    pm[ri] = fmaxf(pm[ri], v);
                }
#pragma unroll
        for (int r = 0; r < 4; r++) {
            pm[r] = fmaxf(pm[r], __shfl_xor_sync(0xffffffffu, pm[r], 1));
            pm[r] = fmaxf(pm[r], __shfl_xor_sync(0xffffffffu, pm[r], 2));
        }
#pragma unroll
        for (int mi = 0; mi < 2; mi++)
#pragma unroll
            for (int nj = 0; nj < 4; nj++)
#pragma unroll
                for (int c = 0; c < 4; c++) {
                    int ri = mi * 2 + (c >> 1);
                    float p = __expf(accS[mi][nj][c] - pm[ri]);
                    accS[mi][nj][c] = p;
                    ps[ri] += p;
                }
#pragma unroll
        for (int r = 0; r < 4; r++) {
            ps[r] += __shfl_xor_sync(0xffffffffu, ps[r], 1);
            ps[r] += __shfl_xor_sync(0xffffffffu, ps[r], 2);
        }
        if (lo == 0) {
#pragma unroll
            for (int mi = 0; mi < 2; mi++)
#pragma unroll
                for (int rb = 0; rb < 2; rb++) {
                    int grow = wm * 32 + mi * 16 + lr + 8 * rb;
                    red[wn * 128 + grow] = make_float2(pm[mi * 2 + rb], ps[mi * 2 + rb]);
                }
        }
        __syncthreads();   // red ready; all warps done reading Kf

        // ---- merge stats across wn-halves, correct O, store Pf ----
        float cf[4], corr[4];
#pragma unroll
        for (int mi = 0; mi < 2; mi++)
#pragma unroll
            for (int rb = 0; rb < 2; rb++) {
                int ri = mi * 2 + rb;
                int grow = wm * 32 + mi * 16 + lr + 8 * rb;
                float2 f0 = red[grow], f1 = red[128 + grow];
                float mnew = fmaxf(m_run[ri], fmaxf(f0.x, f1.x));
                float gsum = f0.y * __expf(f0.x - mnew) + f1.y * __expf(f1.x - mnew);
                corr[ri] = __expf(m_run[ri] - mnew);
                l_run[ri] = l_run[ri] * corr[ri] + gsum;
                m_run[ri] = mnew;
                cf[ri] = __expf(pm[ri] - mnew);
            }
#pragma unroll
        for (int mi = 0; mi < 2; mi++)
#pragma unroll
            for (int nj = 0; nj < 8; nj++)
#pragma unroll
                for (int c = 0; c < 4; c++)
                    accO[mi][nj][c] *= corr[mi * 2 + (c >> 1)];
        // Pf store (A-frag layout, m=q row local, k=kv local)
#pragma unroll
        for (int mi = 0; mi < 2; mi++)
#pragma unroll
            for (int nj = 0; nj < 4; nj++)
#pragma unroll
                for (int c = 0; c < 4; c++) {
                    int rb = c >> 1, cb = c & 1;
                    int addr = ((wn * 4 + nj) * 8 + wm * 2 + mi) * 128
                             + lr * 16 + rb + (2 * (lo & 1) + cb) * 4 + (lo >> 1) * 2;
                    Pf[addr] = to_tf32(accS[mi][nj][c] * cf[mi * 2 + rb]);
                }
        // store prefetched K(t+1)
        if (more) {
#pragma unroll
            for (int i = 0; i < 8; i++) {
                int idx = t + (i << 8);
                int n = idx >> 5, c4 = (idx & 31) << 2;
                int base = ((c4 >> 4) * 8 + (n >> 3)) * 128 + (n & 7) * 16
                         + ((c4 >> 2) & 1) + ((c4 >> 3) & 1) * 2;
                Kf[base + 0] = to_tf32(pre[i].x); Kf[base + 4]  = to_tf32(pre[i].y);
                Kf[base + 8] = to_tf32(pre[i].z); Kf[base + 12] = to_tf32(pre[i].w);
            }
            // prefetch V(t+1)
#pragma unroll
            for (int i = 0; i < 8; i++) {
                int idx = t + (i << 8);
                int kv = idx >> 5, c4 = (idx & 31) << 2;
                pre[i] = *(const float4*)(g_qkv + (size_t)(b * Lc + (kt + 1) * 64 + kv) * QKVN
                                          + 3072 + kh * Dhc + c4);
            }
        }
        __syncthreads();   // Pf ready (Kf(t+1) ready for next iter)

        // ---- O += P @ V (warp tile 32x64) ----
#pragma unroll
        for (int kp = 0; kp < 4; kp++) {
            uint4 bb[8];
#pragma unroll
            for (int nj = 0; nj < 8; nj++)
                bb[nj] = *(const uint4*)&Vf[(kp * 16 + wn * 8 + nj) * 128 + l * 4];
#pragma unroll
            for (int hh = 0; hh < 2; hh++) {
                uint4 aa[2];
#pragma unroll
                for (int mi = 0; mi < 2; mi++)
                    aa[mi] = *(const uint4*)&Pf[((kp * 2 + hh) * 8 + wm * 2 + mi) * 128 + l * 4];
#pragma unroll
                for (int mi = 0; mi < 2; mi++)
#pragma unroll
                    for (int nj = 0; nj < 8; nj++)
                        mma8(accO[mi][nj], aa[mi],
                             hh ? bb[nj].z : bb[nj].x,
                             hh ? bb[nj].w : bb[nj].y);
            }
        }
        __syncthreads();   // all reads of Vf / Pf done

        // store prefetched V(t+1)
        if (more) {
#pragma unroll
            for (int i = 0; i < 8; i++) {
                int idx = t + (i << 8);
                int kv = idx >> 5, c4 = (idx & 31) << 2;
                int base = ((kv >> 4) * 16 + (c4 >> 3)) * 128 + (c4 & 7) * 16
                         + (kv & 3) * 4 + ((kv >> 2) & 1) + ((kv >> 3) & 1) * 2;
                Vf[base + 0]  = to_tf32(pre[i].x); Vf[base + 16] = to_tf32(pre[i].y);
                Vf[base + 32] = to_tf32(pre[i].z); Vf[base + 48] = to_tf32(pre[i].w);
            }
        }
    }

    // ---- epilogue: O /= l, write (tf32 for O-projection GEMM) ----
    float inv[4];
#pragma unroll
    for (int r = 0; r < 4; r++) inv[r] = 1.f / l_run[r];
#pragma unroll
    for (int mi = 0; mi < 2; mi++)
#pragma unroll
        for (int nj = 0; nj < 8; nj++) {
            int col = h * Dhc + wn * 64 + nj * 8 + 2 * lo;
#pragma unroll
            for (int rb = 0; rb < 2; rb++) {
                int row = q0 + wm * 32 + mi * 16 + lr + 8 * rb;
                float iv = inv[mi * 2 + rb];
                *(float2*)(go + (size_t)(b * Lc + row) * Dc + col) =
                    make_float2(to_tf32(accO[mi][nj][rb * 2 + 0] * iv),
                                to_tf32(accO[mi][nj][rb * 2 + 1] * iv));
            }
        }
}

// ================================ host ========================================
extern "C" void kernel_launch(void* const* d_in, const int* in_sizes, int n_in,
                              void* d_out, int out_size) {
    const float* hidden = (const float*)d_in[0];
    const float* temb   = (const float*)d_in[1];
    const float* w_ln   = (const float*)d_in[2];
    const float* w_mod  = (const float*)d_in[3];
    const float* b_mod  = (const float*)d_in[4];
    const float* wq     = (const float*)d_in[5];
    const float* wk     = (const float*)d_in[6];
    const float* wv     = (const float*)d_in[7];
    const float* wo     = (const float*)d_in[8];
    const float* qn     = (const float*)d_in[9];
    const float* kn     = (const float*)d_in[10];
    const float* cos1   = (const float*)d_in[11];
    const float* sin1   = (const float*)d_in[12];
    const float* rope3  = (const float*)d_in[13];
    const int*   mpos   = (const int*)d_in[14];
    float* out = (float*)d_out;

    void *pxm, *pqkv, *po, *pwT, *pwoT;
    cudaGetSymbolAddress(&pxm,  g_xm);
    cudaGetSymbolAddress(&pqkv, g_qkv);
    cudaGetSymbolAddress(&po,   g_o);
    cudaGetSymbolAddress(&pwT,  g_wT);
    cudaGetSymbolAddress(&pwoT, g_woT);

    cudaFuncSetAttribute(k_mma<0>, cudaFuncAttributeMaxDynamicSharedMemorySize, MMASMEM);
    cudaFuncSetAttribute(k_mma<1>, cudaFuncAttributeMaxDynamicSharedMemorySize, MMASMEM);
    cudaFuncSetAttribute(k_flash, cudaFuncAttributeMaxDynamicSharedMemorySize, FSMEM);

    k_mod<<<dim3(D3c / 256, Bc), 256>>>(temb, w_mod, b_mod);
    k_rmsmod<<<Bc * Lc, 256>>>(hidden, w_ln);

    k_transpose<<<dim3(Dc / 32, Dc / 32), dim3(32, 8)>>>(wq, (float*)pwT, Dc, Dc);
    k_transpose<<<dim3(1024 / 32, Dc / 32), dim3(32, 8)>>>(wk, (float*)pwT + (size_t)2048 * Dc, Dc, 1024);
    k_transpose<<<dim3(1024 / 32, Dc / 32), dim3(32, 8)>>>(wv, (float*)pwT + (size_t)3072 * Dc, Dc, 1024);
    k_transpose<<<dim3(Dc / 32, Dc / 32), dim3(32, 8)>>>(wo, (float*)pwoT, Dc, Dc);

    k_mma<0><<<dim3(QKVN / 256, (Bc * Lc) / 128), 256, MMASMEM>>>(
        (const float*)pxm, (const float*)pwT, (float*)pqkv, QKVN, Dc, nullptr);

    k_qknorm_rope<<<(Bc * Lc * (Hc + KVHc)) / 8, 256>>>(cos1, sin1, rope3, qn, kn, mpos);

    k_flash<<<dim3(Lc / 128, Hc, Bc), 256, FSMEM>>>((float*)po);

    k_mma<1><<<dim3(Dc / 256, (Bc * Lc) / 128), 256, MMASMEM>>>(
        (const float*)po, (const float*)pwoT, out, Dc, Dc, hidden);
}

// round 7
// speedup vs baseline: 1.0082x; 1.0048x over previous
#include <cuda_runtime.h>
#include <cstdint>

#define Bc   2
#define Lc   2048
#define Dc   2048
#define Hc   16
#define KVHc 8
#define Dhc  128
#define QKVN 4096
#define D3c  6144
#define EPSc 1e-5f

// ---------------- scratch (device globals: allocation-guard safe) -------------
__device__ float g_mod[Bc * D3c];
__device__ float g_xm [(size_t)Bc * Lc * Dc];
__device__ float g_qkv[(size_t)Bc * Lc * QKVN];   // 0..2047 Q | 2048..3071 K | 3072..4095 V
__device__ float g_o  [(size_t)Bc * Lc * Dc];
__device__ float g_wT [(size_t)QKVN * Dc];
__device__ float g_woT[(size_t)Dc * Dc];

__device__ __forceinline__ float to_tf32(float v) {
    uint32_t u; asm("cvt.rna.tf32.f32 %0, %1;" : "=r"(u) : "f"(v));
    return __uint_as_float(u);
}
__device__ __forceinline__ void mma8(float* d, const uint4& a, uint32_t b0, uint32_t b1) {
    asm volatile("mma.sync.aligned.m16n8k8.row.col.f32.tf32.tf32.f32 "
                 "{%0,%1,%2,%3}, {%4,%5,%6,%7}, {%8,%9}, {%0,%1,%2,%3};"
                 : "+f"(d[0]), "+f"(d[1]), "+f"(d[2]), "+f"(d[3])
                 : "r"(a.x), "r"(a.y), "r"(a.z), "r"(a.w), "r"(b0), "r"(b1));
}

// ================= kernel 1: mod = silu(temb) @ w_mod + b_mod =================
__global__ void k_mod(const float* __restrict__ temb, const float* __restrict__ w_mod,
                      const float* __restrict__ b_mod) {
    __shared__ float st[Dc];
    int b = blockIdx.y;
    int j = blockIdx.x * 256 + threadIdx.x;
    for (int i = threadIdx.x; i < Dc; i += 256) {
        float x = temb[b * Dc + i];
        st[i] = x / (1.f + __expf(-x));
    }
    __syncthreads();
    float acc = b_mod[j];
#pragma unroll 4
    for (int i = 0; i < Dc; i++) acc = fmaf(st[i], w_mod[(size_t)i * D3c + j], acc);
    g_mod[b * D3c + j] = acc;
}

// ====== kernel 2: xm = tf32(rmsnorm(x)*w_ln*(1+scale)+shift) ==================
__global__ void k_rmsmod(const float* __restrict__ x, const float* __restrict__ w_ln) {
    int row = blockIdx.x;
    int b   = row >> 11;
    const float* xr = x + (size_t)row * Dc;
    int tid = threadIdx.x;
    float ss = 0.f;
    for (int i = tid; i < Dc; i += 256) { float v = xr[i]; ss = fmaf(v, v, ss); }
#pragma unroll
    for (int o = 16; o; o >>= 1) ss += __shfl_xor_sync(0xffffffffu, ss, o);
    __shared__ float red[8];
    __shared__ float sinv;
    if ((tid & 31) == 0) red[tid >> 5] = ss;
    __syncthreads();
    if (tid == 0) {
        float t = 0.f;
#pragma unroll
        for (int w = 0; w < 8; w++) t += red[w];
        sinv = rsqrtf(t * (1.f / Dc) + EPSc);
    }
    __syncthreads();
    float inv = sinv;
    const float* sh = g_mod + b * D3c;
    const float* sc = sh + Dc;
    float* xm = g_xm + (size_t)row * Dc;
    for (int i = tid; i < Dc; i += 256)
        xm[i] = to_tf32(fmaf(xr[i] * inv * w_ln[i], 1.f + sc[i], sh[i]));
}

// ====== transpose src[K][N] -> dst[N][K], round tf32 ==========================
__global__ void k_transpose(const float* __restrict__ src, float* __restrict__ dst,
                            int K, int N) {
    __shared__ float t[32][33];
    int kb = blockIdx.y * 32, nb = blockIdx.x * 32;
    int x = threadIdx.x, y = threadIdx.y;
#pragma unroll
    for (int i = 0; i < 32; i += 8)
        t[y + i][x] = src[(size_t)(kb + y + i) * N + nb + x];
    __syncthreads();
#pragma unroll
    for (int i = 0; i < 32; i += 8)
        dst[(size_t)(nb + y + i) * K + kb + x] = to_tf32(t[x][y + i]);
}

// ====== tf32 mma.sync GEMM: C[M,N] = A[M,K] @ Bt[N,K]^T (round-3, verified) ===
#define MMASMEM (24576 * 4)

template<int EPI>
__global__ void __launch_bounds__(256, 1)
k_mma(const float* __restrict__ Ag, const float* __restrict__ Bg,
      float* __restrict__ C, int N, int K, const float* __restrict__ hid) {
    extern __shared__ float smf[];
    float* Asm = smf;
    float* Bsm = smf + 8192;

    int t = threadIdx.x, lane = t & 31, wid = t >> 5;
    int wm = wid >> 2, wn = wid & 3;
    int m0 = blockIdx.y * 128, n0 = blockIdx.x * 256;

    int r0 = t >> 3;
    int kb = (t & 7) * 4;
    int ch = (kb >> 2) & 1;
    int ks = kb >> 3;
    int half = ks & 1, kp = ks >> 1;
    int Abase = (ks * 8 + (r0 >> 4)) * 128 + (r0 & 7) * 16 + ((r0 & 15) >> 3) + 2 * ch;
    int Bbase = (kp * 32 + (r0 >> 3)) * 128 + (r0 & 7) * 16 + half * 2 + ch;

    const float* Aptr = Ag + (size_t)(m0 + r0) * K + kb;
    const float* Bptr = Bg + (size_t)(n0 + r0) * K + kb;

    float acc[4][8][4];
#pragma unroll
    for (int i = 0; i < 4; i++)
#pragma unroll
        for (int j = 0; j < 8; j++)
#pragma unroll
            for (int c = 0; c < 4; c++) acc[i][j][c] = 0.f;

    float4 pa[4], pb[8];
#pragma unroll
    for (int p = 0; p < 4; p++) pa[p] = *(const float4*)(Aptr + (size_t)(p * 32) * K);
#pragma unroll
    for (int p = 0; p < 8; p++) pb[p] = *(const float4*)(Bptr + (size_t)(p * 32) * K);
#pragma unroll
    for (int p = 0; p < 4; p++) {
        Asm[Abase + p * 256 + 0] = pa[p].x; Asm[Abase + p * 256 + 4] = pa[p].y;
        Asm[Abase + p * 256 + 8] = pa[p].z; Asm[Abase + p * 256 + 12] = pa[p].w;
    }
#pragma unroll
    for (int p = 0; p < 8; p++) {
        Bsm[Bbase + p * 512 + 0] = pb[p].x; Bsm[Bbase + p * 512 + 4] = pb[p].y;
        Bsm[Bbase + p * 512 + 8] = pb[p].z; Bsm[Bbase + p * 512 + 12] = pb[p].w;
    }
    __syncthreads();

    int nk = K >> 5;
    int buf = 0;
    for (int kt = 0; kt < nk; kt++) {
        bool more = (kt + 1 < nk);
        if (more) {
            const float* Ap = Aptr + (kt + 1) * 32;
            const float* Bp = Bptr + (kt + 1) * 32;
#pragma unroll
            for (int p = 0; p < 4; p++) pa[p] = *(const float4*)(Ap + (size_t)(p * 32) * K);
#pragma unroll
            for (int p = 0; p < 8; p++) pb[p] = *(const float4*)(Bp + (size_t)(p * 32) * K);
        }

        const float* Ab = Asm + buf * 4096;
        const float* Bb = Bsm + buf * 8192;
#pragma unroll
        for (int kpp = 0; kpp < 2; kpp++) {
            uint4 bb[8];
#pragma unroll
            for (int j = 0; j < 8; j++)
                bb[j] = *(const uint4*)(Bb + (kpp * 32 + wn * 8 + j) * 128 + lane * 4);
#pragma unroll
            for (int hh = 0; hh < 2; hh++) {
                uint4 aa[4];
#pragma unroll
                for (int i = 0; i < 4; i++)
                    aa[i] = *(const uint4*)(Ab + ((kpp * 2 + hh) * 8 + wm * 4 + i) * 128 + lane * 4);
#pragma unroll
                for (int i = 0; i < 4; i++)
#pragma unroll
                    for (int j = 0; j < 8; j++)
                        mma8(acc[i][j], aa[i],
                             hh ? bb[j].z : bb[j].x,
                             hh ? bb[j].w : bb[j].y);
            }
        }

        if (more) {
            float* Ab2 = Asm + (buf ^ 1) * 4096;
            float* Bb2 = Bsm + (buf ^ 1) * 8192;
#pragma unroll
            for (int p = 0; p < 4; p++) {
                Ab2[Abase + p * 256 + 0] = pa[p].x; Ab2[Abase + p * 256 + 4] = pa[p].y;
                Ab2[Abase + p * 256 + 8] = pa[p].z; Ab2[Abase + p * 256 + 12] = pa[p].w;
            }
#pragma unroll
            for (int p = 0; p < 8; p++) {
                Bb2[Bbase + p * 512 + 0] = pb[p].x; Bb2[Bbase + p * 512 + 4] = pb[p].y;
                Bb2[Bbase + p * 512 + 8] = pb[p].z; Bb2[Bbase + p * 512 + 12] = pb[p].w;
            }
        }
        __syncthreads();
        buf ^= 1;
    }

#pragma unroll
    for (int i = 0; i < 4; i++) {
        int gm = m0 + (wm * 4 + i) * 16 + (lane >> 2);
#pragma unroll
        for (int j = 0; j < 8; j++) {
            int gn = n0 + (wn * 8 + j) * 8 + 2 * (lane & 3);
            size_t o0 = (size_t)gm * N + gn;
            size_t o1 = (size_t)(gm + 8) * N + gn;
            if (EPI == 0) {
                *(float2*)(C + o0) = make_float2(acc[i][j][0], acc[i][j][1]);
                *(float2*)(C + o1) = make_float2(acc[i][j][2], acc[i][j][3]);
            } else {
                int b0 = gm >> 11, b1 = (gm + 8) >> 11;
                float2 h0 = *(const float2*)(hid + o0);
                float2 h1 = *(const float2*)(hid + o1);
                float2 g0 = *(const float2*)(g_mod + b0 * D3c + 2 * Dc + gn);
                float2 g1 = *(const float2*)(g_mod + b1 * D3c + 2 * Dc + gn);
                *(float2*)(C + o0) = make_float2(fmaf(g0.x, acc[i][j][0], h0.x),
                                                 fmaf(g0.y, acc[i][j][1], h0.y));
                *(float2*)(C + o1) = make_float2(fmaf(g1.x, acc[i][j][2], h1.x),
                                                 fmaf(g1.y, acc[i][j][3], h1.y));
            }
        }
    }
}

// ====== per-head RMSNorm + mixed RoPE =========================================
__global__ void __launch_bounds__(256)
k_qknorm_rope(const float* __restrict__ cos1d, const float* __restrict__ sin1d,
              const float* __restrict__ rope3d,
              const float* __restrict__ qn, const float* __restrict__ kn,
              const int* __restrict__ mp) {
    int warp = threadIdx.x >> 5, lane = threadIdx.x & 31;
    int v  = blockIdx.x * 8 + warp;
    int bl = v / 24, r = v % 24;
    int b = bl >> 11, l = bl & 2047;

    float* ptr; const float* w;
    if (r < Hc) { ptr = g_qkv + (size_t)bl * QKVN + r * Dhc;               w = qn; }
    else        { ptr = g_qkv + (size_t)bl * QKVN + 2048 + (r - Hc) * Dhc; w = kn; }

    float val[4];
    float ss = 0.f;
#pragma unroll
    for (int i = 0; i < 4; i++) { val[i] = ptr[lane + 32 * i]; ss = fmaf(val[i], val[i], ss); }
#pragma unroll
    for (int o = 16; o; o >>= 1) ss += __shfl_xor_sync(0xffffffffu, ss, o);
    float inv = rsqrtf(ss * (1.f / Dhc) + EPSc);
#pragma unroll
    for (int i = 0; i < 4; i++) val[i] *= inv * w[lane + 32 * i];

    bool is64 = (mp[1] == 0);
    bool in_full = false, in_img = false; int rel = 0;
#pragma unroll
    for (int m = 0; m < 2; m++) {
        int off, ln;
        if (is64) { off = mp[(b * 4 + m * 2) * 2]; ln = mp[(b * 4 + m * 2 + 1) * 2]; }
        else      { off = mp[b * 4 + m * 2];       ln = mp[b * 4 + m * 2 + 1]; }
        int seg_end = off + max(ln, 1);
        if (l >= off && l < seg_end) in_full = true;
        if (l >= off + 1 && l < off + ln) { in_img = true; rel += l - (off + 1); }
    }
    bool text = !in_full;
    bool img  = in_img && (rel < 1024);
    rel = min(max(rel, 0), 1023);

    float out[4];
    if (text) {
#pragma unroll
        for (int i = 0; i < 4; i++) {
            int d = lane + 32 * i;
            float c = cos1d[l * Dhc + d], s = sin1d[l * Dhc + d];
            float rot = (i < 2) ? -val[i ^ 2] : val[i ^ 2];
            out[i] = fmaf(val[i], c, rot * s);
        }
    } else {
#pragma unroll
        for (int i = 0; i < 4; i++) {
            int d = lane + 32 * i; int p = d >> 1; int jj = d & 1;
            float partner = __shfl_xor_sync(0xffffffffu, val[i], 1);
            float q0 = jj ? partner : val[i];
            float q1 = jj ? val[i] : partner;
            const float* R = rope3d + ((size_t)rel * 64 + p) * 4;
            float oimg = fmaf(q0, R[jj], q1 * R[2 + jj]);
            out[i] = img ? oimg : val[i];
        }
    }
#pragma unroll
    for (int i = 0; i < 4; i++) ptr[lane + 32 * i] = out[i];
}

// ====== flash attention, tf32 mma.sync ========================================
// CTA: 128 q-rows x 1 head. 8 warps (4 m x 2 n). kv-tile = 64.
// smem floats: Qf[16384] Kf[8192] Vf[8192] Pf[8192] red[512]
#define FSMEM ((16384 + 8192 + 8192 + 8192 + 512) * 4)

__global__ void __launch_bounds__(256, 1)
k_flash(float* __restrict__ go) {
    extern __shared__ float sm[];
    float*  Qf  = sm;
    float*  Kf  = sm + 16384;
    float*  Vf  = sm + 24576;
    float*  Pf  = sm + 32768;
    float2* red = (float2*)(sm + 40960);   // [wn][128] (rowmax, rowsum)

    int t = threadIdx.x, l = t & 31, wid = t >> 5;
    int lo = l & 3, lr = l >> 2;
    int wm = wid >> 1, wn = wid & 1;
    int q0 = blockIdx.x << 7;
    int h  = blockIdx.y, b = blockIdx.z;
    int kh = h >> 1;
    const float SC = 0.08838834764831845f;   // 1/sqrt(128)

    // ---- load Q (once) into A-fragment layout, tf32 ----
    {
        const float* qb = g_qkv + (size_t)(b * Lc + q0) * QKVN + h * Dhc;
#pragma unroll
        for (int i = 0; i < 16; i++) {
            int idx = t + (i << 8);
            int row = idx >> 5, c4 = (idx & 31) << 2;
            float4 v = *(const float4*)(qb + (size_t)row * QKVN + c4);
            int base = ((c4 >> 3) * 8 + (row >> 4)) * 128 + (row & 7) * 16
                     + ((row >> 3) & 1) + ((c4 >> 2) & 1) * 2;
            Qf[base + 0]  = to_tf32(v.x); Qf[base + 4]  = to_tf32(v.y);
            Qf[base + 8]  = to_tf32(v.z); Qf[base + 12] = to_tf32(v.w);
        }
    }
    // ---- load K(0), V(0) ----
    {
#pragma unroll
        for (int i = 0; i < 8; i++) {
            int idx = t + (i << 8);
            int n = idx >> 5, c4 = (idx & 31) << 2;
            float4 v = *(const float4*)(g_qkv + (size_t)(b * Lc + n) * QKVN + 2048 + kh * Dhc + c4);
            int base = ((c4 >> 4) * 8 + (n >> 3)) * 128 + (n & 7) * 16
                     + ((c4 >> 2) & 1) + ((c4 >> 3) & 1) * 2;
            Kf[base + 0] = to_tf32(v.x); Kf[base + 4] = to_tf32(v.y);
            Kf[base + 8] = to_tf32(v.z); Kf[base + 12] = to_tf32(v.w);
        }
#pragma unroll
        for (int i = 0; i < 8; i++) {
            int idx = t + (i << 8);
            int kv = idx >> 5, c4 = (idx & 31) << 2;
            float4 v = *(const float4*)(g_qkv + (size_t)(b * Lc + kv) * QKVN + 3072 + kh * Dhc + c4);
            int base = ((kv >> 4) * 16 + (c4 >> 3)) * 128 + (c4 & 7) * 16
                     + (kv & 3) * 4 + ((kv >> 2) & 1) + ((kv >> 3) & 1) * 2;
            Vf[base + 0]  = to_tf32(v.x); Vf[base + 16] = to_tf32(v.y);
            Vf[base + 32] = to_tf32(v.z); Vf[base + 48] = to_tf32(v.w);
        }
    }
    __syncthreads();

    float accO[2][8][4];
    float m_run[4], l_run[4];
#pragma unroll
    for (int i = 0; i < 2; i++)
#pragma unroll
        for (int j = 0; j < 8; j++)
#pragma unroll
            for (int c = 0; c < 4; c++) accO[i][j][c] = 0.f;
#pragma unroll
    for (int r = 0; r < 4; r++) { m_run[r] = -1e30f; l_run[r] = 0.f; }

    for (int kt = 0; kt < 32; kt++) {
        bool more = (kt + 1 < 32);
        // prefetch K(t+1)
        float4 pre[8];
        if (more) {
#pragma unroll
            for (int i = 0; i < 8; i++) {
                int idx = t + (i << 8);
                int n = idx >> 5, c4 = (idx & 31) << 2;
                pre[i] = *(const float4*)(g_qkv + (size_t)(b * Lc + (kt + 1) * 64 + n) * QKVN
                                          + 2048 + kh * Dhc + c4);
            }
        }

        // ---- S = Q @ K^T (warp tile 32x32) ----
        float accS[2][4][4];
#pragma unroll
        for (int i = 0; i < 2; i++)
#pragma unroll
            for (int j = 0; j < 4; j++)
#pragma unroll
                for (int c = 0; c < 4; c++) accS[i][j][c] = 0.f;
#pragma unroll
        for (int kp = 0; kp < 8; kp++) {
            uint4 bb[4];
#pragma unroll
            for (int nj = 0; nj < 4; nj++)
                bb[nj] = *(const uint4*)&Kf[(kp * 8 + wn * 4 + nj) * 128 + l * 4];
#pragma unroll
            for (int hh = 0; hh < 2; hh++) {
                uint4 aa[2];
#pragma unroll
                for (int mi = 0; mi < 2; mi++)
                    aa[mi] = *(const uint4*)&Qf[((kp * 2 + hh) * 8 + wm * 2 + mi) * 128 + l * 4];
#pragma unroll
                for (int mi = 0; mi < 2; mi++)
#pragma unroll
                    for (int nj = 0; nj < 4; nj++)
                        mma8(accS[mi][nj], aa[mi],
                             hh ? bb[nj].z : bb[nj].x,
                             hh ? bb[nj].w : bb[nj].y);
            }
        }

        // ---- softmax part 1: scale, warp-partial max, exp, partial sum ----
        float pm[4], ps[4];
#pragma unroll
        for (int r = 0; r < 4; r++) { pm[r] = -1e30f; ps[r] = 0.f; }
#pragma unroll
        for (int mi = 0; mi < 2; mi++)
#pragma unroll
            for (int nj = 0; nj < 4; nj++)
#pragma unroll
                for (int c = 0; c < 4; c++) {
                    float v = accS[mi][nj][c] * SC;
                    accS[mi][nj][c] = v;
                    int ri = mi * 2 + (c >> 1);
                    pm[ri] = fmaxf(pm[ri], v);
                }
#pragma unroll
        for (int r = 0; r < 4; r++) {
            pm[r] = fmaxf(pm[r], __shfl_xor_sync(0xffffffffu, pm[r], 1));
            pm[r] = fmaxf(pm[r], __shfl_xor_sync(0xffffffffu, pm[r], 2));
        }
#pragma unroll
        for (int mi = 0; mi < 2; mi++)
#pragma unroll
            for (int nj = 0; nj < 4; nj++)
#pragma unroll
                for (int c = 0; c < 4; c++) {
                    int ri = mi * 2 + (c >> 1);
                    float p = __expf(accS[mi][nj][c] - pm[ri]);
                    accS[mi][nj][c] = p;
                    ps[ri] += p;
                }
#pragma unroll
        for (int r = 0; r < 4; r++) {
            ps[r] += __shfl_xor_sync(0xffffffffu, ps[r], 1);
            ps[r] += __shfl_xor_sync(0xffffffffu, ps[r], 2);
        }
        if (lo == 0) {
#pragma unroll
            for (int mi = 0; mi < 2; mi++)
#pragma unroll
                for (int rb = 0; rb < 2; rb++) {
                    int grow = wm * 32 + mi * 16 + lr + 8 * rb;
                    red[wn * 128 + grow] = make_float2(pm[mi * 2 + rb], ps[mi * 2 + rb]);
                }
        }
        __syncthreads();   // red ready; all warps done reading Kf

        // ---- merge stats across wn-halves, correct O, store Pf ----
        float cf[4], corr[4];
#pragma unroll
        for (int mi = 0; mi < 2; mi++)
#pragma unroll
            for (int rb = 0; rb < 2; rb++) {
                int ri = mi * 2 + rb;
                int grow = wm * 32 + mi * 16 + lr + 8 * rb;
                float2 f0 = red[grow], f1 = red[128 + grow];
                float mnew = fmaxf(m_run[ri], fmaxf(f0.x, f1.x));
                float gsum = f0.y * __expf(f0.x - mnew) + f1.y * __expf(f1.x - mnew);
                corr[ri] = __expf(m_run[ri] - mnew);
                l_run[ri] = l_run[ri] * corr[ri] + gsum;
                m_run[ri] = mnew;
                cf[ri] = __expf(pm[ri] - mnew);
            }
#pragma unroll
        for (int mi = 0; mi < 2; mi++)
#pragma unroll
            for (int nj = 0; nj < 8; nj++)
#pragma unroll
                for (int c = 0; c < 4; c++)
                    accO[mi][nj][c] *= corr[mi * 2 + (c >> 1)];
        // Pf store (A-frag layout, m=q row local, k=kv local)
#pragma unroll
        for (int mi = 0; mi < 2; mi++)
#pragma unroll
            for (int nj = 0; nj < 4; nj++)
#pragma unroll
                for (int c = 0; c < 4; c++) {
                    int rb = c >> 1, cb = c & 1;
                    int addr = ((wn * 4 + nj) * 8 + wm * 2 + mi) * 128
                             + lr * 16 + rb + (2 * (lo & 1) + cb) * 4 + (lo >> 1) * 2;
                    Pf[addr] = to_tf32(accS[mi][nj][c] * cf[mi * 2 + rb]);
                }
        // store prefetched K(t+1)
        if (more) {
#pragma unroll
            for (int i = 0; i < 8; i++) {
                int idx = t + (i << 8);
                int n = idx >> 5, c4 = (idx & 31) << 2;
                int base = ((c4 >> 4) * 8 + (n >> 3)) * 128 + (n & 7) * 16
                         + ((c4 >> 2) & 1) + ((c4 >> 3) & 1) * 2;
                Kf[base + 0] = to_tf32(pre[i].x); Kf[base + 4]  = to_tf32(pre[i].y);
                Kf[base + 8] = to_tf32(pre[i].z); Kf[base + 12] = to_tf32(pre[i].w);
            }
            // prefetch V(t+1)
#pragma unroll
            for (int i = 0; i < 8; i++) {
                int idx = t + (i << 8);
                int kv = idx >> 5, c4 = (idx & 31) << 2;
                pre[i] = *(const float4*)(g_qkv + (size_t)(b * Lc + (kt + 1) * 64 + kv) * QKVN
                                          + 3072 + kh * Dhc + c4);
            }
        }
        __syncthreads();   // Pf ready (Kf(t+1) ready for next iter)

        // ---- O += P @ V (warp tile 32x64) ----
#pragma unroll
        for (int kp = 0; kp < 4; kp++) {
            uint4 bb[8];
#pragma unroll
            for (int nj = 0; nj < 8; nj++)
                bb[nj] = *(const uint4*)&Vf[(kp * 16 + wn * 8 + nj) * 128 + l * 4];
#pragma unroll
            for (int hh = 0; hh < 2; hh++) {
                uint4 aa[2];
#pragma unroll
                for (int mi = 0; mi < 2; mi++)
                    aa[mi] = *(const uint4*)&Pf[((kp * 2 + hh) * 8 + wm * 2 + mi) * 128 + l * 4];
#pragma unroll
                for (int mi = 0; mi < 2; mi++)
#pragma unroll
                    for (int nj = 0; nj < 8; nj++)
                        mma8(accO[mi][nj], aa[mi],
                             hh ? bb[nj].z : bb[nj].x,
                             hh ? bb[nj].w : bb[nj].y);
            }
        }
        __syncthreads();   // all reads of Vf / Pf done

        // store prefetched V(t+1)
        if (more) {
#pragma unroll
            for (int i = 0; i < 8; i++) {
                int idx = t + (i << 8);
                int kv = idx >> 5, c4 = (idx & 31) << 2;
                int base = ((kv >> 4) * 16 + (c4 >> 3)) * 128 + (c4 & 7) * 16
                         + (kv & 3) * 4 + ((kv >> 2) & 1) + ((kv >> 3) & 1) * 2;
                Vf[base + 0]  = to_tf32(pre[i].x); Vf[base + 16] = to_tf32(pre[i].y);
                Vf[base + 32] = to_tf32(pre[i].z); Vf[base + 48] = to_tf32(pre[i].w);
            }
        }
    }

    // ---- epilogue: O /= l, write (tf32 for O-projection GEMM) ----
    float inv[4];
#pragma unroll
    for (int r = 0; r < 4; r++) inv[r] = 1.f / l_run[r];
#pragma unroll
    for (int mi = 0; mi < 2; mi++)
#pragma unroll
        for (int nj = 0; nj < 8; nj++) {
            int col = h * Dhc + wn * 64 + nj * 8 + 2 * lo;
#pragma unroll
            for (int rb = 0; rb < 2; rb++) {
                int row = q0 + wm * 32 + mi * 16 + lr + 8 * rb;
                float iv = inv[mi * 2 + rb];
                *(float2*)(go + (size_t)(b * Lc + row) * Dc + col) =
                    make_float2(to_tf32(accO[mi][nj][rb * 2 + 0] * iv),
                                to_tf32(accO[mi][nj][rb * 2 + 1] * iv));
            }
        }
}

// ================================ host ========================================
extern "C" void kernel_launch(void* const* d_in, const int* in_sizes, int n_in,
                              void* d_out, int out_size) {
    const float* hidden = (const float*)d_in[0];
    const float* temb   = (const float*)d_in[1];
    const float* w_ln   = (const float*)d_in[2];
    const float* w_mod  = (const float*)d_in[3];
    const float* b_mod  = (const float*)d_in[4];
    const float* wq     = (const float*)d_in[5];
    const float* wk     = (const float*)d_in[6];
    const float* wv     = (const float*)d_in[7];
    const float* wo     = (const float*)d_in[8];
    const float* qn     = (const float*)d_in[9];
    const float* kn     = (const float*)d_in[10];
    const float* cos1   = (const float*)d_in[11];
    const float* sin1   = (const float*)d_in[12];
    const float* rope3  = (const float*)d_in[13];
    const int*   mpos   = (const int*)d_in[14];
    float* out = (float*)d_out;

    void *pxm, *pqkv, *po, *pwT, *pwoT;
    cudaGetSymbolAddress(&pxm,  g_xm);
    cudaGetSymbolAddress(&pqkv, g_qkv);
    cudaGetSymbolAddress(&po,   g_o);
    cudaGetSymbolAddress(&pwT,  g_wT);
    cudaGetSymbolAddress(&pwoT, g_woT);

    cudaFuncSetAttribute(k_mma<0>, cudaFuncAttributeMaxDynamicSharedMemorySize, MMASMEM);
    cudaFuncSetAttribute(k_mma<1>, cudaFuncAttributeMaxDynamicSharedMemorySize, MMASMEM);
    cudaFuncSetAttribute(k_flash, cudaFuncAttributeMaxDynamicSharedMemorySize, FSMEM);

    k_mod<<<dim3(D3c / 256, Bc), 256>>>(temb, w_mod, b_mod);
    k_rmsmod<<<Bc * Lc, 256>>>(hidden, w_ln);

    k_transpose<<<dim3(Dc / 32, Dc / 32), dim3(32, 8)>>>(wq, (float*)pwT, Dc, Dc);
    k_transpose<<<dim3(1024 / 32, Dc / 32), dim3(32, 8)>>>(wk, (float*)pwT + (size_t)2048 * Dc, Dc, 1024);
    k_transpose<<<dim3(1024 / 32, Dc / 32), dim3(32, 8)>>>(wv, (float*)pwT + (size_t)3072 * Dc, Dc, 1024);
    k_transpose<<<dim3(Dc / 32, Dc / 32), dim3(32, 8)>>>(wo, (float*)pwoT, Dc, Dc);

    k_mma<0><<<dim3(QKVN / 256, (Bc * Lc) / 128), 256, MMASMEM>>>(
        (const float*)pxm, (const float*)pwT, (float*)pqkv, QKVN, Dc, nullptr);

    k_qknorm_rope<<<(Bc * Lc * (Hc + KVHc)) / 8, 256>>>(cos1, sin1, rope3, qn, kn, mpos);

    k_flash<<<dim3(Lc / 128, Hc, Bc), 256, FSMEM>>>((float*)po);

    k_mma<1><<<dim3(Dc / 256, (Bc * Lc) / 128), 256, MMASMEM>>>(
        (const float*)po, (const float*)pwoT, out, Dc, Dc, hidden);
}

// round 8
// speedup vs baseline: 2.2336x; 2.2156x over previous
#include <cuda_runtime.h>
#include <cuda_fp16.h>
#include <cstdint>

#define Bc   2
#define Lc   2048
#define Dc   2048
#define Hc   16
#define KVHc 8
#define Dhc  128
#define QKVN 4096
#define D3c  6144
#define EPSc 1e-5f

// ---------------- scratch (device globals: allocation-guard safe) -------------
__device__ float  g_mod [Bc * D3c];
__device__ __half g_xmh [(size_t)Bc * Lc * Dc];
__device__ __half g_qkvh[(size_t)Bc * Lc * QKVN];  // 0..2047 Q | 2048..3071 K | 3072..4095 V
__device__ __half g_oh  [(size_t)Bc * Lc * Dc];
__device__ __half g_wTh [(size_t)QKVN * Dc];       // [wq^T ; wk^T ; wv^T], K-contig rows
__device__ __half g_woTh[(size_t)Dc * Dc];

// ================= helpers ====================================================
__device__ __forceinline__ uint32_t smem_u32(const void* p) {
    uint32_t a;
    asm("{ .reg .u64 t; cvta.to.shared.u64 t, %1; cvt.u32.u64 %0, t; }" : "=r"(a) : "l"(p));
    return a;
}
__device__ __forceinline__ void ldsm4(uint32_t* r, uint32_t a) {
    asm volatile("ldmatrix.sync.aligned.m8n8.x4.shared.b16 {%0,%1,%2,%3}, [%4];"
                 : "=r"(r[0]), "=r"(r[1]), "=r"(r[2]), "=r"(r[3]) : "r"(a));
}
__device__ __forceinline__ void ldsm4t(uint32_t* r, uint32_t a) {
    asm volatile("ldmatrix.sync.aligned.m8n8.x4.trans.shared.b16 {%0,%1,%2,%3}, [%4];"
                 : "=r"(r[0]), "=r"(r[1]), "=r"(r[2]), "=r"(r[3]) : "r"(a));
}
__device__ __forceinline__ void mma16(float* d, const uint32_t* a, uint32_t b0, uint32_t b1) {
    asm volatile("mma.sync.aligned.m16n8k16.row.col.f32.f16.f16.f32 "
                 "{%0,%1,%2,%3}, {%4,%5,%6,%7}, {%8,%9}, {%0,%1,%2,%3};"
                 : "+f"(d[0]), "+f"(d[1]), "+f"(d[2]), "+f"(d[3])
                 : "r"(a[0]), "r"(a[1]), "r"(a[2]), "r"(a[3]), "r"(b0), "r"(b1));
}
__device__ __forceinline__ void cpa16(uint32_t s, const void* g) {
    asm volatile("cp.async.cg.shared.global [%0], [%1], 16;" :: "r"(s), "l"(g));
}
#define CP_COMMIT() asm volatile("cp.async.commit_group;" ::: "memory")
#define CP_WAIT0()  asm volatile("cp.async.wait_group 0;" ::: "memory")

// ================= kernel 1: mod = silu(temb) @ w_mod + b_mod =================
__global__ void k_mod(const float* __restrict__ temb, const float* __restrict__ w_mod,
                      const float* __restrict__ b_mod) {
    __shared__ float st[Dc];
    int b = blockIdx.y;
    int j = blockIdx.x * 256 + threadIdx.x;
    for (int i = threadIdx.x; i < Dc; i += 256) {
        float x = temb[b * Dc + i];
        st[i] = x / (1.f + __expf(-x));
    }
    __syncthreads();
    float acc = b_mod[j];
#pragma unroll 4
    for (int i = 0; i < Dc; i++) acc = fmaf(st[i], w_mod[(size_t)i * D3c + j], acc);
    g_mod[b * D3c + j] = acc;
}

// ====== kernel 2: xm = half(rmsnorm(x)*w_ln*(1+scale)+shift) ==================
__global__ void k_rmsmod(const float* __restrict__ x, const float* __restrict__ w_ln) {
    int row = blockIdx.x;
    int b   = row >> 11;
    const float* xr = x + (size_t)row * Dc;
    int tid = threadIdx.x;
    float ss = 0.f;
    for (int i = tid; i < Dc; i += 256) { float v = xr[i]; ss = fmaf(v, v, ss); }
#pragma unroll
    for (int o = 16; o; o >>= 1) ss += __shfl_xor_sync(0xffffffffu, ss, o);
    __shared__ float red[8];
    __shared__ float sinv;
    if ((tid & 31) == 0) red[tid >> 5] = ss;
    __syncthreads();
    if (tid == 0) {
        float t = 0.f;
#pragma unroll
        for (int w = 0; w < 8; w++) t += red[w];
        sinv = rsqrtf(t * (1.f / Dc) + EPSc);
    }
    __syncthreads();
    float inv = sinv;
    const float* sh = g_mod + b * D3c;
    const float* sc = sh + Dc;
    __half* xm = g_xmh + (size_t)row * Dc;
    for (int i = tid; i < Dc; i += 256)
        xm[i] = __float2half_rn(fmaf(xr[i] * inv * w_ln[i], 1.f + sc[i], sh[i]));
}

// ====== transpose src[K][N] -> dst[N][K] (half) ===============================
__global__ void k_transpose(const float* __restrict__ src, __half* __restrict__ dst,
                            int K, int N) {
    __shared__ float t[32][33];
    int kb = blockIdx.y * 32, nb = blockIdx.x * 32;
    int x = threadIdx.x, y = threadIdx.y;
#pragma unroll
    for (int i = 0; i < 32; i += 8)
        t[y + i][x] = src[(size_t)(kb + y + i) * N + nb + x];
    __syncthreads();
#pragma unroll
    for (int i = 0; i < 32; i += 8)
        dst[(size_t)(nb + y + i) * K + kb + x] = __float2half_rn(t[x][y + i]);
}

// ====== fp16 mma.sync GEMM: C[M,N] = A[M,K] @ Bt[N,K]^T =======================
// BM=128 BN=256 BK=32. 8 warps 2x4, warp tile 64x64. ldmatrix + cp.async.
// smem halves: A buf 128*40=5120, B buf 256*40=10240; x2 buffers.
#define MMASMEM ((5120 + 10240) * 2 * 2)   // 61440 bytes

template<int EPI>
__global__ void __launch_bounds__(256, 1)
k_mma(const __half* __restrict__ Ag, const __half* __restrict__ Bg,
      void* __restrict__ Cv, int N, int K, const float* __restrict__ hid) {
    extern __shared__ __half sh[];
    uint32_t base = smem_u32(sh);
    int t = threadIdx.x, l = t & 31, wid = t >> 5;
    int wm = wid >> 2, wn = wid & 3;
    int m0 = blockIdx.y * 128, n0 = blockIdx.x * 256;

    auto loadT = [&](int kt, int buf) {
        uint32_t ab = base + buf * 30720;            // bytes
#pragma unroll
        for (int i = 0; i < 2; i++) {                // A: 512 cells
            int p = t + (i << 8); int r = p >> 2, c = p & 3;
            cpa16(ab + (r * 40 + c * 8) * 2,
                  Ag + (size_t)(m0 + r) * K + kt * 32 + c * 8);
        }
#pragma unroll
        for (int i = 0; i < 4; i++) {                // B: 1024 cells
            int p = t + (i << 8); int r = p >> 2, c = p & 3;
            cpa16(ab + 10240 + (r * 40 + c * 8) * 2,
                  Bg + (size_t)(n0 + r) * K + kt * 32 + c * 8);
        }
    };

    float acc[4][8][4];
#pragma unroll
    for (int i = 0; i < 4; i++)
#pragma unroll
        for (int j = 0; j < 8; j++)
#pragma unroll
            for (int c = 0; c < 4; c++) acc[i][j][c] = 0.f;

    loadT(0, 0);
    CP_COMMIT();
    CP_WAIT0();
    __syncthreads();

    int nk = K >> 5;
    int buf = 0;
    for (int kt = 0; kt < nk; kt++) {
        bool more = (kt + 1 < nk);
        if (more) { loadT(kt + 1, buf ^ 1); CP_COMMIT(); }

        uint32_t Ab = base + buf * 30720;
        uint32_t Bb = Ab + 10240;
        uint32_t bb[8][4];
#pragma unroll
        for (int j = 0; j < 8; j++)
            ldsm4(bb[j], Bb + ((wn * 64 + j * 8 + (l & 7)) * 40 + (l >> 3) * 8) * 2);
#pragma unroll
        for (int kc = 0; kc < 2; kc++) {
            uint32_t aa[4][4];
#pragma unroll
            for (int i = 0; i < 4; i++)
                ldsm4(aa[i], Ab + ((wm * 64 + i * 16 + ((l >> 3) & 1) * 8 + (l & 7)) * 40
                                   + (2 * kc + (l >> 4)) * 8) * 2);
#pragma unroll
            for (int i = 0; i < 4; i++)
#pragma unroll
                for (int j = 0; j < 8; j++)
                    mma16(acc[i][j], aa[i], bb[j][2 * kc], bb[j][2 * kc + 1]);
        }
        if (more) CP_WAIT0();
        __syncthreads();
        buf ^= 1;
    }

    // epilogue: c0=(r,2c) c1=(r,2c+1) c2=(r+8,2c) c3=(r+8,2c+1); r=l>>2, c=l&3
#pragma unroll
    for (int i = 0; i < 4; i++) {
        int gm = m0 + wm * 64 + i * 16 + (l >> 2);
#pragma unroll
        for (int j = 0; j < 8; j++) {
            int gn = n0 + wn * 64 + j * 8 + 2 * (l & 3);
            if (EPI == 0) {
                __half* C = (__half*)Cv;
                *(__half2*)(C + (size_t)gm * N + gn) =
                    __floats2half2_rn(acc[i][j][0], acc[i][j][1]);
                *(__half2*)(C + (size_t)(gm + 8) * N + gn) =
                    __floats2half2_rn(acc[i][j][2], acc[i][j][3]);
            } else {
                float* C = (float*)Cv;
                size_t o0 = (size_t)gm * N + gn;
                size_t o1 = (size_t)(gm + 8) * N + gn;
                int b0 = gm >> 11, b1 = (gm + 8) >> 11;
                float2 h0 = *(const float2*)(hid + o0);
                float2 h1 = *(const float2*)(hid + o1);
                float2 g0 = *(const float2*)(g_mod + b0 * D3c + 2 * Dc + gn);
                float2 g1 = *(const float2*)(g_mod + b1 * D3c + 2 * Dc + gn);
                *(float2*)(C + o0) = make_float2(fmaf(g0.x, acc[i][j][0], h0.x),
                                                 fmaf(g0.y, acc[i][j][1], h0.y));
                *(float2*)(C + o1) = make_float2(fmaf(g1.x, acc[i][j][2], h1.x),
                                                 fmaf(g1.y, acc[i][j][3], h1.y));
            }
        }
    }
}

// ====== per-head RMSNorm + mixed RoPE (half qkv, stride 4096) =================
__global__ void __launch_bounds__(256)
k_qknorm_rope(const float* __restrict__ cos1d, const float* __restrict__ sin1d,
              const float* __restrict__ rope3d,
              const float* __restrict__ qn, const float* __restrict__ kn,
              const int* __restrict__ mp) {
    int warp = threadIdx.x >> 5, lane = threadIdx.x & 31;
    int v  = blockIdx.x * 8 + warp;
    int bl = v / 24, r = v % 24;
    int b = bl >> 11, l = bl & 2047;

    __half* ptr; const float* w;
    if (r < Hc) { ptr = g_qkvh + (size_t)bl * QKVN + r * Dhc;               w = qn; }
    else        { ptr = g_qkvh + (size_t)bl * QKVN + 2048 + (r - Hc) * Dhc; w = kn; }

    float val[4];
    float ss = 0.f;
#pragma unroll
    for (int i = 0; i < 4; i++) {
        val[i] = __half2float(ptr[lane + 32 * i]);
        ss = fmaf(val[i], val[i], ss);
    }
#pragma unroll
    for (int o = 16; o; o >>= 1) ss += __shfl_xor_sync(0xffffffffu, ss, o);
    float inv = rsqrtf(ss * (1.f / Dhc) + EPSc);
#pragma unroll
    for (int i = 0; i < 4; i++) val[i] *= inv * w[lane + 32 * i];

    bool is64 = (mp[1] == 0);
    bool in_full = false, in_img = false; int rel = 0;
#pragma unroll
    for (int m = 0; m < 2; m++) {
        int off, ln;
        if (is64) { off = mp[(b * 4 + m * 2) * 2]; ln = mp[(b * 4 + m * 2 + 1) * 2]; }
        else      { off = mp[b * 4 + m * 2];       ln = mp[b * 4 + m * 2 + 1]; }
        int seg_end = off + max(ln, 1);
        if (l >= off && l < seg_end) in_full = true;
        if (l >= off + 1 && l < off + ln) { in_img = true; rel += l - (off + 1); }
    }
    bool text = !in_full;
    bool img  = in_img && (rel < 1024);
    rel = min(max(rel, 0), 1023);

    float out[4];
    if (text) {
#pragma unroll
        for (int i = 0; i < 4; i++) {
            int d = lane + 32 * i;
            float c = cos1d[l * Dhc + d], s = sin1d[l * Dhc + d];
            float rot = (i < 2) ? -val[i ^ 2] : val[i ^ 2];
            out[i] = fmaf(val[i], c, rot * s);
        }
    } else {
#pragma unroll
        for (int i = 0; i < 4; i++) {
            int d = lane + 32 * i; int p = d >> 1; int jj = d & 1;
            float partner = __shfl_xor_sync(0xffffffffu, val[i], 1);
            float q0 = jj ? partner : val[i];
            float q1 = jj ? val[i] : partner;
            const float* R = rope3d + ((size_t)rel * 64 + p) * 4;
            float oimg = fmaf(q0, R[jj], q1 * R[2 + jj]);
            out[i] = img ? oimg : val[i];
        }
    }
#pragma unroll
    for (int i = 0; i < 4; i++) ptr[lane + 32 * i] = __float2half_rn(out[i]);
}

// ====== flash attention, fp16 mma.sync + ldmatrix + cp.async ==================
// CTA: 128 q-rows x 1 head. 8 warps (4m x 2n). kv-tile 64, K/V double-buffered.
// half offsets: Qh 0 (128x136), Kh 17408+buf*8704 (64x136), Vh 34816+buf*8704,
//               Ph 52224 (128x72), red floats at half 61440.
#define FSMEM (61440 * 2 + 2048)   // 124928 bytes

__global__ void __launch_bounds__(256, 1)
k_flash(__half* __restrict__ go) {
    extern __shared__ __half fh[];
    uint32_t base = smem_u32(fh);
    float2* red = (float2*)(fh + 61440);   // [wn][128] (rowmax, rowsum)

    int t = threadIdx.x, l = t & 31, wid = t >> 5;
    int lo = l & 3, lr = l >> 2;
    int wm = wid >> 1, wn = wid & 1;
    int q0 = blockIdx.x << 7;
    int h  = blockIdx.y, b = blockIdx.z;
    int kh = h >> 1;
    const float SC = 0.08838834764831845f;   // 1/sqrt(128)

    const __half* qkv = g_qkvh;

    // Q: 128x128 halves -> 2048 cells (stride 136)
#pragma unroll
    for (int i = 0; i < 8; i++) {
        int p = t + (i << 8); int r = p >> 4, c = p & 15;
        cpa16(base + (r * 136 + c * 8) * 2,
              qkv + (size_t)(b * Lc + q0 + r) * QKVN + h * Dhc + c * 8);
    }
    auto loadKV = [&](int kt, int buf) {
#pragma unroll
        for (int i = 0; i < 4; i++) {   // K: 1024 cells
            int p = t + (i << 8); int r = p >> 4, c = p & 15;
            cpa16(base + (17408 + buf * 8704 + r * 136 + c * 8) * 2,
                  qkv + (size_t)(b * Lc + kt * 64 + r) * QKVN + 2048 + kh * Dhc + c * 8);
        }
#pragma unroll
        for (int i = 0; i < 4; i++) {   // V: 1024 cells
            int p = t + (i << 8); int r = p >> 4, c = p & 15;
            cpa16(base + (34816 + buf * 8704 + r * 136 + c * 8) * 2,
                  qkv + (size_t)(b * Lc + kt * 64 + r) * QKVN + 3072 + kh * Dhc + c * 8);
        }
    };
    loadKV(0, 0);
    CP_COMMIT();
    CP_WAIT0();
    __syncthreads();

    float accO[2][8][4];
    float m_run[4], l_run[4];
#pragma unroll
    for (int i = 0; i < 2; i++)
#pragma unroll
        for (int j = 0; j < 8; j++)
#pragma unroll
            for (int c = 0; c < 4; c++) accO[i][j][c] = 0.f;
#pragma unroll
    for (int r = 0; r < 4; r++) { m_run[r] = -1e30f; l_run[r] = 0.f; }

    for (int kt = 0; kt < 32; kt++) {
        int cur = kt & 1;
        bool more = (kt + 1 < 32);
        if (more) { loadKV(kt + 1, cur ^ 1); CP_COMMIT(); }

        // ---- S = Q @ K^T (warp tile 32 q x 32 kv, k=128) ----
        float accS[2][4][4];
#pragma unroll
        for (int i = 0; i < 2; i++)
#pragma unroll
            for (int j = 0; j < 4; j++)
#pragma unroll
                for (int c = 0; c < 4; c++) accS[i][j][c] = 0.f;

        uint32_t Kb = base + (17408 + cur * 8704) * 2;
#pragma unroll
        for (int kc2 = 0; kc2 < 4; kc2++) {     // k32 chunks
            uint32_t bb[4][4];
#pragma unroll
            for (int nj = 0; nj < 4; nj++)
                ldsm4(bb[nj], Kb + ((wn * 32 + nj * 8 + (l & 7)) * 136
                                    + (kc2 * 4 + (l >> 3)) * 8) * 2);
#pragma unroll
            for (int kc = 0; kc < 2; kc++) {
                uint32_t aa[2][4];
#pragma unroll
                for (int mi = 0; mi < 2; mi++)
                    ldsm4(aa[mi], base + ((wm * 32 + mi * 16 + ((l >> 3) & 1) * 8 + (l & 7)) * 136
                                          + (kc2 * 4 + 2 * kc + (l >> 4)) * 8) * 2);
#pragma unroll
                for (int mi = 0; mi < 2; mi++)
#pragma unroll
                    for (int nj = 0; nj < 4; nj++)
                        mma16(accS[mi][nj], aa[mi], bb[nj][2 * kc], bb[nj][2 * kc + 1]);
            }
        }

        // ---- softmax: scale, warp-partial max/exp/sum ----
        float pm[4], ps[4];
#pragma unroll
        for (int r = 0; r < 4; r++) { pm[r] = -1e30f; ps[r] = 0.f; }
#pragma unroll
        for (int mi = 0; mi < 2; mi++)
#pragma unroll
            for (int nj = 0; nj < 4; nj++)
#pragma unroll
                for (int c = 0; c < 4; c++) {
                    float v = accS[mi][nj][c] * SC;
                    accS[mi][nj][c] = v;
                    int ri = mi * 2 + (c >> 1);
                    pm[ri] = fmaxf(pm[ri], v);
                }
#pragma unroll
        for (int r = 0; r < 4; r++) {
            pm[r] = fmaxf(pm[r], __shfl_xor_sync(0xffffffffu, pm[r], 1));
            pm[r] = fmaxf(pm[r], __shfl_xor_sync(0xffffffffu, pm[r], 2));
        }
#pragma unroll
        for (int mi = 0; mi < 2; mi++)
#pragma unroll
            for (int nj = 0; nj < 4; nj++)
#pragma unroll
                for (int c = 0; c < 4; c++) {
                    int ri = mi * 2 + (c >> 1);
                    float p = __expf(accS[mi][nj][c] - pm[ri]);
                    accS[mi][nj][c] = p;
                    ps[ri] += p;
                }
#pragma unroll
        for (int r = 0; r < 4; r++) {
            ps[r] += __shfl_xor_sync(0xffffffffu, ps[r], 1);
            ps[r] += __shfl_xor_sync(0xffffffffu, ps[r], 2);
        }
        if (lo == 0) {
#pragma unroll
            for (int mi = 0; mi < 2; mi++)
#pragma unroll
                for (int rb = 0; rb < 2; rb++) {
                    int grow = wm * 32 + mi * 16 + lr + 8 * rb;
                    red[wn * 128 + grow] = make_float2(pm[mi * 2 + rb], ps[mi * 2 + rb]);
                }
        }
        __syncthreads();   // red visible

        // ---- merge stats, correct O, write Ph ----
        float cf[4], corr[4];
#pragma unroll
        for (int mi = 0; mi < 2; mi++)
#pragma unroll
            for (int rb = 0; rb < 2; rb++) {
                int ri = mi * 2 + rb;
                int grow = wm * 32 + mi * 16 + lr + 8 * rb;
                float2 f0 = red[grow], f1 = red[128 + grow];
                float mnew = fmaxf(m_run[ri], fmaxf(f0.x, f1.x));
                float gsum = f0.y * __expf(f0.x - mnew) + f1.y * __expf(f1.x - mnew);
                corr[ri] = __expf(m_run[ri] - mnew);
                l_run[ri] = l_run[ri] * corr[ri] + gsum;
                m_run[ri] = mnew;
                cf[ri] = __expf(pm[ri] - mnew);
            }
#pragma unroll
        for (int mi = 0; mi < 2; mi++)
#pragma unroll
            for (int nj = 0; nj < 8; nj++)
#pragma unroll
                for (int c = 0; c < 4; c++)
                    accO[mi][nj][c] *= corr[mi * 2 + (c >> 1)];
        // Ph[row][col] half, stride 72: row=q local, col=kv local
#pragma unroll
        for (int mi = 0; mi < 2; mi++)
#pragma unroll
            for (int nj = 0; nj < 4; nj++)
#pragma unroll
                for (int rb = 0; rb < 2; rb++) {
                    int row = wm * 32 + mi * 16 + lr + 8 * rb;
                    int col = wn * 32 + nj * 8 + 2 * lo;
                    float c = cf[mi * 2 + rb];
                    *(__half2*)(fh + 52224 + row * 72 + col) =
                        __floats2half2_rn(accS[mi][nj][rb * 2 + 0] * c,
                                          accS[mi][nj][rb * 2 + 1] * c);
                }
        __syncthreads();   // Ph visible

        // ---- O += P @ V (warp tile 32 q x 64 dh, k=64) ----
        uint32_t Vb = base + (34816 + cur * 8704) * 2;
        uint32_t Pb = base + 52224 * 2;
#pragma unroll
        for (int kc2 = 0; kc2 < 2; kc2++) {     // kv32 chunks
            uint32_t bb[8][4];
#pragma unroll
            for (int nj = 0; nj < 8; nj++)
                ldsm4t(bb[nj], Vb + ((kc2 * 32 + (l >> 3) * 8 + (l & 7)) * 136
                                     + wn * 64 + nj * 8) * 2);
#pragma unroll
            for (int kc = 0; kc < 2; kc++) {
                uint32_t aa[2][4];
#pragma unroll
                for (int mi = 0; mi < 2; mi++)
                    ldsm4(aa[mi], Pb + ((wm * 32 + mi * 16 + ((l >> 3) & 1) * 8 + (l & 7)) * 72
                                        + ((kc2 * 2 + kc) * 2 + (l >> 4)) * 8) * 2);
#pragma unroll
                for (int mi = 0; mi < 2; mi++)
#pragma unroll
                    for (int nj = 0; nj < 8; nj++)
                        mma16(accO[mi][nj], aa[mi], bb[nj][2 * kc], bb[nj][2 * kc + 1]);
            }
        }
        if (more) CP_WAIT0();
        __syncthreads();   // Ph/red reuse safe; Kh/Vh next buffer visible
    }

    // ---- epilogue: O /= l, write half ----
    float inv[4];
#pragma unroll
    for (int r = 0; r < 4; r++) inv[r] = 1.f / l_run[r];
#pragma unroll
    for (int mi = 0; mi < 2; mi++)
#pragma unroll
        for (int nj = 0; nj < 8; nj++) {
            int col = h * Dhc + wn * 64 + nj * 8 + 2 * lo;
#pragma unroll
            for (int rb = 0; rb < 2; rb++) {
                int row = q0 + wm * 32 + mi * 16 + lr + 8 * rb;
                float iv = inv[mi * 2 + rb];
                *(__half2*)(go + (size_t)(b * Lc + row) * Dc + col) =
                    __floats2half2_rn(accO[mi][nj][rb * 2 + 0] * iv,
                                      accO[mi][nj][rb * 2 + 1] * iv);
            }
        }
}

// ================================ host ========================================
extern "C" void kernel_launch(void* const* d_in, const int* in_sizes, int n_in,
                              void* d_out, int out_size) {
    const float* hidden = (const float*)d_in[0];
    const float* temb   = (const float*)d_in[1];
    const float* w_ln   = (const float*)d_in[2];
    const float* w_mod  = (const float*)d_in[3];
    const float* b_mod  = (const float*)d_in[4];
    const float* wq     = (const float*)d_in[5];
    const float* wk     = (const float*)d_in[6];
    const float* wv     = (const float*)d_in[7];
    const float* wo     = (const float*)d_in[8];
    const float* qn     = (const float*)d_in[9];
    const float* kn     = (const float*)d_in[10];
    const float* cos1   = (const float*)d_in[11];
    const float* sin1   = (const float*)d_in[12];
    const float* rope3  = (const float*)d_in[13];
    const int*   mpos   = (const int*)d_in[14];
    float* out = (float*)d_out;

    void *pxm, *pqkv, *po, *pwT, *pwoT;
    cudaGetSymbolAddress(&pxm,  g_xmh);
    cudaGetSymbolAddress(&pqkv, g_qkvh);
    cudaGetSymbolAddress(&po,   g_oh);
    cudaGetSymbolAddress(&pwT,  g_wTh);
    cudaGetSymbolAddress(&pwoT, g_woTh);

    cudaFuncSetAttribute(k_mma<0>, cudaFuncAttributeMaxDynamicSharedMemorySize, MMASMEM);
    cudaFuncSetAttribute(k_mma<1>, cudaFuncAttributeMaxDynamicSharedMemorySize, MMASMEM);
    cudaFuncSetAttribute(k_flash, cudaFuncAttributeMaxDynamicSharedMemorySize, FSMEM);

    k_mod<<<dim3(D3c / 256, Bc), 256>>>(temb, w_mod, b_mod);
    k_rmsmod<<<Bc * Lc, 256>>>(hidden, w_ln);

    k_transpose<<<dim3(Dc / 32, Dc / 32), dim3(32, 8)>>>(wq, (__half*)pwT, Dc, Dc);
    k_transpose<<<dim3(1024 / 32, Dc / 32), dim3(32, 8)>>>(wk, (__half*)pwT + (size_t)2048 * Dc, Dc, 1024);
    k_transpose<<<dim3(1024 / 32, Dc / 32), dim3(32, 8)>>>(wv, (__half*)pwT + (size_t)3072 * Dc, Dc, 1024);
    k_transpose<<<dim3(Dc / 32, Dc / 32), dim3(32, 8)>>>(wo, (__half*)pwoT, Dc, Dc);

    // fused QKV GEMM: [4096 x 4096] = xm @ [wq|wk|wv]^T  (half out)
    k_mma<0><<<dim3(QKVN / 256, (Bc * Lc) / 128), 256, MMASMEM>>>(
        (const __half*)pxm, (const __half*)pwT, pqkv, QKVN, Dc, nullptr);

    k_qknorm_rope<<<(Bc * Lc * (Hc + KVHc)) / 8, 256>>>(cos1, sin1, rope3, qn, kn, mpos);

    k_flash<<<dim3(Lc / 128, Hc, Bc), 256, FSMEM>>>((__half*)po);

    // output projection + residual/gate epilogue (float out)
    k_mma<1><<<dim3(Dc / 256, (Bc * Lc) / 128), 256, MMASMEM>>>(
        (const __half*)po, (const __half*)pwoT, out, Dc, Dc, hidden);
}

// round 9
// speedup vs baseline: 2.6663x; 1.1937x over previous
#include <cuda_runtime.h>
#include <cuda_fp16.h>
#include <cstdint>

#define Bc   2
#define Lc   2048
#define Dc   2048
#define Hc   16
#define KVHc 8
#define Dhc  128
#define QKVN 4096
#define D3c  6144
#define EPSc 1e-5f

// ---------------- scratch (device globals: allocation-guard safe) -------------
__device__ float  g_mod [Bc * D3c];
__device__ __half g_xmh [(size_t)Bc * Lc * Dc];
__device__ __half g_qkvh[(size_t)Bc * Lc * QKVN];  // 0..2047 Q | 2048..3071 K | 3072..4095 V
__device__ __half g_oh  [(size_t)Bc * Lc * Dc];
__device__ __half g_wTh [(size_t)QKVN * Dc];       // [wq^T ; wk^T ; wv^T], K-contig rows
__device__ __half g_woTh[(size_t)Dc * Dc];

// ================= helpers ====================================================
__device__ __forceinline__ uint32_t smem_u32(const void* p) {
    uint32_t a;
    asm("{ .reg .u64 t; cvta.to.shared.u64 t, %1; cvt.u32.u64 %0, t; }" : "=r"(a) : "l"(p));
    return a;
}
__device__ __forceinline__ void ldsm4(uint32_t* r, uint32_t a) {
    asm volatile("ldmatrix.sync.aligned.m8n8.x4.shared.b16 {%0,%1,%2,%3}, [%4];"
                 : "=r"(r[0]), "=r"(r[1]), "=r"(r[2]), "=r"(r[3]) : "r"(a));
}
__device__ __forceinline__ void ldsm4t(uint32_t* r, uint32_t a) {
    asm volatile("ldmatrix.sync.aligned.m8n8.x4.trans.shared.b16 {%0,%1,%2,%3}, [%4];"
                 : "=r"(r[0]), "=r"(r[1]), "=r"(r[2]), "=r"(r[3]) : "r"(a));
}
__device__ __forceinline__ void mma16(float* d, const uint32_t* a, uint32_t b0, uint32_t b1) {
    asm volatile("mma.sync.aligned.m16n8k16.row.col.f32.f16.f16.f32 "
                 "{%0,%1,%2,%3}, {%4,%5,%6,%7}, {%8,%9}, {%0,%1,%2,%3};"
                 : "+f"(d[0]), "+f"(d[1]), "+f"(d[2]), "+f"(d[3])
                 : "r"(a[0]), "r"(a[1]), "r"(a[2]), "r"(a[3]), "r"(b0), "r"(b1));
}
__device__ __forceinline__ void cpa16(uint32_t s, const void* g) {
    asm volatile("cp.async.cg.shared.global [%0], [%1], 16;" :: "r"(s), "l"(g));
}
#define CP_COMMIT() asm volatile("cp.async.commit_group;" ::: "memory")
#define CP_WAIT0()  asm volatile("cp.async.wait_group 0;" ::: "memory")
#define CP_WAIT1()  asm volatile("cp.async.wait_group 1;" ::: "memory")

// ================= kernel 1: mod = silu(temb) @ w_mod + b_mod =================
// 192 blocks, 4 threads per output column, shared partial reduce.
__global__ void k_mod(const float* __restrict__ temb, const float* __restrict__ w_mod,
                      const float* __restrict__ b_mod) {
    __shared__ float st[Dc];
    __shared__ float ps[4][64];
    int b = blockIdx.y;
    int tx = threadIdx.x & 63, ty = threadIdx.x >> 6;
    int j = blockIdx.x * 64 + tx;
    for (int i = threadIdx.x; i < Dc; i += 256) {
        float x = temb[b * Dc + i];
        st[i] = x / (1.f + __expf(-x));
    }
    __syncthreads();
    float acc = 0.f;
    int k0 = ty * 512;
#pragma unroll 4
    for (int i = 0; i < 512; i++)
        acc = fmaf(st[k0 + i], w_mod[(size_t)(k0 + i) * D3c + j], acc);
    ps[ty][tx] = acc;
    __syncthreads();
    if (ty == 0)
        g_mod[b * D3c + j] = ps[0][tx] + ps[1][tx] + ps[2][tx] + ps[3][tx] + b_mod[j];
}

// ====== kernel 2: xm = half(rmsnorm(x)*w_ln*(1+scale)+shift) ==================
__global__ void k_rmsmod(const float* __restrict__ x, const float* __restrict__ w_ln) {
    int row = blockIdx.x;
    int b   = row >> 11;
    const float* xr = x + (size_t)row * Dc;
    int tid = threadIdx.x;
    float ss = 0.f;
    for (int i = tid; i < Dc; i += 256) { float v = xr[i]; ss = fmaf(v, v, ss); }
#pragma unroll
    for (int o = 16; o; o >>= 1) ss += __shfl_xor_sync(0xffffffffu, ss, o);
    __shared__ float red[8];
    __shared__ float sinv;
    if ((tid & 31) == 0) red[tid >> 5] = ss;
    __syncthreads();
    if (tid == 0) {
        float t = 0.f;
#pragma unroll
        for (int w = 0; w < 8; w++) t += red[w];
        sinv = rsqrtf(t * (1.f / Dc) + EPSc);
    }
    __syncthreads();
    float inv = sinv;
    const float* sh = g_mod + b * D3c;
    const float* sc = sh + Dc;
    __half* xm = g_xmh + (size_t)row * Dc;
    for (int i = tid; i < Dc; i += 256)
        xm[i] = __float2half_rn(fmaf(xr[i] * inv * w_ln[i], 1.f + sc[i], sh[i]));
}

// ====== transpose src[K][N] -> dst[N][K] (half) ===============================
__global__ void k_transpose(const float* __restrict__ src, __half* __restrict__ dst,
                            int K, int N) {
    __shared__ float t[32][33];
    int kb = blockIdx.y * 32, nb = blockIdx.x * 32;
    int x = threadIdx.x, y = threadIdx.y;
#pragma unroll
    for (int i = 0; i < 32; i += 8)
        t[y + i][x] = src[(size_t)(kb + y + i) * N + nb + x];
    __syncthreads();
#pragma unroll
    for (int i = 0; i < 32; i += 8)
        dst[(size_t)(nb + y + i) * K + kb + x] = __float2half_rn(t[x][y + i]);
}

// ====== fp16 mma.sync GEMM: C[M,N] = A[M,K] @ Bt[N,K]^T =======================
// BM=128 BN=256 BK=32. 16 warps (2m x 8n), warp tile 64x32. 3-stage cp.async.
// stage bytes: A 128*40*2=10240, B 256*40*2=20480 -> 30720; x3 stages.
#define MMASMEM (30720 * 3)   // 92160 bytes

template<int EPI>
__global__ void __launch_bounds__(512, 1)
k_mma(const __half* __restrict__ Ag, const __half* __restrict__ Bg,
      void* __restrict__ Cv, int N, int K, const float* __restrict__ hid) {
    extern __shared__ __half sh[];
    uint32_t base = smem_u32(sh);
    int t = threadIdx.x, l = t & 31, wid = t >> 5;
    int wm = wid >> 3, wn = wid & 7;
    int m0 = blockIdx.y * 128, n0 = blockIdx.x * 256;

    auto loadT = [&](int kt, int buf) {
        uint32_t ab = base + buf * 30720;
        {   // A: 512 cells, 1 per thread
            int r = t >> 2, c = t & 3;
            cpa16(ab + (r * 40 + c * 8) * 2,
                  Ag + (size_t)(m0 + r) * K + kt * 32 + c * 8);
        }
#pragma unroll
        for (int i = 0; i < 2; i++) {   // B: 1024 cells
            int p = t + (i << 9); int r = p >> 2, c = p & 3;
            cpa16(ab + 10240 + (r * 40 + c * 8) * 2,
                  Bg + (size_t)(n0 + r) * K + kt * 32 + c * 8);
        }
    };

    float acc[4][4][4];
#pragma unroll
    for (int i = 0; i < 4; i++)
#pragma unroll
        for (int j = 0; j < 4; j++)
#pragma unroll
            for (int c = 0; c < 4; c++) acc[i][j][c] = 0.f;

    int nk = K >> 5;
    loadT(0, 0); CP_COMMIT();
    loadT(1, 1); CP_COMMIT();

    int cur = 0;
    for (int kt = 0; kt < nk; kt++) {
        if (kt + 1 < nk) CP_WAIT1(); else CP_WAIT0();
        __syncthreads();
        if (kt + 2 < nk) {
            int nb = cur + 2; if (nb >= 3) nb -= 3;
            loadT(kt + 2, nb);
            CP_COMMIT();
        }

        uint32_t Ab = base + cur * 30720;
        uint32_t Bb = Ab + 10240;
        uint32_t bb[4][4];
#pragma unroll
        for (int j = 0; j < 4; j++)
            ldsm4(bb[j], Bb + ((wn * 32 + j * 8 + (l & 7)) * 40 + (l >> 3) * 8) * 2);
#pragma unroll
        for (int kc = 0; kc < 2; kc++) {
            uint32_t aa[4][4];
#pragma unroll
            for (int i = 0; i < 4; i++)
                ldsm4(aa[i], Ab + ((wm * 64 + i * 16 + ((l >> 3) & 1) * 8 + (l & 7)) * 40
                                   + (2 * kc + (l >> 4)) * 8) * 2);
#pragma unroll
            for (int i = 0; i < 4; i++)
#pragma unroll
                for (int j = 0; j < 4; j++)
                    mma16(acc[i][j], aa[i], bb[j][2 * kc], bb[j][2 * kc + 1]);
        }
        __syncthreads();   // all reads of buffer `cur` done before it is refilled
        cur++; if (cur == 3) cur = 0;
    }

    // epilogue: c0=(r,2c) c1=(r,2c+1) c2=(r+8,..) ; r=l>>2, c=l&3
#pragma unroll
    for (int i = 0; i < 4; i++) {
        int gm = m0 + wm * 64 + i * 16 + (l >> 2);
#pragma unroll
        for (int j = 0; j < 4; j++) {
            int gn = n0 + wn * 32 + j * 8 + 2 * (l & 3);
            if (EPI == 0) {
                __half* C = (__half*)Cv;
                *(__half2*)(C + (size_t)gm * N + gn) =
                    __floats2half2_rn(acc[i][j][0], acc[i][j][1]);
                *(__half2*)(C + (size_t)(gm + 8) * N + gn) =
                    __floats2half2_rn(acc[i][j][2], acc[i][j][3]);
            } else {
                float* C = (float*)Cv;
                size_t o0 = (size_t)gm * N + gn;
                size_t o1 = (size_t)(gm + 8) * N + gn;
                int b0 = gm >> 11, b1 = (gm + 8) >> 11;
                float2 h0 = *(const float2*)(hid + o0);
                float2 h1 = *(const float2*)(hid + o1);
                float2 g0 = *(const float2*)(g_mod + b0 * D3c + 2 * Dc + gn);
                float2 g1 = *(const float2*)(g_mod + b1 * D3c + 2 * Dc + gn);
                *(float2*)(C + o0) = make_float2(fmaf(g0.x, acc[i][j][0], h0.x),
                                                 fmaf(g0.y, acc[i][j][1], h0.y));
                *(float2*)(C + o1) = make_float2(fmaf(g1.x, acc[i][j][2], h1.x),
                                                 fmaf(g1.y, acc[i][j][3], h1.y));
            }
        }
    }
}

// ====== per-head RMSNorm + mixed RoPE (half qkv, stride 4096) =================
__global__ void __launch_bounds__(256)
k_qknorm_rope(const float* __restrict__ cos1d, const float* __restrict__ sin1d,
              const float* __restrict__ rope3d,
              const float* __restrict__ qn, const float* __restrict__ kn,
              const int* __restrict__ mp) {
    int warp = threadIdx.x >> 5, lane = threadIdx.x & 31;
    int v  = blockIdx.x * 8 + warp;
    int bl = v / 24, r = v % 24;
    int b = bl >> 11, l = bl & 2047;

    __half* ptr; const float* w;
    if (r < Hc) { ptr = g_qkvh + (size_t)bl * QKVN + r * Dhc;               w = qn; }
    else        { ptr = g_qkvh + (size_t)bl * QKVN + 2048 + (r - Hc) * Dhc; w = kn; }

    float val[4];
    float ss = 0.f;
#pragma unroll
    for (int i = 0; i < 4; i++) {
        val[i] = __half2float(ptr[lane + 32 * i]);
        ss = fmaf(val[i], val[i], ss);
    }
#pragma unroll
    for (int o = 16; o; o >>= 1) ss += __shfl_xor_sync(0xffffffffu, ss, o);
    float inv = rsqrtf(ss * (1.f / Dhc) + EPSc);
#pragma unroll
    for (int i = 0; i < 4; i++) val[i] *= inv * w[lane + 32 * i];

    bool is64 = (mp[1] == 0);
    bool in_full = false, in_img = false; int rel = 0;
#pragma unroll
    for (int m = 0; m < 2; m++) {
        int off, ln;
        if (is64) { off = mp[(b * 4 + m * 2) * 2]; ln = mp[(b * 4 + m * 2 + 1) * 2]; }
        else      { off = mp[b * 4 + m * 2];       ln = mp[b * 4 + m * 2 + 1]; }
        int seg_end = off + max(ln, 1);
        if (l >= off && l < seg_end) in_full = true;
        if (l >= off + 1 && l < off + ln) { in_img = true; rel += l - (off + 1); }
    }
    bool text = !in_full;
    bool img  = in_img && (rel < 1024);
    rel = min(max(rel, 0), 1023);

    float out[4];
    if (text) {
#pragma unroll
        for (int i = 0; i < 4; i++) {
            int d = lane + 32 * i;
            float c = cos1d[l * Dhc + d], s = sin1d[l * Dhc + d];
            float rot = (i < 2) ? -val[i ^ 2] : val[i ^ 2];
            out[i] = fmaf(val[i], c, rot * s);
        }
    } else {
#pragma unroll
        for (int i = 0; i < 4; i++) {
            int d = lane + 32 * i; int p = d >> 1; int jj = d & 1;
            float partner = __shfl_xor_sync(0xffffffffu, val[i], 1);
            float q0 = jj ? partner : val[i];
            float q1 = jj ? val[i] : partner;
            const float* R = rope3d + ((size_t)rel * 64 + p) * 4;
            float oimg = fmaf(q0, R[jj], q1 * R[2 + jj]);
            out[i] = img ? oimg : val[i];
        }
    }
#pragma unroll
    for (int i = 0; i < 4; i++) ptr[lane + 32 * i] = __float2half_rn(out[i]);
}

// ====== flash attention, fp16 mma.sync, q-tile 64, 2 CTAs/SM ==================
// CTA: 64 q-rows x 1 head, 4 warps (2m x 2n). kv-tile 64, K/V double-buffered.
// half offsets: Qh 0 (64x136), Kh 8704+buf*8704, Vh 26112+buf*8704,
//               Ph 43520 (64x72), red floats at half 48128.
#define FSMEM (48128 * 2 + 1024)   // 97280 bytes -> 2 CTAs/SM

__global__ void __launch_bounds__(128)
k_flash(__half* __restrict__ go) {
    extern __shared__ __half fh[];
    uint32_t base = smem_u32(fh);
    float2* red = (float2*)(fh + 48128);   // [wn][64] (rowmax, rowsum)

    int t = threadIdx.x, l = t & 31, wid = t >> 5;
    int lo = l & 3, lr = l >> 2;
    int wm = wid >> 1, wn = wid & 1;
    int q0 = blockIdx.x << 6;
    int h  = blockIdx.y, b = blockIdx.z;
    int kh = h >> 1;
    const float SC = 0.08838834764831845f;   // 1/sqrt(128)

    const __half* qkv = g_qkvh;

    // Q: 64x128 halves -> 1024 cells (stride 136)
#pragma unroll
    for (int i = 0; i < 8; i++) {
        int p = t + (i << 7); int r = p >> 4, c = p & 15;
        cpa16(base + (r * 136 + c * 8) * 2,
              qkv + (size_t)(b * Lc + q0 + r) * QKVN + h * Dhc + c * 8);
    }
    auto loadKV = [&](int kt, int buf) {
#pragma unroll
        for (int i = 0; i < 8; i++) {   // K: 1024 cells
            int p = t + (i << 7); int r = p >> 4, c = p & 15;
            cpa16(base + (8704 + buf * 8704 + r * 136 + c * 8) * 2,
                  qkv + (size_t)(b * Lc + kt * 64 + r) * QKVN + 2048 + kh * Dhc + c * 8);
        }
#pragma unroll
        for (int i = 0; i < 8; i++) {   // V: 1024 cells
            int p = t + (i << 7); int r = p >> 4, c = p & 15;
            cpa16(base + (26112 + buf * 8704 + r * 136 + c * 8) * 2,
                  qkv + (size_t)(b * Lc + kt * 64 + r) * QKVN + 3072 + kh * Dhc + c * 8);
        }
    };
    loadKV(0, 0);
    CP_COMMIT();
    CP_WAIT0();
    __syncthreads();

    float accO[2][8][4];
    float m_run[4], l_run[4];
#pragma unroll
    for (int i = 0; i < 2; i++)
#pragma unroll
        for (int j = 0; j < 8; j++)
#pragma unroll
            for (int c = 0; c < 4; c++) accO[i][j][c] = 0.f;
#pragma unroll
    for (int r = 0; r < 4; r++) { m_run[r] = -1e30f; l_run[r] = 0.f; }

    for (int kt = 0; kt < 32; kt++) {
        int cur = kt & 1;
        bool more = (kt + 1 < 32);
        if (more) { loadKV(kt + 1, cur ^ 1); CP_COMMIT(); }

        // ---- S = Q @ K^T (warp tile 32 q x 32 kv, k=128) ----
        float accS[2][4][4];
#pragma unroll
        for (int i = 0; i < 2; i++)
#pragma unroll
            for (int j = 0; j < 4; j++)
#pragma unroll
                for (int c = 0; c < 4; c++) accS[i][j][c] = 0.f;

        uint32_t Kb = base + (8704 + cur * 8704) * 2;
#pragma unroll
        for (int kc2 = 0; kc2 < 4; kc2++) {     // k32 chunks
            uint32_t bb[4][4];
#pragma unroll
            for (int nj = 0; nj < 4; nj++)
                ldsm4(bb[nj], Kb + ((wn * 32 + nj * 8 + (l & 7)) * 136
                                    + (kc2 * 4 + (l >> 3)) * 8) * 2);
#pragma unroll
            for (int kc = 0; kc < 2; kc++) {
                uint32_t aa[2][4];
#pragma unroll
                for (int mi = 0; mi < 2; mi++)
                    ldsm4(aa[mi], base + ((wm * 32 + mi * 16 + ((l >> 3) & 1) * 8 + (l & 7)) * 136
                                          + (kc2 * 4 + 2 * kc + (l >> 4)) * 8) * 2);
#pragma unroll
                for (int mi = 0; mi < 2; mi++)
#pragma unroll
                    for (int nj = 0; nj < 4; nj++)
                        mma16(accS[mi][nj], aa[mi], bb[nj][2 * kc], bb[nj][2 * kc + 1]);
            }
        }

        // ---- softmax: scale, warp-partial max/exp/sum ----
        float pm[4], ps[4];
#pragma unroll
        for (int r = 0; r < 4; r++) { pm[r] = -1e30f; ps[r] = 0.f; }
#pragma unroll
        for (int mi = 0; mi < 2; mi++)
#pragma unroll
            for (int nj = 0; nj < 4; nj++)
#pragma unroll
                for (int c = 0; c < 4; c++) {
                    float v = accS[mi][nj][c] * SC;
                    accS[mi][nj][c] = v;
                    int ri = mi * 2 + (c >> 1);
                    pm[ri] = fmaxf(pm[ri], v);
                }
#pragma unroll
        for (int r = 0; r < 4; r++) {
            pm[r] = fmaxf(pm[r], __shfl_xor_sync(0xffffffffu, pm[r], 1));
            pm[r] = fmaxf(pm[r], __shfl_xor_sync(0xffffffffu, pm[r], 2));
        }
#pragma unroll
        for (int mi = 0; mi < 2; mi++)
#pragma unroll
            for (int nj = 0; nj < 4; nj++)
#pragma unroll
                for (int c = 0; c < 4; c++) {
                    int ri = mi * 2 + (c >> 1);
                    float p = __expf(accS[mi][nj][c] - pm[ri]);
                    accS[mi][nj][c] = p;
                    ps[ri] += p;
                }
#pragma unroll
        for (int r = 0; r < 4; r++) {
            ps[r] += __shfl_xor_sync(0xffffffffu, ps[r], 1);
            ps[r] += __shfl_xor_sync(0xffffffffu, ps[r], 2);
        }
        if (lo == 0) {
#pragma unroll
            for (int mi = 0; mi < 2; mi++)
#pragma unroll
                for (int rb = 0; rb < 2; rb++) {
                    int grow = wm * 32 + mi * 16 + lr + 8 * rb;
                    red[wn * 64 + grow] = make_float2(pm[mi * 2 + rb], ps[mi * 2 + rb]);
                }
        }
        __syncthreads();   // red visible

        // ---- merge stats, correct O, write Ph ----
        float cf[4], corr[4];
#pragma unroll
        for (int mi = 0; mi < 2; mi++)
#pragma unroll
            for (int rb = 0; rb < 2; rb++) {
                int ri = mi * 2 + rb;
                int grow = wm * 32 + mi * 16 + lr + 8 * rb;
                float2 f0 = red[grow], f1 = red[64 + grow];
                float mnew = fmaxf(m_run[ri], fmaxf(f0.x, f1.x));
                float gsum = f0.y * __expf(f0.x - mnew) + f1.y * __expf(f1.x - mnew);
                corr[ri] = __expf(m_run[ri] - mnew);
                l_run[ri] = l_run[ri] * corr[ri] + gsum;
                m_run[ri] = mnew;
                cf[ri] = __expf(pm[ri] - mnew);
            }
#pragma unroll
        for (int mi = 0; mi < 2; mi++)
#pragma unroll
            for (int nj = 0; nj < 8; nj++)
#pragma unroll
                for (int c = 0; c < 4; c++)
                    accO[mi][nj][c] *= corr[mi * 2 + (c >> 1)];
        // Ph[row][col] half, stride 72
#pragma unroll
        for (int mi = 0; mi < 2; mi++)
#pragma unroll
            for (int nj = 0; nj < 4; nj++)
#pragma unroll
                for (int rb = 0; rb < 2; rb++) {
                    int row = wm * 32 + mi * 16 + lr + 8 * rb;
                    int col = wn * 32 + nj * 8 + 2 * lo;
                    float c = cf[mi * 2 + rb];
                    *(__half2*)(fh + 43520 + row * 72 + col) =
                        __floats2half2_rn(accS[mi][nj][rb * 2 + 0] * c,
                                          accS[mi][nj][rb * 2 + 1] * c);
                }
        __syncthreads();   // Ph visible

        // ---- O += P @ V (warp tile 32 q x 64 dh, k=64) ----
        uint32_t Vb = base + (26112 + cur * 8704) * 2;
        uint32_t Pb = base + 43520 * 2;
#pragma unroll
        for (int kc2 = 0; kc2 < 2; kc2++) {     // kv32 chunks
            uint32_t bb[8][4];
#pragma unroll
            for (int nj = 0; nj < 8; nj++)
                ldsm4t(bb[nj], Vb + ((kc2 * 32 + (l >> 3) * 8 + (l & 7)) * 136
                                     + wn * 64 + nj * 8) * 2);
#pragma unroll
            for (int kc = 0; kc < 2; kc++) {
                uint32_t aa[2][4];
#pragma unroll
                for (int mi = 0; mi < 2; mi++)
                    ldsm4(aa[mi], Pb + ((wm * 32 + mi * 16 + ((l >> 3) & 1) * 8 + (l & 7)) * 72
                                        + ((kc2 * 2 + kc) * 2 + (l >> 4)) * 8) * 2);
#pragma unroll
                for (int mi = 0; mi < 2; mi++)
#pragma unroll
                    for (int nj = 0; nj < 8; nj++)
                        mma16(accO[mi][nj], aa[mi], bb[nj][2 * kc], bb[nj][2 * kc + 1]);
            }
        }
        if (more) CP_WAIT0();
        __syncthreads();   // Ph/red reuse safe; next K/V buffer visible
    }

    // ---- epilogue: O /= l, write half ----
    float inv[4];
#pragma unroll
    for (int r = 0; r < 4; r++) inv[r] = 1.f / l_run[r];
#pragma unroll
    for (int mi = 0; mi < 2; mi++)
#pragma unroll
        for (int nj = 0; nj < 8; nj++) {
            int col = h * Dhc + wn * 64 + nj * 8 + 2 * lo;
#pragma unroll
            for (int rb = 0; rb < 2; rb++) {
                int row = q0 + wm * 32 + mi * 16 + lr + 8 * rb;
                float iv = inv[mi * 2 + rb];
                *(__half2*)(go + (size_t)(b * Lc + row) * Dc + col) =
                    __floats2half2_rn(accO[mi][nj][rb * 2 + 0] * iv,
                                      accO[mi][nj][rb * 2 + 1] * iv);
            }
        }
}

// ================================ host ========================================
extern "C" void kernel_launch(void* const* d_in, const int* in_sizes, int n_in,
                              void* d_out, int out_size) {
    const float* hidden = (const float*)d_in[0];
    const float* temb   = (const float*)d_in[1];
    const float* w_ln   = (const float*)d_in[2];
    const float* w_mod  = (const float*)d_in[3];
    const float* b_mod  = (const float*)d_in[4];
    const float* wq     = (const float*)d_in[5];
    const float* wk     = (const float*)d_in[6];
    const float* wv     = (const float*)d_in[7];
    const float* wo     = (const float*)d_in[8];
    const float* qn     = (const float*)d_in[9];
    const float* kn     = (const float*)d_in[10];
    const float* cos1   = (const float*)d_in[11];
    const float* sin1   = (const float*)d_in[12];
    const float* rope3  = (const float*)d_in[13];
    const int*   mpos   = (const int*)d_in[14];
    float* out = (float*)d_out;

    void *pxm, *pqkv, *po, *pwT, *pwoT;
    cudaGetSymbolAddress(&pxm,  g_xmh);
    cudaGetSymbolAddress(&pqkv, g_qkvh);
    cudaGetSymbolAddress(&po,   g_oh);
    cudaGetSymbolAddress(&pwT,  g_wTh);
    cudaGetSymbolAddress(&pwoT, g_woTh);

    cudaFuncSetAttribute(k_mma<0>, cudaFuncAttributeMaxDynamicSharedMemorySize, MMASMEM);
    cudaFuncSetAttribute(k_mma<1>, cudaFuncAttributeMaxDynamicSharedMemorySize, MMASMEM);
    cudaFuncSetAttribute(k_flash, cudaFuncAttributeMaxDynamicSharedMemorySize, FSMEM);

    k_mod<<<dim3(D3c / 64, Bc), 256>>>(temb, w_mod, b_mod);
    k_rmsmod<<<Bc * Lc, 256>>>(hidden, w_ln);

    k_transpose<<<dim3(Dc / 32, Dc / 32), dim3(32, 8)>>>(wq, (__half*)pwT, Dc, Dc);
    k_transpose<<<dim3(1024 / 32, Dc / 32), dim3(32, 8)>>>(wk, (__half*)pwT + (size_t)2048 * Dc, Dc, 1024);
    k_transpose<<<dim3(1024 / 32, Dc / 32), dim3(32, 8)>>>(wv, (__half*)pwT + (size_t)3072 * Dc, Dc, 1024);
    k_transpose<<<dim3(Dc / 32, Dc / 32), dim3(32, 8)>>>(wo, (__half*)pwoT, Dc, Dc);

    // fused QKV GEMM: [4096 x 4096] = xm @ [wq|wk|wv]^T  (half out)
    k_mma<0><<<dim3(QKVN / 256, (Bc * Lc) / 128), 512, MMASMEM>>>(
        (const __half*)pxm, (const __half*)pwT, pqkv, QKVN, Dc, nullptr);

    k_qknorm_rope<<<(Bc * Lc * (Hc + KVHc)) / 8, 256>>>(cos1, sin1, rope3, qn, kn, mpos);

    k_flash<<<dim3(Lc / 64, Hc, Bc), 128, FSMEM>>>((__half*)po);

    // output projection + residual/gate epilogue (float out)
    k_mma<1><<<dim3(Dc / 256, (Bc * Lc) / 128), 512, MMASMEM>>>(
        (const __half*)po, (const __half*)pwoT, out, Dc, Dc, hidden);
}

// round 11
// speedup vs baseline: 2.9140x; 1.0929x over previous
#include <cuda_runtime.h>
#include <cuda_fp16.h>
#include <cstdint>

#define Bc   2
#define Lc   2048
#define Dc   2048
#define Hc   16
#define KVHc 8
#define Dhc  128
#define QKVN 4096
#define D3c  6144
#define EPSc 1e-5f

// ---------------- scratch (device globals: allocation-guard safe) -------------
__device__ float  g_mod [Bc * D3c];
__device__ __half g_xmh [(size_t)Bc * Lc * Dc];
__device__ __half g_qkvh[(size_t)Bc * Lc * QKVN];  // 0..2047 Q | 2048..3071 K | 3072..4095 V
__device__ __half g_oh  [(size_t)Bc * Lc * Dc];
__device__ __half g_wTh [(size_t)QKVN * Dc];       // [wq^T ; wk^T ; wv^T], K-contig rows
__device__ __half g_woTh[(size_t)Dc * Dc];

// ================= helpers ====================================================
__device__ __forceinline__ uint32_t smem_u32(const void* p) {
    uint32_t a;
    asm("{ .reg .u64 t; cvta.to.shared.u64 t, %1; cvt.u32.u64 %0, t; }" : "=r"(a) : "l"(p));
    return a;
}
__device__ __forceinline__ void ldsm4(uint32_t* r, uint32_t a) {
    asm volatile("ldmatrix.sync.aligned.m8n8.x4.shared.b16 {%0,%1,%2,%3}, [%4];"
                 : "=r"(r[0]), "=r"(r[1]), "=r"(r[2]), "=r"(r[3]) : "r"(a));
}
__device__ __forceinline__ void ldsm4t(uint32_t* r, uint32_t a) {
    asm volatile("ldmatrix.sync.aligned.m8n8.x4.trans.shared.b16 {%0,%1,%2,%3}, [%4];"
                 : "=r"(r[0]), "=r"(r[1]), "=r"(r[2]), "=r"(r[3]) : "r"(a));
}
__device__ __forceinline__ void mma16(float* d, const uint32_t* a, uint32_t b0, uint32_t b1) {
    asm volatile("mma.sync.aligned.m16n8k16.row.col.f32.f16.f16.f32 "
                 "{%0,%1,%2,%3}, {%4,%5,%6,%7}, {%8,%9}, {%0,%1,%2,%3};"
                 : "+f"(d[0]), "+f"(d[1]), "+f"(d[2]), "+f"(d[3])
                 : "r"(a[0]), "r"(a[1]), "r"(a[2]), "r"(a[3]), "r"(b0), "r"(b1));
}
__device__ __forceinline__ void cpa16(uint32_t s, const void* g) {
    asm volatile("cp.async.cg.shared.global [%0], [%1], 16;" :: "r"(s), "l"(g));
}
__device__ __forceinline__ uint32_t pack2(float a, float b) {
    __half2 h = __floats2half2_rn(a, b);
    return *reinterpret_cast<uint32_t*>(&h);   // FIX: full 32-bit bit-cast, not __half2_raw.x
}
#define CP_COMMIT() asm volatile("cp.async.commit_group;" ::: "memory")
#define CP_WAIT0()  asm volatile("cp.async.wait_group 0;" ::: "memory")
#define CP_WAIT1()  asm volatile("cp.async.wait_group 1;" ::: "memory")

// ================= kernel 1: mod = silu(temb) @ w_mod + b_mod =================
__global__ void k_mod(const float* __restrict__ temb, const float* __restrict__ w_mod,
                      const float* __restrict__ b_mod) {
    __shared__ float st[Dc];
    __shared__ float ps[4][64];
    int b = blockIdx.y;
    int tx = threadIdx.x & 63, ty = threadIdx.x >> 6;
    int j = blockIdx.x * 64 + tx;
    for (int i = threadIdx.x; i < Dc; i += 256) {
        float x = temb[b * Dc + i];
        st[i] = x / (1.f + __expf(-x));
    }
    __syncthreads();
    float acc = 0.f;
    int k0 = ty * 512;
#pragma unroll 4
    for (int i = 0; i < 512; i++)
        acc = fmaf(st[k0 + i], w_mod[(size_t)(k0 + i) * D3c + j], acc);
    ps[ty][tx] = acc;
    __syncthreads();
    if (ty == 0)
        g_mod[b * D3c + j] = ps[0][tx] + ps[1][tx] + ps[2][tx] + ps[3][tx] + b_mod[j];
}

// ====== kernel 2: xm = half(rmsnorm(x)*w_ln*(1+scale)+shift) ==================
__global__ void k_rmsmod(const float* __restrict__ x, const float* __restrict__ w_ln) {
    int row = blockIdx.x;
    int b   = row >> 11;
    const float* xr = x + (size_t)row * Dc;
    int tid = threadIdx.x;
    float ss = 0.f;
    for (int i = tid; i < Dc; i += 256) { float v = xr[i]; ss = fmaf(v, v, ss); }
#pragma unroll
    for (int o = 16; o; o >>= 1) ss += __shfl_xor_sync(0xffffffffu, ss, o);
    __shared__ float red[8];
    __shared__ float sinv;
    if ((tid & 31) == 0) red[tid >> 5] = ss;
    __syncthreads();
    if (tid == 0) {
        float t = 0.f;
#pragma unroll
        for (int w = 0; w < 8; w++) t += red[w];
        sinv = rsqrtf(t * (1.f / Dc) + EPSc);
    }
    __syncthreads();
    float inv = sinv;
    const float* sh = g_mod + b * D3c;
    const float* sc = sh + Dc;
    __half* xm = g_xmh + (size_t)row * Dc;
    for (int i = tid; i < Dc; i += 256)
        xm[i] = __float2half_rn(fmaf(xr[i] * inv * w_ln[i], 1.f + sc[i], sh[i]));
}

// ====== transpose src[K][N] -> dst[N][K] (half) ===============================
__global__ void k_transpose(const float* __restrict__ src, __half* __restrict__ dst,
                            int K, int N) {
    __shared__ float t[32][33];
    int kb = blockIdx.y * 32, nb = blockIdx.x * 32;
    int x = threadIdx.x, y = threadIdx.y;
#pragma unroll
    for (int i = 0; i < 32; i += 8)
        t[y + i][x] = src[(size_t)(kb + y + i) * N + nb + x];
    __syncthreads();
#pragma unroll
    for (int i = 0; i < 32; i += 8)
        dst[(size_t)(nb + y + i) * K + kb + x] = __float2half_rn(t[x][y + i]);
}

// ====== fp16 mma.sync GEMM: C[M,N] = A[M,K] @ Bt[N,K]^T =======================
// BM=128 BN=256 BK=32. 16 warps (2m x 8n), warp tile 64x32. 3-stage cp.async,
// single __syncthreads per k-iter (multistage order).
#define MMASMEM (30720 * 3)   // 92160 bytes

template<int EPI>
__global__ void __launch_bounds__(512, 1)
k_mma(const __half* __restrict__ Ag, const __half* __restrict__ Bg,
      void* __restrict__ Cv, int N, int K, const float* __restrict__ hid) {
    extern __shared__ __half sh[];
    uint32_t base = smem_u32(sh);
    int t = threadIdx.x, l = t & 31, wid = t >> 5;
    int wm = wid >> 3, wn = wid & 7;
    int m0 = blockIdx.y * 128, n0 = blockIdx.x * 256;

    auto loadT = [&](int kt, int buf) {
        uint32_t ab = base + buf * 30720;
        {   // A: 512 cells, 1 per thread
            int r = t >> 2, c = t & 3;
            cpa16(ab + (r * 40 + c * 8) * 2,
                  Ag + (size_t)(m0 + r) * K + kt * 32 + c * 8);
        }
#pragma unroll
        for (int i = 0; i < 2; i++) {   // B: 1024 cells
            int p = t + (i << 9); int r = p >> 2, c = p & 3;
            cpa16(ab + 10240 + (r * 40 + c * 8) * 2,
                  Bg + (size_t)(n0 + r) * K + kt * 32 + c * 8);
        }
    };

    float acc[4][4][4];
#pragma unroll
    for (int i = 0; i < 4; i++)
#pragma unroll
        for (int j = 0; j < 4; j++)
#pragma unroll
            for (int c = 0; c < 4; c++) acc[i][j][c] = 0.f;

    int nk = K >> 5;
    loadT(0, 0); CP_COMMIT();
    loadT(1, 1); CP_COMMIT();

    int cur = 0;
    for (int kt = 0; kt < nk; kt++) {
        if (kt + 1 < nk) CP_WAIT1(); else CP_WAIT0();
        __syncthreads();   // buffer `cur` visible; buffer (kt-1)%3 fully drained
        if (kt + 2 < nk) {
            int nb = cur + 2; if (nb >= 3) nb -= 3;
            loadT(kt + 2, nb);
            CP_COMMIT();
        }

        uint32_t Ab = base + cur * 30720;
        uint32_t Bb = Ab + 10240;
        uint32_t bb[4][4];
#pragma unroll
        for (int j = 0; j < 4; j++)
            ldsm4(bb[j], Bb + ((wn * 32 + j * 8 + (l & 7)) * 40 + (l >> 3) * 8) * 2);
#pragma unroll
        for (int kc = 0; kc < 2; kc++) {
            uint32_t aa[4][4];
#pragma unroll
            for (int i = 0; i < 4; i++)
                ldsm4(aa[i], Ab + ((wm * 64 + i * 16 + ((l >> 3) & 1) * 8 + (l & 7)) * 40
                                   + (2 * kc + (l >> 4)) * 8) * 2);
#pragma unroll
            for (int i = 0; i < 4; i++)
#pragma unroll
                for (int j = 0; j < 4; j++)
                    mma16(acc[i][j], aa[i], bb[j][2 * kc], bb[j][2 * kc + 1]);
        }
        cur++; if (cur == 3) cur = 0;
    }

    // epilogue: c0=(r,2c) c1=(r,2c+1) c2=(r+8,..) ; r=l>>2, c=l&3
#pragma unroll
    for (int i = 0; i < 4; i++) {
        int gm = m0 + wm * 64 + i * 16 + (l >> 2);
#pragma unroll
        for (int j = 0; j < 4; j++) {
            int gn = n0 + wn * 32 + j * 8 + 2 * (l & 3);
            if (EPI == 0) {
                __half* C = (__half*)Cv;
                *(__half2*)(C + (size_t)gm * N + gn) =
                    __floats2half2_rn(acc[i][j][0], acc[i][j][1]);
                *(__half2*)(C + (size_t)(gm + 8) * N + gn) =
                    __floats2half2_rn(acc[i][j][2], acc[i][j][3]);
            } else {
                float* C = (float*)Cv;
                size_t o0 = (size_t)gm * N + gn;
                size_t o1 = (size_t)(gm + 8) * N + gn;
                int b0 = gm >> 11, b1 = (gm + 8) >> 11;
                float2 h0 = *(const float2*)(hid + o0);
                float2 h1 = *(const float2*)(hid + o1);
                float2 g0 = *(const float2*)(g_mod + b0 * D3c + 2 * Dc + gn);
                float2 g1 = *(const float2*)(g_mod + b1 * D3c + 2 * Dc + gn);
                *(float2*)(C + o0) = make_float2(fmaf(g0.x, acc[i][j][0], h0.x),
                                                 fmaf(g0.y, acc[i][j][1], h0.y));
                *(float2*)(C + o1) = make_float2(fmaf(g1.x, acc[i][j][2], h1.x),
                                                 fmaf(g1.y, acc[i][j][3], h1.y));
            }
        }
    }
}

// ====== per-head RMSNorm + mixed RoPE (half qkv, stride 4096) =================
__global__ void __launch_bounds__(256)
k_qknorm_rope(const float* __restrict__ cos1d, const float* __restrict__ sin1d,
              const float* __restrict__ rope3d,
              const float* __restrict__ qn, const float* __restrict__ kn,
              const int* __restrict__ mp) {
    int warp = threadIdx.x >> 5, lane = threadIdx.x & 31;
    int v  = blockIdx.x * 8 + warp;
    int bl = v / 24, r = v % 24;
    int b = bl >> 11, l = bl & 2047;

    __half* ptr; const float* w;
    if (r < Hc) { ptr = g_qkvh + (size_t)bl * QKVN + r * Dhc;               w = qn; }
    else        { ptr = g_qkvh + (size_t)bl * QKVN + 2048 + (r - Hc) * Dhc; w = kn; }

    float val[4];
    float ss = 0.f;
#pragma unroll
    for (int i = 0; i < 4; i++) {
        val[i] = __half2float(ptr[lane + 32 * i]);
        ss = fmaf(val[i], val[i], ss);
    }
#pragma unroll
    for (int o = 16; o; o >>= 1) ss += __shfl_xor_sync(0xffffffffu, ss, o);
    float inv = rsqrtf(ss * (1.f / Dhc) + EPSc);
#pragma unroll
    for (int i = 0; i < 4; i++) val[i] *= inv * w[lane + 32 * i];

    bool is64 = (mp[1] == 0);
    bool in_full = false, in_img = false; int rel = 0;
#pragma unroll
    for (int m = 0; m < 2; m++) {
        int off, ln;
        if (is64) { off = mp[(b * 4 + m * 2) * 2]; ln = mp[(b * 4 + m * 2 + 1) * 2]; }
        else      { off = mp[b * 4 + m * 2];       ln = mp[b * 4 + m * 2 + 1]; }
        int seg_end = off + max(ln, 1);
        if (l >= off && l < seg_end) in_full = true;
        if (l >= off + 1 && l < off + ln) { in_img = true; rel += l - (off + 1); }
    }
    bool text = !in_full;
    bool img  = in_img && (rel < 1024);
    rel = min(max(rel, 0), 1023);

    float out[4];
    if (text) {
#pragma unroll
        for (int i = 0; i < 4; i++) {
            int d = lane + 32 * i;
            float c = cos1d[l * Dhc + d], s = sin1d[l * Dhc + d];
            float rot = (i < 2) ? -val[i ^ 2] : val[i ^ 2];
            out[i] = fmaf(val[i], c, rot * s);
        }
    } else {
#pragma unroll
        for (int i = 0; i < 4; i++) {
            int d = lane + 32 * i; int p = d >> 1; int jj = d & 1;
            float partner = __shfl_xor_sync(0xffffffffu, val[i], 1);
            float q0 = jj ? partner : val[i];
            float q1 = jj ? val[i] : partner;
            const float* R = rope3d + ((size_t)rel * 64 + p) * 4;
            float oimg = fmaf(q0, R[jj], q1 * R[2 + jj]);
            out[i] = img ? oimg : val[i];
        }
    }
#pragma unroll
    for (int i = 0; i < 4; i++) ptr[lane + 32 * i] = __float2half_rn(out[i]);
}

// ====== flash attention, FA2-style: warp = 16 q-rows x full 64-kv tile ========
// CTA: 64 q-rows x 1 head, 4 warps. P register-resident (C-frag == A-frag).
// Q frags preloaded. ONE __syncthreads per kv-iter. 2 CTAs/SM (87 KB smem).
#define FSMEM (43520 * 2)   // 87040 bytes

__global__ void __launch_bounds__(128)
k_flash(__half* __restrict__ go) {
    extern __shared__ __half fh[];
    uint32_t base = smem_u32(fh);

    int t = threadIdx.x, l = t & 31, wid = t >> 5;
    int lo = l & 3, lr = l >> 2;
    int q0 = blockIdx.x << 6;
    int h  = blockIdx.y, b = blockIdx.z;
    int kh = h >> 1;
    const float SC = 0.08838834764831845f;   // 1/sqrt(128)

    const __half* qkv = g_qkvh;

    // Q: 64x128 halves (stride 136), in group 0 with KV(0)
#pragma unroll
    for (int i = 0; i < 8; i++) {
        int p = t + (i << 7); int r = p >> 4, c = p & 15;
        cpa16(base + (r * 136 + c * 8) * 2,
              qkv + (size_t)(b * Lc + q0 + r) * QKVN + h * Dhc + c * 8);
    }
    auto loadKV = [&](int kt, int buf) {
        uint32_t sb = base + (8704 + buf * 17408) * 2;
#pragma unroll
        for (int i = 0; i < 8; i++) {   // K: 1024 cells
            int p = t + (i << 7); int r = p >> 4, c = p & 15;
            cpa16(sb + (r * 136 + c * 8) * 2,
                  qkv + (size_t)(b * Lc + kt * 64 + r) * QKVN + 2048 + kh * Dhc + c * 8);
        }
#pragma unroll
        for (int i = 0; i < 8; i++) {   // V: 1024 cells
            int p = t + (i << 7); int r = p >> 4, c = p & 15;
            cpa16(sb + (8704 + r * 136 + c * 8) * 2,
                  qkv + (size_t)(b * Lc + kt * 64 + r) * QKVN + 3072 + kh * Dhc + c * 8);
        }
    };
    loadKV(0, 0); CP_COMMIT();     // G0: Q + KV(0)
    loadKV(1, 1); CP_COMMIT();     // G1: KV(1)
    CP_WAIT1();                    // G0 done
    __syncthreads();

    // Q fragments: loop-invariant, 32 regs (rows wid*16..+15, k=128)
    uint32_t Qa[8][4];
#pragma unroll
    for (int kq = 0; kq < 8; kq++)
        ldsm4(Qa[kq], base + ((wid * 16 + ((l >> 3) & 1) * 8 + (l & 7)) * 136
                              + (kq * 2 + (l >> 4)) * 8) * 2);

    float accO[16][4];
    float m_run[2], l_run[2];
#pragma unroll
    for (int j = 0; j < 16; j++)
#pragma unroll
        for (int c = 0; c < 4; c++) accO[j][c] = 0.f;
    m_run[0] = m_run[1] = -1e30f;
    l_run[0] = l_run[1] = 0.f;

    for (int kt = 0; kt < 32; kt++) {
        int cur = kt & 1;
        uint32_t Kb = base + (8704 + cur * 17408) * 2;
        uint32_t Vb = Kb + 8704 * 2;

        // ---- S = Q @ K^T : warp tile 16q x 64kv, k=128 ----
        float accS[8][4];
#pragma unroll
        for (int j = 0; j < 8; j++)
#pragma unroll
            for (int c = 0; c < 4; c++) accS[j][c] = 0.f;
#pragma unroll
        for (int kc2 = 0; kc2 < 4; kc2++) {
            uint32_t bb[8][4];
#pragma unroll
            for (int nj = 0; nj < 8; nj++)
                ldsm4(bb[nj], Kb + ((nj * 8 + (l & 7)) * 136 + (kc2 * 4 + (l >> 3)) * 8) * 2);
#pragma unroll
            for (int kc = 0; kc < 2; kc++)
#pragma unroll
                for (int nj = 0; nj < 8; nj++)
                    mma16(accS[nj], Qa[kc2 * 2 + kc], bb[nj][2 * kc], bb[nj][2 * kc + 1]);
        }

        // ---- softmax (warp-local rows lr, lr+8; reduce over lanes lo) ----
        float pm[2], ps[2];
        pm[0] = pm[1] = -1e30f; ps[0] = ps[1] = 0.f;
#pragma unroll
        for (int nj = 0; nj < 8; nj++)
#pragma unroll
            for (int c = 0; c < 4; c++) {
                float v = accS[nj][c] * SC;
                accS[nj][c] = v;
                pm[c >> 1] = fmaxf(pm[c >> 1], v);
            }
#pragma unroll
        for (int r = 0; r < 2; r++) {
            pm[r] = fmaxf(pm[r], __shfl_xor_sync(0xffffffffu, pm[r], 1));
            pm[r] = fmaxf(pm[r], __shfl_xor_sync(0xffffffffu, pm[r], 2));
        }
#pragma unroll
        for (int nj = 0; nj < 8; nj++)
#pragma unroll
            for (int c = 0; c < 4; c++) {
                float p = __expf(accS[nj][c] - pm[c >> 1]);
                accS[nj][c] = p;
                ps[c >> 1] += p;
            }
#pragma unroll
        for (int r = 0; r < 2; r++) {
            ps[r] += __shfl_xor_sync(0xffffffffu, ps[r], 1);
            ps[r] += __shfl_xor_sync(0xffffffffu, ps[r], 2);
        }
        float cf[2], corr[2];
#pragma unroll
        for (int r = 0; r < 2; r++) {
            float mnew = fmaxf(m_run[r], pm[r]);
            corr[r] = __expf(m_run[r] - mnew);
            cf[r]   = __expf(pm[r] - mnew);
            l_run[r] = l_run[r] * corr[r] + ps[r] * cf[r];
            m_run[r] = mnew;
        }
#pragma unroll
        for (int nj = 0; nj < 16; nj++)
#pragma unroll
            for (int c = 0; c < 4; c++)
                accO[nj][c] *= corr[c >> 1];

        // ---- P repack: C-frag -> A-frag (registers), fold cf ----
        uint32_t Pa[4][4];
#pragma unroll
        for (int kc = 0; kc < 4; kc++) {
            Pa[kc][0] = pack2(accS[2*kc][0]   * cf[0], accS[2*kc][1]   * cf[0]);
            Pa[kc][1] = pack2(accS[2*kc][2]   * cf[1], accS[2*kc][3]   * cf[1]);
            Pa[kc][2] = pack2(accS[2*kc+1][0] * cf[0], accS[2*kc+1][1] * cf[0]);
            Pa[kc][3] = pack2(accS[2*kc+1][2] * cf[1], accS[2*kc+1][3] * cf[1]);
        }

        // ---- O += P @ V : warp tile 16q x 128dh, k=64 ----
#pragma unroll
        for (int kc2 = 0; kc2 < 2; kc2++)
#pragma unroll
            for (int nh = 0; nh < 2; nh++) {
                uint32_t bb[8][4];
#pragma unroll
                for (int nj = 0; nj < 8; nj++)
                    ldsm4t(bb[nj], Vb + ((kc2 * 32 + (l >> 3) * 8 + (l & 7)) * 136
                                         + (nh * 8 + nj) * 8) * 2);
#pragma unroll
                for (int kc = 0; kc < 2; kc++)
#pragma unroll
                    for (int nj = 0; nj < 8; nj++)
                        mma16(accO[nh * 8 + nj], Pa[kc2 * 2 + kc],
                              bb[nj][2 * kc], bb[nj][2 * kc + 1]);
            }

        // ---- advance pipeline: KV(kt+1) arrived; stage `cur` is free ----
        if (kt < 31) {
            CP_WAIT0();
            __syncthreads();
            if (kt < 30) { loadKV(kt + 2, cur); CP_COMMIT(); }
        }
    }

    // ---- epilogue: O /= l, write half (rows wid*16+lr, wid*16+lr+8) ----
    float inv0 = 1.f / l_run[0], inv1 = 1.f / l_run[1];
    int row0 = q0 + wid * 16 + lr;
#pragma unroll
    for (int nj = 0; nj < 16; nj++) {
        int col = h * Dhc + nj * 8 + 2 * lo;
        *(__half2*)(go + (size_t)(b * Lc + row0) * Dc + col) =
            __floats2half2_rn(accO[nj][0] * inv0, accO[nj][1] * inv0);
        *(__half2*)(go + (size_t)(b * Lc + row0 + 8) * Dc + col) =
            __floats2half2_rn(accO[nj][2] * inv1, accO[nj][3] * inv1);
    }
}

// ================================ host ========================================
extern "C" void kernel_launch(void* const* d_in, const int* in_sizes, int n_in,
                              void* d_out, int out_size) {
    const float* hidden = (const float*)d_in[0];
    const float* temb   = (const float*)d_in[1];
    const float* w_ln   = (const float*)d_in[2];
    const float* w_mod  = (const float*)d_in[3];
    const float* b_mod  = (const float*)d_in[4];
    const float* wq     = (const float*)d_in[5];
    const float* wk     = (const float*)d_in[6];
    const float* wv     = (const float*)d_in[7];
    const float* wo     = (const float*)d_in[8];
    const float* qn     = (const float*)d_in[9];
    const float* kn     = (const float*)d_in[10];
    const float* cos1   = (const float*)d_in[11];
    const float* sin1   = (const float*)d_in[12];
    const float* rope3  = (const float*)d_in[13];
    const int*   mpos   = (const int*)d_in[14];
    float* out = (float*)d_out;

    void *pxm, *pqkv, *po, *pwT, *pwoT;
    cudaGetSymbolAddress(&pxm,  g_xmh);
    cudaGetSymbolAddress(&pqkv, g_qkvh);
    cudaGetSymbolAddress(&po,   g_oh);
    cudaGetSymbolAddress(&pwT,  g_wTh);
    cudaGetSymbolAddress(&pwoT, g_woTh);

    cudaFuncSetAttribute(k_mma<0>, cudaFuncAttributeMaxDynamicSharedMemorySize, MMASMEM);
    cudaFuncSetAttribute(k_mma<1>, cudaFuncAttributeMaxDynamicSharedMemorySize, MMASMEM);
    cudaFuncSetAttribute(k_flash, cudaFuncAttributeMaxDynamicSharedMemorySize, FSMEM);

    k_mod<<<dim3(D3c / 64, Bc), 256>>>(temb, w_mod, b_mod);
    k_rmsmod<<<Bc * Lc, 256>>>(hidden, w_ln);

    k_transpose<<<dim3(Dc / 32, Dc / 32), dim3(32, 8)>>>(wq, (__half*)pwT, Dc, Dc);
    k_transpose<<<dim3(1024 / 32, Dc / 32), dim3(32, 8)>>>(wk, (__half*)pwT + (size_t)2048 * Dc, Dc, 1024);
    k_transpose<<<dim3(1024 / 32, Dc / 32), dim3(32, 8)>>>(wv, (__half*)pwT + (size_t)3072 * Dc, Dc, 1024);
    k_transpose<<<dim3(Dc / 32, Dc / 32), dim3(32, 8)>>>(wo, (__half*)pwoT, Dc, Dc);

    // fused QKV GEMM: [4096 x 4096] = xm @ [wq|wk|wv]^T  (half out)
    k_mma<0><<<dim3(QKVN / 256, (Bc * Lc) / 128), 512, MMASMEM>>>(
        (const __half*)pxm, (const __half*)pwT, pqkv, QKVN, Dc, nullptr);

    k_qknorm_rope<<<(Bc * Lc * (Hc + KVHc)) / 8, 256>>>(cos1, sin1, rope3, qn, kn, mpos);

    k_flash<<<dim3(Lc / 64, Hc, Bc), 128, FSMEM>>>((__half*)po);

    // output projection + residual/gate epilogue (float out)
    k_mma<1><<<dim3(Dc / 256, (Bc * Lc) / 128), 512, MMASMEM>>>(
        (const __half*)po, (const __half*)pwoT, out, Dc, Dc, hidden);
}

// round 12
// speedup vs baseline: 3.2419x; 1.1125x over previous
#include <cuda_runtime.h>
#include <cuda_fp16.h>
#include <cstdint>

#define Bc   2
#define Lc   2048
#define Dc   2048
#define Hc   16
#define KVHc 8
#define Dhc  128
#define QKVN 4096
#define D3c  6144
#define EPSc 1e-5f

// ---------------- scratch (device globals: allocation-guard safe) -------------
__device__ float  g_mod [Bc * D3c];
__device__ __half g_xmh [(size_t)Bc * Lc * Dc];
__device__ __half g_qkvh[(size_t)Bc * Lc * QKVN];  // 0..2047 Q | 2048..3071 K | 3072..4095 V
__device__ __half g_oh  [(size_t)Bc * Lc * Dc];
__device__ __half g_wTh [(size_t)QKVN * Dc];       // [wq^T ; wk^T ; wv^T], K-contig rows
__device__ __half g_woTh[(size_t)Dc * Dc];

// ================= helpers ====================================================
__device__ __forceinline__ uint32_t smem_u32(const void* p) {
    uint32_t a;
    asm("{ .reg .u64 t; cvta.to.shared.u64 t, %1; cvt.u32.u64 %0, t; }" : "=r"(a) : "l"(p));
    return a;
}
__device__ __forceinline__ void ldsm4(uint32_t* r, uint32_t a) {
    asm volatile("ldmatrix.sync.aligned.m8n8.x4.shared.b16 {%0,%1,%2,%3}, [%4];"
                 : "=r"(r[0]), "=r"(r[1]), "=r"(r[2]), "=r"(r[3]) : "r"(a));
}
__device__ __forceinline__ void ldsm4t(uint32_t* r, uint32_t a) {
    asm volatile("ldmatrix.sync.aligned.m8n8.x4.trans.shared.b16 {%0,%1,%2,%3}, [%4];"
                 : "=r"(r[0]), "=r"(r[1]), "=r"(r[2]), "=r"(r[3]) : "r"(a));
}
__device__ __forceinline__ void mma16(float* d, const uint32_t* a, uint32_t b0, uint32_t b1) {
    asm volatile("mma.sync.aligned.m16n8k16.row.col.f32.f16.f16.f32 "
                 "{%0,%1,%2,%3}, {%4,%5,%6,%7}, {%8,%9}, {%0,%1,%2,%3};"
                 : "+f"(d[0]), "+f"(d[1]), "+f"(d[2]), "+f"(d[3])
                 : "r"(a[0]), "r"(a[1]), "r"(a[2]), "r"(a[3]), "r"(b0), "r"(b1));
}
__device__ __forceinline__ void cpa16(uint32_t s, const void* g) {
    asm volatile("cp.async.cg.shared.global [%0], [%1], 16;" :: "r"(s), "l"(g));
}
__device__ __forceinline__ uint32_t pack2(float a, float b) {
    __half2 h = __floats2half2_rn(a, b);
    return *reinterpret_cast<uint32_t*>(&h);
}
#define CP_COMMIT() asm volatile("cp.async.commit_group;" ::: "memory")
#define CP_WAIT0()  asm volatile("cp.async.wait_group 0;" ::: "memory")
#define CP_WAIT1()  asm volatile("cp.async.wait_group 1;" ::: "memory")

// ================= kernel 1: mod = silu(temb) @ w_mod + b_mod =================
__global__ void k_mod(const float* __restrict__ temb, const float* __restrict__ w_mod,
                      const float* __restrict__ b_mod) {
    __shared__ float st[Dc];
    __shared__ float ps[4][64];
    int b = blockIdx.y;
    int tx = threadIdx.x & 63, ty = threadIdx.x >> 6;
    int j = blockIdx.x * 64 + tx;
    for (int i = threadIdx.x; i < Dc; i += 256) {
        float x = temb[b * Dc + i];
        st[i] = x / (1.f + __expf(-x));
    }
    __syncthreads();
    float acc = 0.f;
    int k0 = ty * 512;
#pragma unroll 4
    for (int i = 0; i < 512; i++)
        acc = fmaf(st[k0 + i], w_mod[(size_t)(k0 + i) * D3c + j], acc);
    ps[ty][tx] = acc;
    __syncthreads();
    if (ty == 0)
        g_mod[b * D3c + j] = ps[0][tx] + ps[1][tx] + ps[2][tx] + ps[3][tx] + b_mod[j];
}

// ====== kernel 2: xm = half(rmsnorm(x)*w_ln*(1+scale)+shift) ==================
__global__ void k_rmsmod(const float* __restrict__ x, const float* __restrict__ w_ln) {
    int row = blockIdx.x;
    int b   = row >> 11;
    const float* xr = x + (size_t)row * Dc;
    int tid = threadIdx.x;
    float ss = 0.f;
    for (int i = tid; i < Dc; i += 256) { float v = xr[i]; ss = fmaf(v, v, ss); }
#pragma unroll
    for (int o = 16; o; o >>= 1) ss += __shfl_xor_sync(0xffffffffu, ss, o);
    __shared__ float red[8];
    __shared__ float sinv;
    if ((tid & 31) == 0) red[tid >> 5] = ss;
    __syncthreads();
    if (tid == 0) {
        float t = 0.f;
#pragma unroll
        for (int w = 0; w < 8; w++) t += red[w];
        sinv = rsqrtf(t * (1.f / Dc) + EPSc);
    }
    __syncthreads();
    float inv = sinv;
    const float* sh = g_mod + b * D3c;
    const float* sc = sh + Dc;
    __half* xm = g_xmh + (size_t)row * Dc;
    for (int i = tid; i < Dc; i += 256)
        xm[i] = __float2half_rn(fmaf(xr[i] * inv * w_ln[i], 1.f + sc[i], sh[i]));
}

// ====== batched transpose: all 4 weights in one launch ========================
__global__ void k_transpose4(const float* __restrict__ wq, const float* __restrict__ wk,
                             const float* __restrict__ wv, const float* __restrict__ wo) {
    __shared__ float t[32][33];
    const float* src; __half* dst; int N;
    switch (blockIdx.z) {
        case 0:  src = wq; dst = g_wTh;                         N = 2048; break;
        case 1:  src = wk; dst = g_wTh + (size_t)2048 * Dc;     N = 1024; break;
        case 2:  src = wv; dst = g_wTh + (size_t)3072 * Dc;     N = 1024; break;
        default: src = wo; dst = g_woTh;                        N = 2048; break;
    }
    int nb = blockIdx.x * 32;
    if (nb >= N) return;
    int kb = blockIdx.y * 32;
    int x = threadIdx.x, y = threadIdx.y;
#pragma unroll
    for (int i = 0; i < 32; i += 8)
        t[y + i][x] = src[(size_t)(kb + y + i) * N + nb + x];
    __syncthreads();
#pragma unroll
    for (int i = 0; i < 32; i += 8)
        dst[(size_t)(nb + y + i) * Dc + kb + x] = __float2half_rn(t[x][y + i]);
}

// ====== fp16 mma.sync GEMM: C[M,N] = A[M,K] @ Bt[N,K]^T =======================
// BM=128 BN=256 BK=64. 16 warps (2m x 8n), warp tile 64x32. 3-stage cp.async,
// single __syncthreads per k-iter. Row stride 72 halves (9 cells, odd -> ok).
#define GSTAGE 55296                 // A 128*72*2 + B 256*72*2
#define MMASMEM (GSTAGE * 3)         // 165888 bytes

template<int EPI>
__global__ void __launch_bounds__(512, 1)
k_mma(const __half* __restrict__ Ag, const __half* __restrict__ Bg,
      void* __restrict__ Cv, int N, int K, const float* __restrict__ hid) {
    extern __shared__ __half sh[];
    uint32_t base = smem_u32(sh);
    int t = threadIdx.x, l = t & 31, wid = t >> 5;
    int wm = wid >> 3, wn = wid & 7;
    int m0 = blockIdx.y * 128, n0 = blockIdx.x * 256;

    auto loadT = [&](int kt, int buf) {
        uint32_t ab = base + buf * GSTAGE;
#pragma unroll
        for (int i = 0; i < 2; i++) {   // A: 1024 cells (128 rows x 8 cells)
            int p = t + (i << 9); int r = p >> 3, c = p & 7;
            cpa16(ab + (r * 72 + c * 8) * 2,
                  Ag + (size_t)(m0 + r) * K + kt * 64 + c * 8);
        }
#pragma unroll
        for (int i = 0; i < 4; i++) {   // B: 2048 cells (256 rows x 8 cells)
            int p = t + (i << 9); int r = p >> 3, c = p & 7;
            cpa16(ab + 18432 + (r * 72 + c * 8) * 2,
                  Bg + (size_t)(n0 + r) * K + kt * 64 + c * 8);
        }
    };

    float acc[4][4][4];
#pragma unroll
    for (int i = 0; i < 4; i++)
#pragma unroll
        for (int j = 0; j < 4; j++)
#pragma unroll
            for (int c = 0; c < 4; c++) acc[i][j][c] = 0.f;

    int nk = K >> 6;
    loadT(0, 0); CP_COMMIT();
    loadT(1, 1); CP_COMMIT();

    int cur = 0;
    for (int kt = 0; kt < nk; kt++) {
        if (kt + 1 < nk) CP_WAIT1(); else CP_WAIT0();
        __syncthreads();   // buffer `cur` visible; prev buffer fully drained
        if (kt + 2 < nk) {
            int nb = cur + 2; if (nb >= 3) nb -= 3;
            loadT(kt + 2, nb);
            CP_COMMIT();
        }

        uint32_t Ab = base + cur * GSTAGE;
        uint32_t Bb = Ab + 18432;
#pragma unroll
        for (int kc2 = 0; kc2 < 2; kc2++) {      // two k32 chunks of BK=64
            uint32_t bb[4][4];
#pragma unroll
            for (int j = 0; j < 4; j++)
                ldsm4(bb[j], Bb + ((wn * 32 + j * 8 + (l & 7)) * 72
                                   + (kc2 * 4 + (l >> 3)) * 8) * 2);
#pragma unroll
            for (int kc = 0; kc < 2; kc++) {
                uint32_t aa[4][4];
#pragma unroll
                for (int i = 0; i < 4; i++)
                    ldsm4(aa[i], Ab + ((wm * 64 + i * 16 + ((l >> 3) & 1) * 8 + (l & 7)) * 72
                                       + (kc2 * 4 + 2 * kc + (l >> 4)) * 8) * 2);
#pragma unroll
                for (int i = 0; i < 4; i++)
#pragma unroll
                    for (int j = 0; j < 4; j++)
                        mma16(acc[i][j], aa[i], bb[j][2 * kc], bb[j][2 * kc + 1]);
            }
        }
        cur++; if (cur == 3) cur = 0;
    }

    // epilogue
#pragma unroll
    for (int i = 0; i < 4; i++) {
        int gm = m0 + wm * 64 + i * 16 + (l >> 2);
#pragma unroll
        for (int j = 0; j < 4; j++) {
            int gn = n0 + wn * 32 + j * 8 + 2 * (l & 3);
            if (EPI == 0) {
                __half* C = (__half*)Cv;
                *(__half2*)(C + (size_t)gm * N + gn) =
                    __floats2half2_rn(acc[i][j][0], acc[i][j][1]);
                *(__half2*)(C + (size_t)(gm + 8) * N + gn) =
                    __floats2half2_rn(acc[i][j][2], acc[i][j][3]);
            } else {
                float* C = (float*)Cv;
                size_t o0 = (size_t)gm * N + gn;
                size_t o1 = (size_t)(gm + 8) * N + gn;
                int b0 = gm >> 11, b1 = (gm + 8) >> 11;
                float2 h0 = *(const float2*)(hid + o0);
                float2 h1 = *(const float2*)(hid + o1);
                float2 g0 = *(const float2*)(g_mod + b0 * D3c + 2 * Dc + gn);
                float2 g1 = *(const float2*)(g_mod + b1 * D3c + 2 * Dc + gn);
                *(float2*)(C + o0) = make_float2(fmaf(g0.x, acc[i][j][0], h0.x),
                                                 fmaf(g0.y, acc[i][j][1], h0.y));
                *(float2*)(C + o1) = make_float2(fmaf(g1.x, acc[i][j][2], h1.x),
                                                 fmaf(g1.y, acc[i][j][3], h1.y));
            }
        }
    }
}

// ====== per-head RMSNorm + mixed RoPE, vectorized (uint2 per lane) ============
// lane owns d = lane*4 .. lane*4+3 (contiguous). Image pairs intra-lane;
// text rotate-half partner via shfl_xor(16).
__global__ void __launch_bounds__(256)
k_qknorm_rope(const float* __restrict__ cos1d, const float* __restrict__ sin1d,
              const float* __restrict__ rope3d,
              const float* __restrict__ qn, const float* __restrict__ kn,
              const int* __restrict__ mp) {
    int warp = threadIdx.x >> 5, lane = threadIdx.x & 31;
    int v  = blockIdx.x * 8 + warp;
    int bl = v / 24, r = v % 24;
    int b = bl >> 11, l = bl & 2047;
    int d0 = lane * 4;

    __half* ptr; const float* w;
    if (r < Hc) { ptr = g_qkvh + (size_t)bl * QKVN + r * Dhc;               w = qn; }
    else        { ptr = g_qkvh + (size_t)bl * QKVN + 2048 + (r - Hc) * Dhc; w = kn; }

    __half2 h01 = *(const __half2*)(ptr + d0);
    __half2 h23 = *(const __half2*)(ptr + d0 + 2);
    float val[4] = { __half2float(h01.x), __half2float(h01.y),
                     __half2float(h23.x), __half2float(h23.y) };
    float ss = 0.f;
#pragma unroll
    for (int i = 0; i < 4; i++) ss = fmaf(val[i], val[i], ss);
#pragma unroll
    for (int o = 16; o; o >>= 1) ss += __shfl_xor_sync(0xffffffffu, ss, o);
    float inv = rsqrtf(ss * (1.f / Dhc) + EPSc);
    float4 wv4 = *(const float4*)(w + d0);
    val[0] *= inv * wv4.x; val[1] *= inv * wv4.y;
    val[2] *= inv * wv4.z; val[3] *= inv * wv4.w;

    bool is64 = (mp[1] == 0);
    bool in_full = false, in_img = false; int rel = 0;
#pragma unroll
    for (int m = 0; m < 2; m++) {
        int off, ln;
        if (is64) { off = mp[(b * 4 + m * 2) * 2]; ln = mp[(b * 4 + m * 2 + 1) * 2]; }
        else      { off = mp[b * 4 + m * 2];       ln = mp[b * 4 + m * 2 + 1]; }
        int seg_end = off + max(ln, 1);
        if (l >= off && l < seg_end) in_full = true;
        if (l >= off + 1 && l < off + ln) { in_img = true; rel += l - (off + 1); }
    }
    bool text = !in_full;
    bool img  = in_img && (rel < 1024);
    rel = min(max(rel, 0), 1023);

    float out[4];
    if (text) {
        float4 c4 = *(const float4*)(cos1d + l * Dhc + d0);
        float4 s4 = *(const float4*)(sin1d + l * Dhc + d0);
        float sgn = (d0 < 64) ? -1.f : 1.f;
        float cc[4] = {c4.x, c4.y, c4.z, c4.w};
        float s_[4] = {s4.x, s4.y, s4.z, s4.w};
#pragma unroll
        for (int i = 0; i < 4; i++) {
            float partner = __shfl_xor_sync(0xffffffffu, val[i], 16);
            out[i] = fmaf(val[i], cc[i], sgn * partner * s_[i]);
        }
    } else {
        // pairs (d0, d0+1) and (d0+2, d0+3): p = 2*lane, 2*lane+1
        const float4 R0 = *(const float4*)(rope3d + ((size_t)rel * 64 + 2 * lane) * 4);
        const float4 R1 = *(const float4*)(rope3d + ((size_t)rel * 64 + 2 * lane + 1) * 4);
        float o0 = fmaf(val[0], R0.x, val[1] * R0.z);
        float o1 = fmaf(val[0], R0.y, val[1] * R0.w);
        float o2 = fmaf(val[2], R1.x, val[3] * R1.z);
        float o3 = fmaf(val[2], R1.y, val[3] * R1.w);
        out[0] = img ? o0 : val[0]; out[1] = img ? o1 : val[1];
        out[2] = img ? o2 : val[2]; out[3] = img ? o3 : val[3];
    }
    *(__half2*)(ptr + d0)     = __floats2half2_rn(out[0], out[1]);
    *(__half2*)(ptr + d0 + 2) = __floats2half2_rn(out[2], out[3]);
}

// ====== flash attention, FA2-style (round-11, verified) =======================
#define FSMEM (43520 * 2)   // 87040 bytes, 2 CTAs/SM

__global__ void __launch_bounds__(128)
k_flash(__half* __restrict__ go) {
    extern __shared__ __half fh[];
    uint32_t base = smem_u32(fh);

    int t = threadIdx.x, l = t & 31, wid = t >> 5;
    int lo = l & 3, lr = l >> 2;
    int q0 = blockIdx.x << 6;
    int h  = blockIdx.y, b = blockIdx.z;
    int kh = h >> 1;
    const float SC = 0.08838834764831845f;

    const __half* qkv = g_qkvh;

#pragma unroll
    for (int i = 0; i < 8; i++) {
        int p = t + (i << 7); int r = p >> 4, c = p & 15;
        cpa16(base + (r * 136 + c * 8) * 2,
              qkv + (size_t)(b * Lc + q0 + r) * QKVN + h * Dhc + c * 8);
    }
    auto loadKV = [&](int kt, int buf) {
        uint32_t sb = base + (8704 + buf * 17408) * 2;
#pragma unroll
        for (int i = 0; i < 8; i++) {
            int p = t + (i << 7); int r = p >> 4, c = p & 15;
            cpa16(sb + (r * 136 + c * 8) * 2,
                  qkv + (size_t)(b * Lc + kt * 64 + r) * QKVN + 2048 + kh * Dhc + c * 8);
        }
#pragma unroll
        for (int i = 0; i < 8; i++) {
            int p = t + (i << 7); int r = p >> 4, c = p & 15;
            cpa16(sb + (8704 + r * 136 + c * 8) * 2,
                  qkv + (size_t)(b * Lc + kt * 64 + r) * QKVN + 3072 + kh * Dhc + c * 8);
        }
    };
    loadKV(0, 0); CP_COMMIT();
    loadKV(1, 1); CP_COMMIT();
    CP_WAIT1();
    __syncthreads();

    uint32_t Qa[8][4];
#pragma unroll
    for (int kq = 0; kq < 8; kq++)
        ldsm4(Qa[kq], base + ((wid * 16 + ((l >> 3) & 1) * 8 + (l & 7)) * 136
                              + (kq * 2 + (l >> 4)) * 8) * 2);

    float accO[16][4];
    float m_run[2], l_run[2];
#pragma unroll
    for (int j = 0; j < 16; j++)
#pragma unroll
        for (int c = 0; c < 4; c++) accO[j][c] = 0.f;
    m_run[0] = m_run[1] = -1e30f;
    l_run[0] = l_run[1] = 0.f;

    for (int kt = 0; kt < 32; kt++) {
        int cur = kt & 1;
        uint32_t Kb = base + (8704 + cur * 17408) * 2;
        uint32_t Vb = Kb + 8704 * 2;

        float accS[8][4];
#pragma unroll
        for (int j = 0; j < 8; j++)
#pragma unroll
            for (int c = 0; c < 4; c++) accS[j][c] = 0.f;
#pragma unroll
        for (int kc2 = 0; kc2 < 4; kc2++) {
            uint32_t bb[8][4];
#pragma unroll
            for (int nj = 0; nj < 8; nj++)
                ldsm4(bb[nj], Kb + ((nj * 8 + (l & 7)) * 136 + (kc2 * 4 + (l >> 3)) * 8) * 2);
#pragma unroll
            for (int kc = 0; kc < 2; kc++)
#pragma unroll
                for (int nj = 0; nj < 8; nj++)
                    mma16(accS[nj], Qa[kc2 * 2 + kc], bb[nj][2 * kc], bb[nj][2 * kc + 1]);
        }

        float pm[2], ps[2];
        pm[0] = pm[1] = -1e30f; ps[0] = ps[1] = 0.f;
#pragma unroll
        for (int nj = 0; nj < 8; nj++)
#pragma unroll
            for (int c = 0; c < 4; c++) {
                float v = accS[nj][c] * SC;
                accS[nj][c] = v;
                pm[c >> 1] = fmaxf(pm[c >> 1], v);
            }
#pragma unroll
        for (int r = 0; r < 2; r++) {
            pm[r] = fmaxf(pm[r], __shfl_xor_sync(0xffffffffu, pm[r], 1));
            pm[r] = fmaxf(pm[r], __shfl_xor_sync(0xffffffffu, pm[r], 2));
        }
#pragma unroll
        for (int nj = 0; nj < 8; nj++)
#pragma unroll
            for (int c = 0; c < 4; c++) {
                float p = __expf(accS[nj][c] - pm[c >> 1]);
                accS[nj][c] = p;
                ps[c >> 1] += p;
            }
#pragma unroll
        for (int r = 0; r < 2; r++) {
            ps[r] += __shfl_xor_sync(0xffffffffu, ps[r], 1);
            ps[r] += __shfl_xor_sync(0xffffffffu, ps[r], 2);
        }
        float cf[2], corr[2];
#pragma unroll
        for (int r = 0; r < 2; r++) {
            float mnew = fmaxf(m_run[r], pm[r]);
            corr[r] = __expf(m_run[r] - mnew);
            cf[r]   = __expf(pm[r] - mnew);
            l_run[r] = l_run[r] * corr[r] + ps[r] * cf[r];
            m_run[r] = mnew;
        }
#pragma unroll
        for (int nj = 0; nj < 16; nj++)
#pragma unroll
            for (int c = 0; c < 4; c++)
                accO[nj][c] *= corr[c >> 1];

        uint32_t Pa[4][4];
#pragma unroll
        for (int kc = 0; kc < 4; kc++) {
            Pa[kc][0] = pack2(accS[2*kc][0]   * cf[0], accS[2*kc][1]   * cf[0]);
            Pa[kc][1] = pack2(accS[2*kc][2]   * cf[1], accS[2*kc][3]   * cf[1]);
            Pa[kc][2] = pack2(accS[2*kc+1][0] * cf[0], accS[2*kc+1][1] * cf[0]);
            Pa[kc][3] = pack2(accS[2*kc+1][2] * cf[1], accS[2*kc+1][3] * cf[1]);
        }

#pragma unroll
        for (int kc2 = 0; kc2 < 2; kc2++)
#pragma unroll
            for (int nh = 0; nh < 2; nh++) {
                uint32_t bb[8][4];
#pragma unroll
                for (int nj = 0; nj < 8; nj++)
                    ldsm4t(bb[nj], Vb + ((kc2 * 32 + (l >> 3) * 8 + (l & 7)) * 136
                                         + (nh * 8 + nj) * 8) * 2);
#pragma unroll
                for (int kc = 0; kc < 2; kc++)
#pragma unroll
                    for (int nj = 0; nj < 8; nj++)
                        mma16(accO[nh * 8 + nj], Pa[kc2 * 2 + kc],
                              bb[nj][2 * kc], bb[nj][2 * kc + 1]);
            }

        if (kt < 31) {
            CP_WAIT0();
            __syncthreads();
            if (kt < 30) { loadKV(kt + 2, cur); CP_COMMIT(); }
        }
    }

    float inv0 = 1.f / l_run[0], inv1 = 1.f / l_run[1];
    int row0 = q0 + wid * 16 + lr;
#pragma unroll
    for (int nj = 0; nj < 16; nj++) {
        int col = h * Dhc + nj * 8 + 2 * lo;
        *(__half2*)(go + (size_t)(b * Lc + row0) * Dc + col) =
            __floats2half2_rn(accO[nj][0] * inv0, accO[nj][1] * inv0);
        *(__half2*)(go + (size_t)(b * Lc + row0 + 8) * Dc + col) =
            __floats2half2_rn(accO[nj][2] * inv1, accO[nj][3] * inv1);
    }
}

// ================================ host ========================================
extern "C" void kernel_launch(void* const* d_in, const int* in_sizes, int n_in,
                              void* d_out, int out_size) {
    const float* hidden = (const float*)d_in[0];
    const float* temb   = (const float*)d_in[1];
    const float* w_ln   = (const float*)d_in[2];
    const float* w_mod  = (const float*)d_in[3];
    const float* b_mod  = (const float*)d_in[4];
    const float* wq     = (const float*)d_in[5];
    const float* wk     = (const float*)d_in[6];
    const float* wv     = (const float*)d_in[7];
    const float* wo     = (const float*)d_in[8];
    const float* qn     = (const float*)d_in[9];
    const float* kn     = (const float*)d_in[10];
    const float* cos1   = (const float*)d_in[11];
    const float* sin1   = (const float*)d_in[12];
    const float* rope3  = (const float*)d_in[13];
    const int*   mpos   = (const int*)d_in[14];
    float* out = (float*)d_out;

    void *pxm, *pqkv, *po, *pwT, *pwoT;
    cudaGetSymbolAddress(&pxm,  g_xmh);
    cudaGetSymbolAddress(&pqkv, g_qkvh);
    cudaGetSymbolAddress(&po,   g_oh);
    cudaGetSymbolAddress(&pwT,  g_wTh);
    cudaGetSymbolAddress(&pwoT, g_woTh);

    cudaFuncSetAttribute(k_mma<0>, cudaFuncAttributeMaxDynamicSharedMemorySize, MMASMEM);
    cudaFuncSetAttribute(k_mma<1>, cudaFuncAttributeMaxDynamicSharedMemorySize, MMASMEM);
    cudaFuncSetAttribute(k_flash, cudaFuncAttributeMaxDynamicSharedMemorySize, FSMEM);

    k_mod<<<dim3(D3c / 64, Bc), 256>>>(temb, w_mod, b_mod);
    k_rmsmod<<<Bc * Lc, 256>>>(hidden, w_ln);

    k_transpose4<<<dim3(64, 64, 4), dim3(32, 8)>>>(wq, wk, wv, wo);

    // fused QKV GEMM: [4096 x 4096] = xm @ [wq|wk|wv]^T  (half out)
    k_mma<0><<<dim3(QKVN / 256, (Bc * Lc) / 128), 512, MMASMEM>>>(
        (const __half*)pxm, (const __half*)pwT, pqkv, QKVN, Dc, nullptr);

    k_qknorm_rope<<<(Bc * Lc * (Hc + KVHc)) / 8, 256>>>(cos1, sin1, rope3, qn, kn, mpos);

    k_flash<<<dim3(Lc / 64, Hc, Bc), 128, FSMEM>>>((__half*)po);

    // output projection + residual/gate epilogue (float out)
    k_mma<1><<<dim3(Dc / 256, (Bc * Lc) / 128), 512, MMASMEM>>>(
        (const __half*)po, (const __half*)pwoT, out, Dc, Dc, hidden);
}

// round 13
// speedup vs baseline: 3.3718x; 1.0401x over previous
#include <cuda_runtime.h>
#include <cuda_fp16.h>
#include <cstdint>

#define Bc   2
#define Lc   2048
#define Dc   2048
#define Hc   16
#define KVHc 8
#define Dhc  128
#define QKVN 4096
#define D3c  6144
#define EPSc 1e-5f

// ---------------- scratch (device globals: allocation-guard safe) -------------
__device__ float  g_mod [Bc * D3c];
__device__ __half g_xmh [(size_t)Bc * Lc * Dc];
__device__ __half g_qkvh[(size_t)Bc * Lc * QKVN];  // 0..2047 Q | 2048..3071 K | 3072..4095 V
__device__ __half g_oh  [(size_t)Bc * Lc * Dc];
__device__ __half g_wTh [(size_t)QKVN * Dc];       // [wq^T ; wk^T ; wv^T], K-contig rows
__device__ __half g_woTh[(size_t)Dc * Dc];

// ================= helpers ====================================================
__device__ __forceinline__ uint32_t smem_u32(const void* p) {
    uint32_t a;
    asm("{ .reg .u64 t; cvta.to.shared.u64 t, %1; cvt.u32.u64 %0, t; }" : "=r"(a) : "l"(p));
    return a;
}
__device__ __forceinline__ void ldsm4(uint32_t* r, uint32_t a) {
    asm volatile("ldmatrix.sync.aligned.m8n8.x4.shared.b16 {%0,%1,%2,%3}, [%4];"
                 : "=r"(r[0]), "=r"(r[1]), "=r"(r[2]), "=r"(r[3]) : "r"(a));
}
__device__ __forceinline__ void ldsm4t(uint32_t* r, uint32_t a) {
    asm volatile("ldmatrix.sync.aligned.m8n8.x4.trans.shared.b16 {%0,%1,%2,%3}, [%4];"
                 : "=r"(r[0]), "=r"(r[1]), "=r"(r[2]), "=r"(r[3]) : "r"(a));
}
__device__ __forceinline__ void mma16(float* d, const uint32_t* a, uint32_t b0, uint32_t b1) {
    asm volatile("mma.sync.aligned.m16n8k16.row.col.f32.f16.f16.f32 "
                 "{%0,%1,%2,%3}, {%4,%5,%6,%7}, {%8,%9}, {%0,%1,%2,%3};"
                 : "+f"(d[0]), "+f"(d[1]), "+f"(d[2]), "+f"(d[3])
                 : "r"(a[0]), "r"(a[1]), "r"(a[2]), "r"(a[3]), "r"(b0), "r"(b1));
}
__device__ __forceinline__ void cpa16(uint32_t s, const void* g) {
    asm volatile("cp.async.cg.shared.global [%0], [%1], 16;" :: "r"(s), "l"(g));
}
__device__ __forceinline__ uint32_t pack2(float a, float b) {
    __half2 h = __floats2half2_rn(a, b);
    return *reinterpret_cast<uint32_t*>(&h);
}
#define CP_COMMIT() asm volatile("cp.async.commit_group;" ::: "memory")
#define CP_WAIT0()  asm volatile("cp.async.wait_group 0;" ::: "memory")
#define CP_WAIT1()  asm volatile("cp.async.wait_group 1;" ::: "memory")

// ================= kernel 1: mod = silu(temb) @ w_mod + b_mod =================
__global__ void k_mod(const float* __restrict__ temb, const float* __restrict__ w_mod,
                      const float* __restrict__ b_mod) {
    __shared__ float st[Dc];
    __shared__ float ps[4][64];
    int b = blockIdx.y;
    int tx = threadIdx.x & 63, ty = threadIdx.x >> 6;
    int j = blockIdx.x * 64 + tx;
    for (int i = threadIdx.x; i < Dc; i += 256) {
        float x = temb[b * Dc + i];
        st[i] = x / (1.f + __expf(-x));
    }
    __syncthreads();
    float acc = 0.f;
    int k0 = ty * 512;
#pragma unroll 4
    for (int i = 0; i < 512; i++)
        acc = fmaf(st[k0 + i], w_mod[(size_t)(k0 + i) * D3c + j], acc);
    ps[ty][tx] = acc;
    __syncthreads();
    if (ty == 0)
        g_mod[b * D3c + j] = ps[0][tx] + ps[1][tx] + ps[2][tx] + ps[3][tx] + b_mod[j];
}

// ====== kernel 2: xm = half(rmsnorm(x)*w_ln*(1+scale)+shift) ==================
__global__ void k_rmsmod(const float* __restrict__ x, const float* __restrict__ w_ln) {
    int row = blockIdx.x;
    int b   = row >> 11;
    const float* xr = x + (size_t)row * Dc;
    int tid = threadIdx.x;
    float ss = 0.f;
    for (int i = tid; i < Dc; i += 256) { float v = xr[i]; ss = fmaf(v, v, ss); }
#pragma unroll
    for (int o = 16; o; o >>= 1) ss += __shfl_xor_sync(0xffffffffu, ss, o);
    __shared__ float red[8];
    __shared__ float sinv;
    if ((tid & 31) == 0) red[tid >> 5] = ss;
    __syncthreads();
    if (tid == 0) {
        float t = 0.f;
#pragma unroll
        for (int w = 0; w < 8; w++) t += red[w];
        sinv = rsqrtf(t * (1.f / Dc) + EPSc);
    }
    __syncthreads();
    float inv = sinv;
    const float* sh = g_mod + b * D3c;
    const float* sc = sh + Dc;
    __half* xm = g_xmh + (size_t)row * Dc;
    for (int i = tid; i < Dc; i += 256)
        xm[i] = __float2half_rn(fmaf(xr[i] * inv * w_ln[i], 1.f + sc[i], sh[i]));
}

// ====== batched transpose: all 4 weights in one launch ========================
__global__ void k_transpose4(const float* __restrict__ wq, const float* __restrict__ wk,
                             const float* __restrict__ wv, const float* __restrict__ wo) {
    __shared__ float t[32][33];
    const float* src; __half* dst; int N;
    switch (blockIdx.z) {
        case 0:  src = wq; dst = g_wTh;                         N = 2048; break;
        case 1:  src = wk; dst = g_wTh + (size_t)2048 * Dc;     N = 1024; break;
        case 2:  src = wv; dst = g_wTh + (size_t)3072 * Dc;     N = 1024; break;
        default: src = wo; dst = g_woTh;                        N = 2048; break;
    }
    int nb = blockIdx.x * 32;
    if (nb >= N) return;
    int kb = blockIdx.y * 32;
    int x = threadIdx.x, y = threadIdx.y;
#pragma unroll
    for (int i = 0; i < 32; i += 8)
        t[y + i][x] = src[(size_t)(kb + y + i) * N + nb + x];
    __syncthreads();
#pragma unroll
    for (int i = 0; i < 32; i += 8)
        dst[(size_t)(nb + y + i) * Dc + kb + x] = __float2half_rn(t[x][y + i]);
}

// ====== fp16 mma.sync GEMM: C[M,N] = A[M,K] @ Bt[N,K]^T =======================
// BM=128 BN=128 BK=64. 8 warps (2m x 4n), warp tile 64x32. 3-stage cp.async,
// 256 threads, 2 CTAs/SM (smem 110.6 KB, regs forced <=128).
#define GSTAGE 36864                 // A 128*72*2 + B 128*72*2
#define MMASMEM (GSTAGE * 3)         // 110592 bytes

template<int EPI>
__global__ void __launch_bounds__(256, 2)
k_mma(const __half* __restrict__ Ag, const __half* __restrict__ Bg,
      void* __restrict__ Cv, int N, int K, const float* __restrict__ hid) {
    extern __shared__ __half sh[];
    uint32_t base = smem_u32(sh);
    int t = threadIdx.x, l = t & 31, wid = t >> 5;
    int wm = wid >> 2, wn = wid & 3;
    int m0 = blockIdx.y * 128, n0 = blockIdx.x * 128;

    auto loadT = [&](int kt, int buf) {
        uint32_t ab = base + buf * GSTAGE;
#pragma unroll
        for (int i = 0; i < 4; i++) {   // A: 1024 cells (128 rows x 8 cells)
            int p = t + (i << 8); int r = p >> 3, c = p & 7;
            cpa16(ab + (r * 72 + c * 8) * 2,
                  Ag + (size_t)(m0 + r) * K + kt * 64 + c * 8);
        }
#pragma unroll
        for (int i = 0; i < 4; i++) {   // B: 1024 cells (128 rows x 8 cells)
            int p = t + (i << 8); int r = p >> 3, c = p & 7;
            cpa16(ab + 18432 + (r * 72 + c * 8) * 2,
                  Bg + (size_t)(n0 + r) * K + kt * 64 + c * 8);
        }
    };

    float acc[4][4][4];
#pragma unroll
    for (int i = 0; i < 4; i++)
#pragma unroll
        for (int j = 0; j < 4; j++)
#pragma unroll
            for (int c = 0; c < 4; c++) acc[i][j][c] = 0.f;

    int nk = K >> 6;
    loadT(0, 0); CP_COMMIT();
    loadT(1, 1); CP_COMMIT();

    int cur = 0;
    for (int kt = 0; kt < nk; kt++) {
        if (kt + 1 < nk) CP_WAIT1(); else CP_WAIT0();
        __syncthreads();   // buffer `cur` visible; prev buffer fully drained
        if (kt + 2 < nk) {
            int nb = cur + 2; if (nb >= 3) nb -= 3;
            loadT(kt + 2, nb);
            CP_COMMIT();
        }

        uint32_t Ab = base + cur * GSTAGE;
        uint32_t Bb = Ab + 18432;
#pragma unroll
        for (int kc2 = 0; kc2 < 2; kc2++) {      // two k32 chunks of BK=64
            uint32_t bb[4][4];
#pragma unroll
            for (int j = 0; j < 4; j++)
                ldsm4(bb[j], Bb + ((wn * 32 + j * 8 + (l & 7)) * 72
                                   + (kc2 * 4 + (l >> 3)) * 8) * 2);
#pragma unroll
            for (int kc = 0; kc < 2; kc++) {
                uint32_t aa[4][4];
#pragma unroll
                for (int i = 0; i < 4; i++)
                    ldsm4(aa[i], Ab + ((wm * 64 + i * 16 + ((l >> 3) & 1) * 8 + (l & 7)) * 72
                                       + (kc2 * 4 + 2 * kc + (l >> 4)) * 8) * 2);
#pragma unroll
                for (int i = 0; i < 4; i++)
#pragma unroll
                    for (int j = 0; j < 4; j++)
                        mma16(acc[i][j], aa[i], bb[j][2 * kc], bb[j][2 * kc + 1]);
            }
        }
        cur++; if (cur == 3) cur = 0;
    }

    // epilogue
#pragma unroll
    for (int i = 0; i < 4; i++) {
        int gm = m0 + wm * 64 + i * 16 + (l >> 2);
#pragma unroll
        for (int j = 0; j < 4; j++) {
            int gn = n0 + wn * 32 + j * 8 + 2 * (l & 3);
            if (EPI == 0) {
                __half* C = (__half*)Cv;
                *(__half2*)(C + (size_t)gm * N + gn) =
                    __floats2half2_rn(acc[i][j][0], acc[i][j][1]);
                *(__half2*)(C + (size_t)(gm + 8) * N + gn) =
                    __floats2half2_rn(acc[i][j][2], acc[i][j][3]);
            } else {
                float* C = (float*)Cv;
                size_t o0 = (size_t)gm * N + gn;
                size_t o1 = (size_t)(gm + 8) * N + gn;
                int b0 = gm >> 11, b1 = (gm + 8) >> 11;
                float2 h0 = *(const float2*)(hid + o0);
                float2 h1 = *(const float2*)(hid + o1);
                float2 g0 = *(const float2*)(g_mod + b0 * D3c + 2 * Dc + gn);
                float2 g1 = *(const float2*)(g_mod + b1 * D3c + 2 * Dc + gn);
                *(float2*)(C + o0) = make_float2(fmaf(g0.x, acc[i][j][0], h0.x),
                                                 fmaf(g0.y, acc[i][j][1], h0.y));
                *(float2*)(C + o1) = make_float2(fmaf(g1.x, acc[i][j][2], h1.x),
                                                 fmaf(g1.y, acc[i][j][3], h1.y));
            }
        }
    }
}

// ====== per-head RMSNorm + mixed RoPE, vectorized (round-12, verified) ========
__global__ void __launch_bounds__(256)
k_qknorm_rope(const float* __restrict__ cos1d, const float* __restrict__ sin1d,
              const float* __restrict__ rope3d,
              const float* __restrict__ qn, const float* __restrict__ kn,
              const int* __restrict__ mp) {
    int warp = threadIdx.x >> 5, lane = threadIdx.x & 31;
    int v  = blockIdx.x * 8 + warp;
    int bl = v / 24, r = v % 24;
    int b = bl >> 11, l = bl & 2047;
    int d0 = lane * 4;

    __half* ptr; const float* w;
    if (r < Hc) { ptr = g_qkvh + (size_t)bl * QKVN + r * Dhc;               w = qn; }
    else        { ptr = g_qkvh + (size_t)bl * QKVN + 2048 + (r - Hc) * Dhc; w = kn; }

    __half2 h01 = *(const __half2*)(ptr + d0);
    __half2 h23 = *(const __half2*)(ptr + d0 + 2);
    float val[4] = { __half2float(h01.x), __half2float(h01.y),
                     __half2float(h23.x), __half2float(h23.y) };
    float ss = 0.f;
#pragma unroll
    for (int i = 0; i < 4; i++) ss = fmaf(val[i], val[i], ss);
#pragma unroll
    for (int o = 16; o; o >>= 1) ss += __shfl_xor_sync(0xffffffffu, ss, o);
    float inv = rsqrtf(ss * (1.f / Dhc) + EPSc);
    float4 wv4 = *(const float4*)(w + d0);
    val[0] *= inv * wv4.x; val[1] *= inv * wv4.y;
    val[2] *= inv * wv4.z; val[3] *= inv * wv4.w;

    bool is64 = (mp[1] == 0);
    bool in_full = false, in_img = false; int rel = 0;
#pragma unroll
    for (int m = 0; m < 2; m++) {
        int off, ln;
        if (is64) { off = mp[(b * 4 + m * 2) * 2]; ln = mp[(b * 4 + m * 2 + 1) * 2]; }
        else      { off = mp[b * 4 + m * 2];       ln = mp[b * 4 + m * 2 + 1]; }
        int seg_end = off + max(ln, 1);
        if (l >= off && l < seg_end) in_full = true;
        if (l >= off + 1 && l < off + ln) { in_img = true; rel += l - (off + 1); }
    }
    bool text = !in_full;
    bool img  = in_img && (rel < 1024);
    rel = min(max(rel, 0), 1023);

    float out[4];
    if (text) {
        float4 c4 = *(const float4*)(cos1d + l * Dhc + d0);
        float4 s4 = *(const float4*)(sin1d + l * Dhc + d0);
        float sgn = (d0 < 64) ? -1.f : 1.f;
        float cc[4] = {c4.x, c4.y, c4.z, c4.w};
        float s_[4] = {s4.x, s4.y, s4.z, s4.w};
#pragma unroll
        for (int i = 0; i < 4; i++) {
            float partner = __shfl_xor_sync(0xffffffffu, val[i], 16);
            out[i] = fmaf(val[i], cc[i], sgn * partner * s_[i]);
        }
    } else {
        const float4 R0 = *(const float4*)(rope3d + ((size_t)rel * 64 + 2 * lane) * 4);
        const float4 R1 = *(const float4*)(rope3d + ((size_t)rel * 64 + 2 * lane + 1) * 4);
        float o0 = fmaf(val[0], R0.x, val[1] * R0.z);
        float o1 = fmaf(val[0], R0.y, val[1] * R0.w);
        float o2 = fmaf(val[2], R1.x, val[3] * R1.z);
        float o3 = fmaf(val[2], R1.y, val[3] * R1.w);
        out[0] = img ? o0 : val[0]; out[1] = img ? o1 : val[1];
        out[2] = img ? o2 : val[2]; out[3] = img ? o3 : val[3];
    }
    *(__half2*)(ptr + d0)     = __floats2half2_rn(out[0], out[1]);
    *(__half2*)(ptr + d0 + 2) = __floats2half2_rn(out[2], out[3]);
}

// ====== flash attention, FA2-style (round-11, verified) =======================
#define FSMEM (43520 * 2)   // 87040 bytes, 2 CTAs/SM

__global__ void __launch_bounds__(128)
k_flash(__half* __restrict__ go) {
    extern __shared__ __half fh[];
    uint32_t base = smem_u32(fh);

    int t = threadIdx.x, l = t & 31, wid = t >> 5;
    int lo = l & 3, lr = l >> 2;
    int q0 = blockIdx.x << 6;
    int h  = blockIdx.y, b = blockIdx.z;
    int kh = h >> 1;
    const float SC = 0.08838834764831845f;

    const __half* qkv = g_qkvh;

#pragma unroll
    for (int i = 0; i < 8; i++) {
        int p = t + (i << 7); int r = p >> 4, c = p & 15;
        cpa16(base + (r * 136 + c * 8) * 2,
              qkv + (size_t)(b * Lc + q0 + r) * QKVN + h * Dhc + c * 8);
    }
    auto loadKV = [&](int kt, int buf) {
        uint32_t sb = base + (8704 + buf * 17408) * 2;
#pragma unroll
        for (int i = 0; i < 8; i++) {
            int p = t + (i << 7); int r = p >> 4, c = p & 15;
            cpa16(sb + (r * 136 + c * 8) * 2,
                  qkv + (size_t)(b * Lc + kt * 64 + r) * QKVN + 2048 + kh * Dhc + c * 8);
        }
#pragma unroll
        for (int i = 0; i < 8; i++) {
            int p = t + (i << 7); int r = p >> 4, c = p & 15;
            cpa16(sb + (8704 + r * 136 + c * 8) * 2,
                  qkv + (size_t)(b * Lc + kt * 64 + r) * QKVN + 3072 + kh * Dhc + c * 8);
        }
    };
    loadKV(0, 0); CP_COMMIT();
    loadKV(1, 1); CP_COMMIT();
    CP_WAIT1();
    __syncthreads();

    uint32_t Qa[8][4];
#pragma unroll
    for (int kq = 0; kq < 8; kq++)
        ldsm4(Qa[kq], base + ((wid * 16 + ((l >> 3) & 1) * 8 + (l & 7)) * 136
                              + (kq * 2 + (l >> 4)) * 8) * 2);

    float accO[16][4];
    float m_run[2], l_run[2];
#pragma unroll
    for (int j = 0; j < 16; j++)
#pragma unroll
        for (int c = 0; c < 4; c++) accO[j][c] = 0.f;
    m_run[0] = m_run[1] = -1e30f;
    l_run[0] = l_run[1] = 0.f;

    for (int kt = 0; kt < 32; kt++) {
        int cur = kt & 1;
        uint32_t Kb = base + (8704 + cur * 17408) * 2;
        uint32_t Vb = Kb + 8704 * 2;

        float accS[8][4];
#pragma unroll
        for (int j = 0; j < 8; j++)
#pragma unroll
            for (int c = 0; c < 4; c++) accS[j][c] = 0.f;
#pragma unroll
        for (int kc2 = 0; kc2 < 4; kc2++) {
            uint32_t bb[8][4];
#pragma unroll
            for (int nj = 0; nj < 8; nj++)
                ldsm4(bb[nj], Kb + ((nj * 8 + (l & 7)) * 136 + (kc2 * 4 + (l >> 3)) * 8) * 2);
#pragma unroll
            for (int kc = 0; kc < 2; kc++)
#pragma unroll
                for (int nj = 0; nj < 8; nj++)
                    mma16(accS[nj], Qa[kc2 * 2 + kc], bb[nj][2 * kc], bb[nj][2 * kc + 1]);
        }

        float pm[2], ps[2];
        pm[0] = pm[1] = -1e30f; ps[0] = ps[1] = 0.f;
#pragma unroll
        for (int nj = 0; nj < 8; nj++)
#pragma unroll
            for (int c = 0; c < 4; c++) {
                float v = accS[nj][c] * SC;
                accS[nj][c] = v;
                pm[c >> 1] = fmaxf(pm[c >> 1], v);
            }
#pragma unroll
        for (int r = 0; r < 2; r++) {
            pm[r] = fmaxf(pm[r], __shfl_xor_sync(0xffffffffu, pm[r], 1));
            pm[r] = fmaxf(pm[r], __shfl_xor_sync(0xffffffffu, pm[r], 2));
        }
#pragma unroll
        for (int nj = 0; nj < 8; nj++)
#pragma unroll
            for (int c = 0; c < 4; c++) {
                float p = __expf(accS[nj][c] - pm[c >> 1]);
                accS[nj][c] = p;
                ps[c >> 1] += p;
            }
#pragma unroll
        for (int r = 0; r < 2; r++) {
            ps[r] += __shfl_xor_sync(0xffffffffu, ps[r], 1);
            ps[r] += __shfl_xor_sync(0xffffffffu, ps[r], 2);
        }
        float cf[2], corr[2];
#pragma unroll
        for (int r = 0; r < 2; r++) {
            float mnew = fmaxf(m_run[r], pm[r]);
            corr[r] = __expf(m_run[r] - mnew);
            cf[r]   = __expf(pm[r] - mnew);
            l_run[r] = l_run[r] * corr[r] + ps[r] * cf[r];
            m_run[r] = mnew;
        }
#pragma unroll
        for (int nj = 0; nj < 16; nj++)
#pragma unroll
            for (int c = 0; c < 4; c++)
                accO[nj][c] *= corr[c >> 1];

        uint32_t Pa[4][4];
#pragma unroll
        for (int kc = 0; kc < 4; kc++) {
            Pa[kc][0] = pack2(accS[2*kc][0]   * cf[0], accS[2*kc][1]   * cf[0]);
            Pa[kc][1] = pack2(accS[2*kc][2]   * cf[1], accS[2*kc][3]   * cf[1]);
            Pa[kc][2] = pack2(accS[2*kc+1][0] * cf[0], accS[2*kc+1][1] * cf[0]);
            Pa[kc][3] = pack2(accS[2*kc+1][2] * cf[1], accS[2*kc+1][3] * cf[1]);
        }

#pragma unroll
        for (int kc2 = 0; kc2 < 2; kc2++)
#pragma unroll
            for (int nh = 0; nh < 2; nh++) {
                uint32_t bb[8][4];
#pragma unroll
                for (int nj = 0; nj < 8; nj++)
                    ldsm4t(bb[nj], Vb + ((kc2 * 32 + (l >> 3) * 8 + (l & 7)) * 136
                                         + (nh * 8 + nj) * 8) * 2);
#pragma unroll
                for (int kc = 0; kc < 2; kc++)
#pragma unroll
                    for (int nj = 0; nj < 8; nj++)
                        mma16(accO[nh * 8 + nj], Pa[kc2 * 2 + kc],
                              bb[nj][2 * kc], bb[nj][2 * kc + 1]);
            }

        if (kt < 31) {
            CP_WAIT0();
            __syncthreads();
            if (kt < 30) { loadKV(kt + 2, cur); CP_COMMIT(); }
        }
    }

    float inv0 = 1.f / l_run[0], inv1 = 1.f / l_run[1];
    int row0 = q0 + wid * 16 + lr;
#pragma unroll
    for (int nj = 0; nj < 16; nj++) {
        int col = h * Dhc + nj * 8 + 2 * lo;
        *(__half2*)(go + (size_t)(b * Lc + row0) * Dc + col) =
            __floats2half2_rn(accO[nj][0] * inv0, accO[nj][1] * inv0);
        *(__half2*)(go + (size_t)(b * Lc + row0 + 8) * Dc + col) =
            __floats2half2_rn(accO[nj][2] * inv1, accO[nj][3] * inv1);
    }
}

// ================================ host ========================================
extern "C" void kernel_launch(void* const* d_in, const int* in_sizes, int n_in,
                              void* d_out, int out_size) {
    const float* hidden = (const float*)d_in[0];
    const float* temb   = (const float*)d_in[1];
    const float* w_ln   = (const float*)d_in[2];
    const float* w_mod  = (const float*)d_in[3];
    const float* b_mod  = (const float*)d_in[4];
    const float* wq     = (const float*)d_in[5];
    const float* wk     = (const float*)d_in[6];
    const float* wv     = (const float*)d_in[7];
    const float* wo     = (const float*)d_in[8];
    const float* qn     = (const float*)d_in[9];
    const float* kn     = (const float*)d_in[10];
    const float* cos1   = (const float*)d_in[11];
    const float* sin1   = (const float*)d_in[12];
    const float* rope3  = (const float*)d_in[13];
    const int*   mpos   = (const int*)d_in[14];
    float* out = (float*)d_out;

    void *pxm, *pqkv, *po, *pwT, *pwoT;
    cudaGetSymbolAddress(&pxm,  g_xmh);
    cudaGetSymbolAddress(&pqkv, g_qkvh);
    cudaGetSymbolAddress(&po,   g_oh);
    cudaGetSymbolAddress(&pwT,  g_wTh);
    cudaGetSymbolAddress(&pwoT, g_woTh);

    cudaFuncSetAttribute(k_mma<0>, cudaFuncAttributeMaxDynamicSharedMemorySize, MMASMEM);
    cudaFuncSetAttribute(k_mma<1>, cudaFuncAttributeMaxDynamicSharedMemorySize, MMASMEM);
    cudaFuncSetAttribute(k_flash, cudaFuncAttributeMaxDynamicSharedMemorySize, FSMEM);

    k_mod<<<dim3(D3c / 64, Bc), 256>>>(temb, w_mod, b_mod);
    k_rmsmod<<<Bc * Lc, 256>>>(hidden, w_ln);

    k_transpose4<<<dim3(64, 64, 4), dim3(32, 8)>>>(wq, wk, wv, wo);

    // fused QKV GEMM: [4096 x 4096] = xm @ [wq|wk|wv]^T  (half out)
    k_mma<0><<<dim3(QKVN / 128, (Bc * Lc) / 128), 256, MMASMEM>>>(
        (const __half*)pxm, (const __half*)pwT, pqkv, QKVN, Dc, nullptr);

    k_qknorm_rope<<<(Bc * Lc * (Hc + KVHc)) / 8, 256>>>(cos1, sin1, rope3, qn, kn, mpos);

    k_flash<<<dim3(Lc / 64, Hc, Bc), 128, FSMEM>>>((__half*)po);

    // output projection + residual/gate epilogue (float out)
    k_mma<1><<<dim3(Dc / 128, (Bc * Lc) / 128), 256, MMASMEM>>>(
        (const __half*)po, (const __half*)pwoT, out, Dc, Dc, hidden);
}